// round 8
// baseline (speedup 1.0000x reference)
#include <cuda_runtime.h>
#include <cuda_bf16.h>
#include <cstdint>

#define NN 50000
#define EE 800000
#define SCAN_BLK 1024
#define NSCAN_BLKS ((NN + 1 + SCAN_BLK - 1) / SCAN_BLK)

// ---------------- scratch (static device memory; no allocs) ----------------
__device__ uint32_t g_feat_pk[NN * 128];
__device__ uint32_t g_hp_pk[NN * 128];
__device__ uint32_t g_neigh_pk[NN * 128];
__device__ uint32_t g_h1_pk[NN * 64];
__device__ uint32_t g_h2_pk[NN * 128];
__device__ uint32_t g_w_pk[102400];     // transposed split-bf16 weights, [Nout][K]
__device__ int   g_rowptr[NN + 1];
__device__ int   g_cursor[NN];
__device__ int   g_src_sorted[EE];
__device__ float g_ew_sorted[EE];
__device__ int   g_partials[NSCAN_BLKS];

// weight scratch offsets (uint32 elements), layout [Nout][K]
#define WOFF_P1 0        // 128x128
#define WOFF_S1 16384    // 64x128
#define WOFF_N1 24576    // 64x128
#define WOFF_P2 32768    // 64x64
#define WOFF_S2 36864    // 128x64
#define WOFF_N2 45056    // 128x64
#define WOFF_P3 53248    // 128x128
#define WOFF_S3 69632    // 128x128
#define WOFF_N3 86016    // 128x128

// ---------------- split-bf16 helpers ----------------
// packed u32: high 16 bits = bf16(x) ("hi"), low 16 bits = bf16(x - hi) ("lo")
__device__ __forceinline__ uint32_t pack_split(float x) {
    __nv_bfloat16 h = __float2bfloat16(x);
    float hf = __bfloat162float(h);
    __nv_bfloat16 l = __float2bfloat16(x - hf);
    return ((uint32_t)__bfloat16_as_ushort(h) << 16) | (uint32_t)__bfloat16_as_ushort(l);
}
__device__ __forceinline__ float unpack_split(uint32_t w) {
    float hf = __bfloat162float(__ushort_as_bfloat16((unsigned short)(w >> 16)));
    float lf = __bfloat162float(__ushort_as_bfloat16((unsigned short)(w & 0xFFFFu)));
    return hf + lf;
}

// ---------------- mma.sync m16n8k16 bf16 (baseline PTX, sm_80+) ----------------
__device__ __forceinline__ void mma16816(float* c, const uint32_t* a, uint32_t b0, uint32_t b1) {
    asm volatile(
        "mma.sync.aligned.m16n8k16.row.col.f32.bf16.bf16.f32 "
        "{%0,%1,%2,%3}, {%4,%5,%6,%7}, {%8,%9}, {%0,%1,%2,%3};"
        : "+f"(c[0]), "+f"(c[1]), "+f"(c[2]), "+f"(c[3])
        : "r"(a[0]), "r"(a[1]), "r"(a[2]), "r"(a[3]), "r"(b0), "r"(b1));
}
#define SEL_HI 0x7632u   // {a.hi16, b.hi16}
#define SEL_LO 0x5410u   // {a.lo16, b.lo16}

// ---------------- pack feat ----------------
__global__ void pack_feat_kernel(const float* __restrict__ f) {
    int i = blockIdx.x * blockDim.x + threadIdx.x;
    if (i < NN * 128) g_feat_pk[i] = pack_split(f[i]);
}

// ---------------- combined weight prep: transpose + split-pack all 9 weights ----------------
__global__ void wprep_all_kernel(
    const float* __restrict__ W0, const float* __restrict__ W1t, const float* __restrict__ W2t,
    const float* __restrict__ W3, const float* __restrict__ W4, const float* __restrict__ W5,
    const float* __restrict__ W6, const float* __restrict__ W7, const float* __restrict__ W8)
{
    const float* Ws[9] = {W0, W1t, W2t, W3, W4, W5, W6, W7, W8};
    const int off[9] = {WOFF_P1, WOFF_S1, WOFF_N1, WOFF_P2, WOFF_S2, WOFF_N2, WOFF_P3, WOFF_S3, WOFF_N3};
    const int Kd [9] = {128, 128, 128, 64, 64, 64, 128, 128, 128};
    const int Nd [9] = {128, 64, 64, 64, 128, 128, 128, 128, 128};
    int s = blockIdx.y;
    int sz = Kd[s] * Nd[s];
    int i = blockIdx.x * blockDim.x + threadIdx.x;
    if (i < sz) {
        int k = i / Nd[s], n = i % Nd[s];
        g_w_pk[off[s] + n * Kd[s] + k] = pack_split(Ws[s][k * Nd[s] + n]);
    }
}

// ---------------- CSR build ----------------
__global__ void zero_counts_kernel() {
    int i = blockIdx.x * blockDim.x + threadIdx.x;
    if (i <= NN) g_rowptr[i] = 0;
}
__global__ void hist_kernel(const int* __restrict__ dst) {
    int i = blockIdx.x * blockDim.x + threadIdx.x;
    if (i < EE) atomicAdd(&g_rowptr[dst[i] + 1], 1);
}
__global__ void scan_chunk_kernel(int n) {
    __shared__ int sdata[SCAN_BLK];
    int tid = threadIdx.x;
    int i = blockIdx.x * SCAN_BLK + tid;
    int v = (i < n) ? g_rowptr[i] : 0;
    sdata[tid] = v;
    __syncthreads();
    for (int off = 1; off < SCAN_BLK; off <<= 1) {
        int t = (tid >= off) ? sdata[tid - off] : 0;
        __syncthreads();
        sdata[tid] += t;
        __syncthreads();
    }
    if (i < n) g_rowptr[i] = sdata[tid];
    if (tid == SCAN_BLK - 1) g_partials[blockIdx.x] = sdata[tid];
}
__global__ void scan_partials_kernel(int nb) {
    __shared__ int sh[64];
    int t = threadIdx.x;
    sh[t] = (t < nb) ? g_partials[t] : 0;
    __syncthreads();
    for (int off = 1; off < 64; off <<= 1) {
        int x = (t >= off) ? sh[t - off] : 0;
        __syncthreads();
        sh[t] += x;
        __syncthreads();
    }
    if (t < nb) g_partials[t] = sh[t];
}
__global__ void scan_add_kernel(int n) {
    int i = blockIdx.x * SCAN_BLK + threadIdx.x;
    if (i < n) {
        int off = (blockIdx.x > 0) ? g_partials[blockIdx.x - 1] : 0;
        int val = g_rowptr[i] + off;
        g_rowptr[i] = val;
        if (i < NN) g_cursor[i] = val;
    }
}
__global__ void scatter_kernel(const int* __restrict__ src,
                               const int* __restrict__ dst,
                               const float* __restrict__ ew) {
    int e = blockIdx.x * blockDim.x + threadIdx.x;
    if (e < EE) {
        int p = atomicAdd(&g_cursor[dst[e]], 1);
        g_src_sorted[p] = src[e];
        g_ew_sorted[p]  = ew[e];
    }
}

// ---------------- neighbor max (packed in/out, warp per node, no atomics) ----------------
template <int DIN>
__global__ void neigh_max_pk(const uint32_t* __restrict__ hp, uint32_t* __restrict__ out) {
    int warp = (blockIdx.x * blockDim.x + threadIdx.x) >> 5;
    int lane = threadIdx.x & 31;
    if (warp >= NN) return;
    int beg = g_rowptr[warp];
    int end = g_rowptr[warp + 1];
    if (DIN == 128) {
        float m0 = 0.f, m1 = 0.f, m2 = 0.f, m3 = 0.f;
        int e = beg;
        for (; e + 1 < end; e += 2) {       // 2-way unroll: MLP 2
            int s0 = g_src_sorted[e],     s1 = g_src_sorted[e + 1];
            float w0 = g_ew_sorted[e],    w1 = g_ew_sorted[e + 1];
            uint4 p0 = *(const uint4*)&hp[(size_t)s0 * 128 + lane * 4];
            uint4 p1 = *(const uint4*)&hp[(size_t)s1 * 128 + lane * 4];
            m0 = fmaxf(m0, unpack_split(p0.x) * w0);
            m1 = fmaxf(m1, unpack_split(p0.y) * w0);
            m2 = fmaxf(m2, unpack_split(p0.z) * w0);
            m3 = fmaxf(m3, unpack_split(p0.w) * w0);
            m0 = fmaxf(m0, unpack_split(p1.x) * w1);
            m1 = fmaxf(m1, unpack_split(p1.y) * w1);
            m2 = fmaxf(m2, unpack_split(p1.z) * w1);
            m3 = fmaxf(m3, unpack_split(p1.w) * w1);
        }
        if (e < end) {
            int s = g_src_sorted[e];
            float w = g_ew_sorted[e];
            uint4 p = *(const uint4*)&hp[(size_t)s * 128 + lane * 4];
            m0 = fmaxf(m0, unpack_split(p.x) * w);
            m1 = fmaxf(m1, unpack_split(p.y) * w);
            m2 = fmaxf(m2, unpack_split(p.z) * w);
            m3 = fmaxf(m3, unpack_split(p.w) * w);
        }
        uint4 o;
        o.x = pack_split(m0); o.y = pack_split(m1);
        o.z = pack_split(m2); o.w = pack_split(m3);
        *(uint4*)&out[(size_t)warp * 128 + lane * 4] = o;
    } else {
        float m0 = 0.f, m1 = 0.f;
        int e = beg;
        for (; e + 1 < end; e += 2) {
            int s0 = g_src_sorted[e],  s1 = g_src_sorted[e + 1];
            float w0 = g_ew_sorted[e], w1 = g_ew_sorted[e + 1];
            uint2 p0 = *(const uint2*)&hp[(size_t)s0 * 64 + lane * 2];
            uint2 p1 = *(const uint2*)&hp[(size_t)s1 * 64 + lane * 2];
            m0 = fmaxf(m0, unpack_split(p0.x) * w0);
            m1 = fmaxf(m1, unpack_split(p0.y) * w0);
            m0 = fmaxf(m0, unpack_split(p1.x) * w1);
            m1 = fmaxf(m1, unpack_split(p1.y) * w1);
        }
        if (e < end) {
            int s = g_src_sorted[e];
            float w = g_ew_sorted[e];
            uint2 p = *(const uint2*)&hp[(size_t)s * 64 + lane * 2];
            m0 = fmaxf(m0, unpack_split(p.x) * w);
            m1 = fmaxf(m1, unpack_split(p.y) * w);
        }
        uint2 o;
        o.x = pack_split(m0); o.y = pack_split(m1);
        *(uint2*)&out[(size_t)warp * 64 + lane * 2] = o;
    }
}

// ---------------- HMMA GEMM: split-plane smem, direct LDS fragments, 32x64 warp tiles ----
// CTA 128 threads (4 warps), tile 128 x 64. Warp tile 32 x 64 (2 m-sub x 8 n-sub m16n8k16).
// smem: separate bf16 hi/lo planes for A (128 x K) and B (64 x K), row stride K+8 halfwords.
// hi/lo split done ONCE at fill time (PRMT amortized); inner loop is LDS.32 + HMMA only.
// Split-bf16 3-pass: hi*hi + hi*lo + lo*hi, fp32 register accumulators.
template <int K, bool DUAL, bool FINAL>
__global__ __launch_bounds__(128) void mma_gemm(
    const uint32_t* __restrict__ A1, const uint32_t* __restrict__ W1,
    const uint32_t* __restrict__ A2, const uint32_t* __restrict__ W2,
    const float* __restrict__ bias, void* __restrict__ outp,
    int M, int NOUTtot)
{
    constexpr int SAH = K + 8;                     // halfword stride per row
    constexpr uint32_t offAhi = 0;
    constexpr uint32_t offAlo = offAhi + 128 * SAH * 2;
    constexpr uint32_t offBhi = offAlo + 128 * SAH * 2;
    constexpr uint32_t offBlo = offBhi + 64 * SAH * 2;

    extern __shared__ char smem[];

    int tid = threadIdx.x;
    int warp = tid >> 5, lane = tid & 31;
    int m0 = blockIdx.x * 128;
    int n0 = blockIdx.y * 64;

    int r  = lane >> 2;          // 0..7
    int kp = (lane & 3) * 2;     // 0,2,4,6
    int mrow0 = warp * 32 + r;   // m-sub 0 fragment row; m-sub 1 = +16

    float acc[2][8][4];
#pragma unroll
    for (int ms = 0; ms < 2; ms++)
#pragma unroll
        for (int ns = 0; ns < 8; ns++)
#pragma unroll
            for (int j = 0; j < 4; j++) acc[ms][ns][j] = 0.f;

    const int npass = DUAL ? 2 : 1;
    for (int phase = 0; phase < npass; phase++) {
        const uint32_t* A = (phase == 0) ? A1 : A2;
        const uint32_t* W = (phase == 0) ? W1 : W2;
        if (phase) __syncthreads();           // all reads of prev tiles done

        // fill A planes: 128 rows x K packed -> hi/lo bf16 planes (PRMT once here)
        constexpr int C4 = K / 4;
        for (int idx = tid; idx < 128 * C4; idx += 128) {
            int row = idx / C4, c4 = idx % C4;
            uint4 v = make_uint4(0, 0, 0, 0);
            if (m0 + row < M) v = *(const uint4*)&A[(size_t)(m0 + row) * K + c4 * 4];
            uint2 hi, lo;
            hi.x = __byte_perm(v.x, v.y, SEL_HI); hi.y = __byte_perm(v.z, v.w, SEL_HI);
            lo.x = __byte_perm(v.x, v.y, SEL_LO); lo.y = __byte_perm(v.z, v.w, SEL_LO);
            uint32_t ho = (uint32_t)(row * SAH + c4 * 4) * 2;
            *(uint2*)(smem + offAhi + ho) = hi;
            *(uint2*)(smem + offAlo + ho) = lo;
        }
        // fill B planes: 64 rows x K packed
        for (int idx = tid; idx < 64 * C4; idx += 128) {
            int row = idx / C4, c4 = idx % C4;
            uint4 v = *(const uint4*)&W[(size_t)(n0 + row) * K + c4 * 4];
            uint2 hi, lo;
            hi.x = __byte_perm(v.x, v.y, SEL_HI); hi.y = __byte_perm(v.z, v.w, SEL_HI);
            lo.x = __byte_perm(v.x, v.y, SEL_LO); lo.y = __byte_perm(v.z, v.w, SEL_LO);
            uint32_t ho = (uint32_t)(row * SAH + c4 * 4) * 2;
            *(uint2*)(smem + offBhi + ho) = hi;
            *(uint2*)(smem + offBlo + ho) = lo;
        }
        __syncthreads();

#pragma unroll
        for (int ks = 0; ks < K / 16; ks++) {
            int kb = ks * 16;
            // A fragments (direct LDS.32 from planes; R4-validated index map)
            uint32_t ah0[4], al0[4], ah1[4], al1[4];
#pragma unroll
            for (int ms = 0; ms < 2; ms++) {
                int mr = mrow0 + ms * 16;
                uint32_t o00 = (uint32_t)((mr    ) * SAH + kb + kp) * 2;
                uint32_t o10 = (uint32_t)((mr + 8) * SAH + kb + kp) * 2;
                uint32_t o01 = (uint32_t)((mr    ) * SAH + kb + 8 + kp) * 2;
                uint32_t o11 = (uint32_t)((mr + 8) * SAH + kb + 8 + kp) * 2;
                uint32_t* ah = ms ? ah1 : ah0;
                uint32_t* al = ms ? al1 : al0;
                ah[0] = *(const uint32_t*)(smem + offAhi + o00);
                ah[1] = *(const uint32_t*)(smem + offAhi + o10);
                ah[2] = *(const uint32_t*)(smem + offAhi + o01);
                ah[3] = *(const uint32_t*)(smem + offAhi + o11);
                al[0] = *(const uint32_t*)(smem + offAlo + o00);
                al[1] = *(const uint32_t*)(smem + offAlo + o10);
                al[2] = *(const uint32_t*)(smem + offAlo + o01);
                al[3] = *(const uint32_t*)(smem + offAlo + o11);
            }
#pragma unroll
            for (int ns = 0; ns < 8; ns++) {
                int nrow = ns * 8 + r;
                uint32_t ob0 = (uint32_t)(nrow * SAH + kb + kp) * 2;
                uint32_t ob1 = (uint32_t)(nrow * SAH + kb + 8 + kp) * 2;
                uint32_t bh0 = *(const uint32_t*)(smem + offBhi + ob0);
                uint32_t bh1 = *(const uint32_t*)(smem + offBhi + ob1);
                uint32_t bl0 = *(const uint32_t*)(smem + offBlo + ob0);
                uint32_t bl1 = *(const uint32_t*)(smem + offBlo + ob1);
                mma16816(acc[0][ns], ah0, bh0, bh1);   // hi*hi
                mma16816(acc[0][ns], ah0, bl0, bl1);   // hi*lo
                mma16816(acc[0][ns], al0, bh0, bh1);   // lo*hi
                mma16816(acc[1][ns], ah1, bh0, bh1);
                mma16816(acc[1][ns], ah1, bl0, bl1);
                mma16816(acc[1][ns], al1, bh0, bh1);
            }
        }
    }

    // ---- epilogue (R4-validated fragment->element map) ----
#pragma unroll
    for (int ms = 0; ms < 2; ms++) {
        int row0 = m0 + mrow0 + ms * 16;
        int row1 = row0 + 8;
#pragma unroll
        for (int ns = 0; ns < 8; ns++) {
            int col = n0 + ns * 8 + kp;
            float bx = bias[col], by = bias[col + 1];
            float v0 = fmaxf(acc[ms][ns][0] + bx, 0.f);
            float v1 = fmaxf(acc[ms][ns][1] + by, 0.f);
            float v2 = fmaxf(acc[ms][ns][2] + bx, 0.f);
            float v3 = fmaxf(acc[ms][ns][3] + by, 0.f);
            if (FINAL) {
                float* o = (float*)outp;
                if (row0 < M) *(float2*)&o[(size_t)row0 * NOUTtot + col] = make_float2(v0, v1);
                if (row1 < M) *(float2*)&o[(size_t)row1 * NOUTtot + col] = make_float2(v2, v3);
            } else {
                uint32_t* o = (uint32_t*)outp;
                if (row0 < M) *(uint2*)&o[(size_t)row0 * NOUTtot + col] = make_uint2(pack_split(v0), pack_split(v1));
                if (row1 < M) *(uint2*)&o[(size_t)row1 * NOUTtot + col] = make_uint2(pack_split(v2), pack_split(v3));
            }
        }
    }
}

// ---------------- launch ----------------
extern "C" void kernel_launch(void* const* d_in, const int* in_sizes, int n_in,
                              void* d_out, int out_size) {
    const float* feat = (const float*)d_in[0];
    const int*   src  = (const int*)d_in[1];
    const int*   dst  = (const int*)d_in[2];
    const float* ew   = (const float*)d_in[3];
    const float* Wp1 = (const float*)d_in[4],  *bp1 = (const float*)d_in[5];
    const float* Ws1 = (const float*)d_in[6],  *Wn1 = (const float*)d_in[7],  *b1 = (const float*)d_in[8];
    const float* Wp2 = (const float*)d_in[9],  *bp2 = (const float*)d_in[10];
    const float* Ws2 = (const float*)d_in[11], *Wn2 = (const float*)d_in[12], *b2 = (const float*)d_in[13];
    const float* Wp3 = (const float*)d_in[14], *bp3 = (const float*)d_in[15];
    const float* Ws3 = (const float*)d_in[16], *Wn3 = (const float*)d_in[17], *b3 = (const float*)d_in[18];
    float* out = (float*)d_out;

    uint32_t *featpk, *hppk, *neighpk, *h1pk, *h2pk, *wpk;
    cudaGetSymbolAddress((void**)&featpk, g_feat_pk);
    cudaGetSymbolAddress((void**)&hppk,   g_hp_pk);
    cudaGetSymbolAddress((void**)&neighpk,g_neigh_pk);
    cudaGetSymbolAddress((void**)&h1pk,   g_h1_pk);
    cudaGetSymbolAddress((void**)&h2pk,   g_h2_pk);
    cudaGetSymbolAddress((void**)&wpk,    g_w_pk);

    const int M = NN;
    const int SM128 = (128 + 64) * (128 + 8) * 2 * 2;   // 104448 B
    const int SM64  = (128 + 64) * (64 + 8)  * 2 * 2;   // 55296 B
    cudaFuncSetAttribute(mma_gemm<128, false, false>, cudaFuncAttributeMaxDynamicSharedMemorySize, SM128);
    cudaFuncSetAttribute(mma_gemm<128, true,  false>, cudaFuncAttributeMaxDynamicSharedMemorySize, SM128);
    cudaFuncSetAttribute(mma_gemm<128, true,  true >, cudaFuncAttributeMaxDynamicSharedMemorySize, SM128);
    cudaFuncSetAttribute(mma_gemm<64,  false, false>, cudaFuncAttributeMaxDynamicSharedMemorySize, SM64);
    cudaFuncSetAttribute(mma_gemm<64,  true,  false>, cudaFuncAttributeMaxDynamicSharedMemorySize, SM64);

    const int MT = (M + 127) / 128;   // 391 M-tiles

    // ---- pack feat + combined weight prep ----
    pack_feat_kernel<<<(NN * 128 + 255) / 256, 256>>>(feat);
    wprep_all_kernel<<<dim3((128 * 128 + 255) / 256, 9), 256>>>(
        Wp1, Ws1, Wn1, Wp2, Ws2, Wn2, Wp3, Ws3, Wn3);

    // ---- CSR build (dst shared across layers) ----
    zero_counts_kernel<<<(NN + 256) / 256, 256>>>();
    hist_kernel<<<(EE + 255) / 256, 256>>>(dst);
    scan_chunk_kernel<<<NSCAN_BLKS, SCAN_BLK>>>(NN + 1);
    scan_partials_kernel<<<1, 64>>>(NSCAN_BLKS);
    scan_add_kernel<<<NSCAN_BLKS, SCAN_BLK>>>(NN + 1);
    scatter_kernel<<<(EE + 255) / 256, 256>>>(src, dst, ew);

    dim3 nblk((NN * 32 + 255) / 256);

    // ---- Layer 1: 128 -> 64 ----
    mma_gemm<128, false, false><<<dim3(MT, 2), 128, SM128>>>(featpk, wpk + WOFF_P1, nullptr, nullptr, bp1, hppk, M, 128);
    neigh_max_pk<128><<<nblk, 256>>>(hppk, neighpk);
    mma_gemm<128, true,  false><<<dim3(MT, 1), 128, SM128>>>(featpk, wpk + WOFF_S1, neighpk, wpk + WOFF_N1, b1, h1pk, M, 64);

    // ---- Layer 2: 64 -> 128 ----
    mma_gemm<64, false, false><<<dim3(MT, 1), 128, SM64>>>(h1pk, wpk + WOFF_P2, nullptr, nullptr, bp2, hppk, M, 64);
    neigh_max_pk<64><<<nblk, 256>>>(hppk, neighpk);
    mma_gemm<64, true,  false><<<dim3(MT, 2), 128, SM64>>>(h1pk, wpk + WOFF_S2, neighpk, wpk + WOFF_N2, b2, h2pk, M, 128);

    // ---- Layer 3: 128 -> 128 ----
    mma_gemm<128, false, false><<<dim3(MT, 2), 128, SM128>>>(h2pk, wpk + WOFF_P3, nullptr, nullptr, bp3, hppk, M, 128);
    neigh_max_pk<128><<<nblk, 256>>>(hppk, neighpk);
    mma_gemm<128, true,  true ><<<dim3(MT, 2), 128, SM128>>>(h2pk, wpk + WOFF_S3, neighpk, wpk + WOFF_N3, b3, out, M, 128);
}

// round 9
// speedup vs baseline: 1.1665x; 1.1665x over previous
#include <cuda_runtime.h>
#include <cuda_bf16.h>
#include <cstdint>

#define NN 50000
#define EE 800000
#define SCAN_BLK 1024
#define NSCAN_BLKS ((NN + 1 + SCAN_BLK - 1) / SCAN_BLK)

// ---------------- scratch (static device memory; no allocs) ----------------
__device__ uint32_t g_feat_pk[NN * 128];
__device__ uint32_t g_hp_pk[NN * 128];
__device__ uint32_t g_neigh_pk[NN * 128];
__device__ uint32_t g_h1_pk[NN * 64];
__device__ uint32_t g_h2_pk[NN * 128];
__device__ uint32_t g_w_pk[102400];     // transposed split-bf16 weights, [Nout][K]
__device__ int   g_rowptr[NN + 1];
__device__ int   g_cursor[NN];
__device__ int   g_src_sorted[EE];
__device__ float g_ew_sorted[EE];
__device__ int   g_partials[NSCAN_BLKS];

// weight scratch offsets (uint32 elements), layout [Nout][K]
#define WOFF_P1 0        // 128x128
#define WOFF_S1 16384    // 64x128
#define WOFF_N1 24576    // 64x128
#define WOFF_P2 32768    // 64x64
#define WOFF_S2 36864    // 128x64
#define WOFF_N2 45056    // 128x64
#define WOFF_P3 53248    // 128x128
#define WOFF_S3 69632    // 128x128
#define WOFF_N3 86016    // 128x128

// ---------------- split-bf16 helpers ----------------
// packed u32: high 16 bits = bf16(x) ("hi"), low 16 bits = bf16(x - hi) ("lo")
__device__ __forceinline__ uint32_t pack_split(float x) {
    __nv_bfloat16 h = __float2bfloat16(x);
    float hf = __bfloat162float(h);
    __nv_bfloat16 l = __float2bfloat16(x - hf);
    return ((uint32_t)__bfloat16_as_ushort(h) << 16) | (uint32_t)__bfloat16_as_ushort(l);
}
__device__ __forceinline__ float unpack_split(uint32_t w) {
    float hf = __bfloat162float(__ushort_as_bfloat16((unsigned short)(w >> 16)));
    float lf = __bfloat162float(__ushort_as_bfloat16((unsigned short)(w & 0xFFFFu)));
    return hf + lf;
}

// ---------------- mma.sync m16n8k16 bf16 (baseline PTX, sm_80+) ----------------
__device__ __forceinline__ void mma16816(float* c, const uint32_t* a, uint32_t b0, uint32_t b1) {
    asm volatile(
        "mma.sync.aligned.m16n8k16.row.col.f32.bf16.bf16.f32 "
        "{%0,%1,%2,%3}, {%4,%5,%6,%7}, {%8,%9}, {%0,%1,%2,%3};"
        : "+f"(c[0]), "+f"(c[1]), "+f"(c[2]), "+f"(c[3])
        : "r"(a[0]), "r"(a[1]), "r"(a[2]), "r"(a[3]), "r"(b0), "r"(b1));
}
#define SEL_HI 0x7632u   // {a.hi16, b.hi16}
#define SEL_LO 0x5410u   // {a.lo16, b.lo16}

// ---------------- pack feat ----------------
__global__ void pack_feat_kernel(const float* __restrict__ f) {
    int i = blockIdx.x * blockDim.x + threadIdx.x;
    if (i < NN * 128) g_feat_pk[i] = pack_split(f[i]);
}

// ---------------- combined weight prep: transpose + split-pack all 9 weights ----------------
__global__ void wprep_all_kernel(
    const float* __restrict__ W0, const float* __restrict__ W1t, const float* __restrict__ W2t,
    const float* __restrict__ W3, const float* __restrict__ W4, const float* __restrict__ W5,
    const float* __restrict__ W6, const float* __restrict__ W7, const float* __restrict__ W8)
{
    const float* Ws[9] = {W0, W1t, W2t, W3, W4, W5, W6, W7, W8};
    const int off[9] = {WOFF_P1, WOFF_S1, WOFF_N1, WOFF_P2, WOFF_S2, WOFF_N2, WOFF_P3, WOFF_S3, WOFF_N3};
    const int Kd [9] = {128, 128, 128, 64, 64, 64, 128, 128, 128};
    const int Nd [9] = {128, 64, 64, 64, 128, 128, 128, 128, 128};
    int s = blockIdx.y;
    int sz = Kd[s] * Nd[s];
    int i = blockIdx.x * blockDim.x + threadIdx.x;
    if (i < sz) {
        int k = i / Nd[s], n = i % Nd[s];
        g_w_pk[off[s] + n * Kd[s] + k] = pack_split(Ws[s][k * Nd[s] + n]);
    }
}

// ---------------- CSR build ----------------
__global__ void zero_counts_kernel() {
    int i = blockIdx.x * blockDim.x + threadIdx.x;
    if (i <= NN) g_rowptr[i] = 0;
}
__global__ void hist_kernel(const int* __restrict__ dst) {
    int i = blockIdx.x * blockDim.x + threadIdx.x;
    if (i < EE) atomicAdd(&g_rowptr[dst[i] + 1], 1);
}
__global__ void scan_chunk_kernel(int n) {
    __shared__ int sdata[SCAN_BLK];
    int tid = threadIdx.x;
    int i = blockIdx.x * SCAN_BLK + tid;
    int v = (i < n) ? g_rowptr[i] : 0;
    sdata[tid] = v;
    __syncthreads();
    for (int off = 1; off < SCAN_BLK; off <<= 1) {
        int t = (tid >= off) ? sdata[tid - off] : 0;
        __syncthreads();
        sdata[tid] += t;
        __syncthreads();
    }
    if (i < n) g_rowptr[i] = sdata[tid];
    if (tid == SCAN_BLK - 1) g_partials[blockIdx.x] = sdata[tid];
}
__global__ void scan_partials_kernel(int nb) {
    __shared__ int sh[64];
    int t = threadIdx.x;
    sh[t] = (t < nb) ? g_partials[t] : 0;
    __syncthreads();
    for (int off = 1; off < 64; off <<= 1) {
        int x = (t >= off) ? sh[t - off] : 0;
        __syncthreads();
        sh[t] += x;
        __syncthreads();
    }
    if (t < nb) g_partials[t] = sh[t];
}
__global__ void scan_add_kernel(int n) {
    int i = blockIdx.x * SCAN_BLK + threadIdx.x;
    if (i < n) {
        int off = (blockIdx.x > 0) ? g_partials[blockIdx.x - 1] : 0;
        int val = g_rowptr[i] + off;
        g_rowptr[i] = val;
        if (i < NN) g_cursor[i] = val;
    }
}
__global__ void scatter_kernel(const int* __restrict__ src,
                               const int* __restrict__ dst,
                               const float* __restrict__ ew) {
    int e = blockIdx.x * blockDim.x + threadIdx.x;
    if (e < EE) {
        int p = atomicAdd(&g_cursor[dst[e]], 1);
        g_src_sorted[p] = src[e];
        g_ew_sorted[p]  = ew[e];
    }
}

// ---------------- neighbor max (packed in/out, warp per node, no atomics) ----------------
template <int DIN>
__global__ void neigh_max_pk(const uint32_t* __restrict__ hp, uint32_t* __restrict__ out) {
    int warp = (blockIdx.x * blockDim.x + threadIdx.x) >> 5;
    int lane = threadIdx.x & 31;
    if (warp >= NN) return;
    int beg = g_rowptr[warp];
    int end = g_rowptr[warp + 1];
    if (DIN == 128) {
        float m0 = 0.f, m1 = 0.f, m2 = 0.f, m3 = 0.f;
        int e = beg;
        for (; e + 1 < end; e += 2) {       // 2-way unroll: MLP 2
            int s0 = g_src_sorted[e],     s1 = g_src_sorted[e + 1];
            float w0 = g_ew_sorted[e],    w1 = g_ew_sorted[e + 1];
            uint4 p0 = *(const uint4*)&hp[(size_t)s0 * 128 + lane * 4];
            uint4 p1 = *(const uint4*)&hp[(size_t)s1 * 128 + lane * 4];
            m0 = fmaxf(m0, unpack_split(p0.x) * w0);
            m1 = fmaxf(m1, unpack_split(p0.y) * w0);
            m2 = fmaxf(m2, unpack_split(p0.z) * w0);
            m3 = fmaxf(m3, unpack_split(p0.w) * w0);
            m0 = fmaxf(m0, unpack_split(p1.x) * w1);
            m1 = fmaxf(m1, unpack_split(p1.y) * w1);
            m2 = fmaxf(m2, unpack_split(p1.z) * w1);
            m3 = fmaxf(m3, unpack_split(p1.w) * w1);
        }
        if (e < end) {
            int s = g_src_sorted[e];
            float w = g_ew_sorted[e];
            uint4 p = *(const uint4*)&hp[(size_t)s * 128 + lane * 4];
            m0 = fmaxf(m0, unpack_split(p.x) * w);
            m1 = fmaxf(m1, unpack_split(p.y) * w);
            m2 = fmaxf(m2, unpack_split(p.z) * w);
            m3 = fmaxf(m3, unpack_split(p.w) * w);
        }
        uint4 o;
        o.x = pack_split(m0); o.y = pack_split(m1);
        o.z = pack_split(m2); o.w = pack_split(m3);
        *(uint4*)&out[(size_t)warp * 128 + lane * 4] = o;
    } else {
        float m0 = 0.f, m1 = 0.f;
        int e = beg;
        for (; e + 1 < end; e += 2) {
            int s0 = g_src_sorted[e],  s1 = g_src_sorted[e + 1];
            float w0 = g_ew_sorted[e], w1 = g_ew_sorted[e + 1];
            uint2 p0 = *(const uint2*)&hp[(size_t)s0 * 64 + lane * 2];
            uint2 p1 = *(const uint2*)&hp[(size_t)s1 * 64 + lane * 2];
            m0 = fmaxf(m0, unpack_split(p0.x) * w0);
            m1 = fmaxf(m1, unpack_split(p0.y) * w0);
            m0 = fmaxf(m0, unpack_split(p1.x) * w1);
            m1 = fmaxf(m1, unpack_split(p1.y) * w1);
        }
        if (e < end) {
            int s = g_src_sorted[e];
            float w = g_ew_sorted[e];
            uint2 p = *(const uint2*)&hp[(size_t)s * 64 + lane * 2];
            m0 = fmaxf(m0, unpack_split(p.x) * w);
            m1 = fmaxf(m1, unpack_split(p.y) * w);
        }
        uint2 o;
        o.x = pack_split(m0); o.y = pack_split(m1);
        *(uint2*)&out[(size_t)warp * 64 + lane * 2] = o;
    }
}

// ---------------- HMMA GEMM: split-plane smem, direct LDS fragments ----------------
// CTA 256 threads (8 warps), tile 128 x 64. Warp grid 4(M) x 2(N) of 32x32 warp tiles
// (2 m-subs x 4 n-subs of m16n8k16). smem: bf16 hi/lo planes for A (128 x K) and
// B (64 x K), row stride K+8 halfwords. hi/lo split done ONCE at fill (PRMT amortized);
// inner loop is LDS.32 + HMMA only. Split-bf16 3-pass: hi*hi + hi*lo + lo*hi, fp32 acc.
template <int K, bool DUAL, bool FINAL>
__global__ __launch_bounds__(256) void mma_gemm(
    const uint32_t* __restrict__ A1, const uint32_t* __restrict__ W1,
    const uint32_t* __restrict__ A2, const uint32_t* __restrict__ W2,
    const float* __restrict__ bias, void* __restrict__ outp,
    int M, int NOUTtot)
{
    constexpr int SAH = K + 8;                     // halfword stride per row
    constexpr uint32_t offAhi = 0;
    constexpr uint32_t offAlo = offAhi + 128 * SAH * 2;
    constexpr uint32_t offBhi = offAlo + 128 * SAH * 2;
    constexpr uint32_t offBlo = offBhi + 64 * SAH * 2;

    extern __shared__ char smem[];

    int tid = threadIdx.x;
    int warp = tid >> 5, lane = tid & 31;
    int wm = warp & 3;           // 0..3  -> m offset wm*32
    int wn = warp >> 2;          // 0..1  -> n offset wn*32
    int m0 = blockIdx.x * 128;
    int n0 = blockIdx.y * 64;

    int r  = lane >> 2;          // 0..7
    int kp = (lane & 3) * 2;     // 0,2,4,6
    int mrow0 = wm * 32 + r;     // m-sub 0 fragment row; m-sub 1 = +16

    float acc[2][4][4];
#pragma unroll
    for (int ms = 0; ms < 2; ms++)
#pragma unroll
        for (int ns = 0; ns < 4; ns++)
#pragma unroll
            for (int j = 0; j < 4; j++) acc[ms][ns][j] = 0.f;

    const int npass = DUAL ? 2 : 1;
    for (int phase = 0; phase < npass; phase++) {
        const uint32_t* A = (phase == 0) ? A1 : A2;
        const uint32_t* W = (phase == 0) ? W1 : W2;
        if (phase) __syncthreads();           // all reads of prev tiles done

        // fill A planes: 128 rows x K packed -> hi/lo bf16 planes (PRMT once here)
        constexpr int C4 = K / 4;
        for (int idx = tid; idx < 128 * C4; idx += 256) {
            int row = idx / C4, c4 = idx % C4;
            uint4 v = make_uint4(0, 0, 0, 0);
            if (m0 + row < M) v = *(const uint4*)&A[(size_t)(m0 + row) * K + c4 * 4];
            uint2 hi, lo;
            hi.x = __byte_perm(v.x, v.y, SEL_HI); hi.y = __byte_perm(v.z, v.w, SEL_HI);
            lo.x = __byte_perm(v.x, v.y, SEL_LO); lo.y = __byte_perm(v.z, v.w, SEL_LO);
            uint32_t ho = (uint32_t)(row * SAH + c4 * 4) * 2;
            *(uint2*)(smem + offAhi + ho) = hi;
            *(uint2*)(smem + offAlo + ho) = lo;
        }
        // fill B planes: 64 rows x K packed
        for (int idx = tid; idx < 64 * C4; idx += 256) {
            int row = idx / C4, c4 = idx % C4;
            uint4 v = *(const uint4*)&W[(size_t)(n0 + row) * K + c4 * 4];
            uint2 hi, lo;
            hi.x = __byte_perm(v.x, v.y, SEL_HI); hi.y = __byte_perm(v.z, v.w, SEL_HI);
            lo.x = __byte_perm(v.x, v.y, SEL_LO); lo.y = __byte_perm(v.z, v.w, SEL_LO);
            uint32_t ho = (uint32_t)(row * SAH + c4 * 4) * 2;
            *(uint2*)(smem + offBhi + ho) = hi;
            *(uint2*)(smem + offBlo + ho) = lo;
        }
        __syncthreads();

#pragma unroll
        for (int ks = 0; ks < K / 16; ks++) {
            int kb = ks * 16;
            // A fragments (direct LDS.32 from planes; R4-validated index map)
            uint32_t ah0[4], al0[4], ah1[4], al1[4];
#pragma unroll
            for (int ms = 0; ms < 2; ms++) {
                int mr = mrow0 + ms * 16;
                uint32_t o00 = (uint32_t)((mr    ) * SAH + kb + kp) * 2;
                uint32_t o10 = (uint32_t)((mr + 8) * SAH + kb + kp) * 2;
                uint32_t o01 = (uint32_t)((mr    ) * SAH + kb + 8 + kp) * 2;
                uint32_t o11 = (uint32_t)((mr + 8) * SAH + kb + 8 + kp) * 2;
                uint32_t* ah = ms ? ah1 : ah0;
                uint32_t* al = ms ? al1 : al0;
                ah[0] = *(const uint32_t*)(smem + offAhi + o00);
                ah[1] = *(const uint32_t*)(smem + offAhi + o10);
                ah[2] = *(const uint32_t*)(smem + offAhi + o01);
                ah[3] = *(const uint32_t*)(smem + offAhi + o11);
                al[0] = *(const uint32_t*)(smem + offAlo + o00);
                al[1] = *(const uint32_t*)(smem + offAlo + o10);
                al[2] = *(const uint32_t*)(smem + offAlo + o01);
                al[3] = *(const uint32_t*)(smem + offAlo + o11);
            }
#pragma unroll
            for (int ns = 0; ns < 4; ns++) {
                int nrow = wn * 32 + ns * 8 + r;
                uint32_t ob0 = (uint32_t)(nrow * SAH + kb + kp) * 2;
                uint32_t ob1 = (uint32_t)(nrow * SAH + kb + 8 + kp) * 2;
                uint32_t bh0 = *(const uint32_t*)(smem + offBhi + ob0);
                uint32_t bh1 = *(const uint32_t*)(smem + offBhi + ob1);
                uint32_t bl0 = *(const uint32_t*)(smem + offBlo + ob0);
                uint32_t bl1 = *(const uint32_t*)(smem + offBlo + ob1);
                mma16816(acc[0][ns], ah0, bh0, bh1);   // hi*hi
                mma16816(acc[0][ns], ah0, bl0, bl1);   // hi*lo
                mma16816(acc[0][ns], al0, bh0, bh1);   // lo*hi
                mma16816(acc[1][ns], ah1, bh0, bh1);
                mma16816(acc[1][ns], ah1, bl0, bl1);
                mma16816(acc[1][ns], al1, bh0, bh1);
            }
        }
    }

    // ---- epilogue (R4-validated fragment->element map) ----
#pragma unroll
    for (int ms = 0; ms < 2; ms++) {
        int row0 = m0 + mrow0 + ms * 16;
        int row1 = row0 + 8;
#pragma unroll
        for (int ns = 0; ns < 4; ns++) {
            int col = n0 + wn * 32 + ns * 8 + kp;
            float bx = bias[col], by = bias[col + 1];
            float v0 = fmaxf(acc[ms][ns][0] + bx, 0.f);
            float v1 = fmaxf(acc[ms][ns][1] + by, 0.f);
            float v2 = fmaxf(acc[ms][ns][2] + bx, 0.f);
            float v3 = fmaxf(acc[ms][ns][3] + by, 0.f);
            if (FINAL) {
                float* o = (float*)outp;
                if (row0 < M) *(float2*)&o[(size_t)row0 * NOUTtot + col] = make_float2(v0, v1);
                if (row1 < M) *(float2*)&o[(size_t)row1 * NOUTtot + col] = make_float2(v2, v3);
            } else {
                uint32_t* o = (uint32_t*)outp;
                if (row0 < M) *(uint2*)&o[(size_t)row0 * NOUTtot + col] = make_uint2(pack_split(v0), pack_split(v1));
                if (row1 < M) *(uint2*)&o[(size_t)row1 * NOUTtot + col] = make_uint2(pack_split(v2), pack_split(v3));
            }
        }
    }
}

// ---------------- launch ----------------
extern "C" void kernel_launch(void* const* d_in, const int* in_sizes, int n_in,
                              void* d_out, int out_size) {
    const float* feat = (const float*)d_in[0];
    const int*   src  = (const int*)d_in[1];
    const int*   dst  = (const int*)d_in[2];
    const float* ew   = (const float*)d_in[3];
    const float* Wp1 = (const float*)d_in[4],  *bp1 = (const float*)d_in[5];
    const float* Ws1 = (const float*)d_in[6],  *Wn1 = (const float*)d_in[7],  *b1 = (const float*)d_in[8];
    const float* Wp2 = (const float*)d_in[9],  *bp2 = (const float*)d_in[10];
    const float* Ws2 = (const float*)d_in[11], *Wn2 = (const float*)d_in[12], *b2 = (const float*)d_in[13];
    const float* Wp3 = (const float*)d_in[14], *bp3 = (const float*)d_in[15];
    const float* Ws3 = (const float*)d_in[16], *Wn3 = (const float*)d_in[17], *b3 = (const float*)d_in[18];
    float* out = (float*)d_out;

    uint32_t *featpk, *hppk, *neighpk, *h1pk, *h2pk, *wpk;
    cudaGetSymbolAddress((void**)&featpk, g_feat_pk);
    cudaGetSymbolAddress((void**)&hppk,   g_hp_pk);
    cudaGetSymbolAddress((void**)&neighpk,g_neigh_pk);
    cudaGetSymbolAddress((void**)&h1pk,   g_h1_pk);
    cudaGetSymbolAddress((void**)&h2pk,   g_h2_pk);
    cudaGetSymbolAddress((void**)&wpk,    g_w_pk);

    const int M = NN;
    const int SM128 = (128 + 64) * (128 + 8) * 2 * 2;   // 104448 B
    const int SM64  = (128 + 64) * (64 + 8)  * 2 * 2;   // 55296 B
    cudaFuncSetAttribute(mma_gemm<128, false, false>, cudaFuncAttributeMaxDynamicSharedMemorySize, SM128);
    cudaFuncSetAttribute(mma_gemm<128, true,  false>, cudaFuncAttributeMaxDynamicSharedMemorySize, SM128);
    cudaFuncSetAttribute(mma_gemm<128, true,  true >, cudaFuncAttributeMaxDynamicSharedMemorySize, SM128);
    cudaFuncSetAttribute(mma_gemm<64,  false, false>, cudaFuncAttributeMaxDynamicSharedMemorySize, SM64);
    cudaFuncSetAttribute(mma_gemm<64,  true,  false>, cudaFuncAttributeMaxDynamicSharedMemorySize, SM64);

    const int MT = (M + 127) / 128;   // 391 M-tiles

    // ---- ordering note: launch #4 = L1 pool GEMM so the fixed ncu window
    // (empirically the 4th launch) captures a GEMM instead of hist/scan.
    pack_feat_kernel<<<(NN * 128 + 255) / 256, 256>>>(feat);                      // 1
    wprep_all_kernel<<<dim3((128 * 128 + 255) / 256, 9), 256>>>(                  // 2
        Wp1, Ws1, Wn1, Wp2, Ws2, Wn2, Wp3, Ws3, Wn3);
    zero_counts_kernel<<<(NN + 256) / 256, 256>>>();                              // 3
    mma_gemm<128, false, false><<<dim3(MT, 2), 256, SM128>>>(                     // 4 <- ncu
        featpk, wpk + WOFF_P1, nullptr, nullptr, bp1, hppk, M, 128);
    hist_kernel<<<(EE + 255) / 256, 256>>>(dst);                                  // 5
    scan_chunk_kernel<<<NSCAN_BLKS, SCAN_BLK>>>(NN + 1);                          // 6
    scan_partials_kernel<<<1, 64>>>(NSCAN_BLKS);                                  // 7
    scan_add_kernel<<<NSCAN_BLKS, SCAN_BLK>>>(NN + 1);                            // 8
    scatter_kernel<<<(EE + 255) / 256, 256>>>(src, dst, ew);                      // 9

    dim3 nblk((NN * 32 + 255) / 256);

    // ---- Layer 1: 128 -> 64 (pool GEMM already launched above) ----
    neigh_max_pk<128><<<nblk, 256>>>(hppk, neighpk);
    mma_gemm<128, true,  false><<<dim3(MT, 1), 256, SM128>>>(featpk, wpk + WOFF_S1, neighpk, wpk + WOFF_N1, b1, h1pk, M, 64);

    // ---- Layer 2: 64 -> 128 ----
    mma_gemm<64, false, false><<<dim3(MT, 1), 256, SM64>>>(h1pk, wpk + WOFF_P2, nullptr, nullptr, bp2, hppk, M, 64);
    neigh_max_pk<64><<<nblk, 256>>>(hppk, neighpk);
    mma_gemm<64, true,  false><<<dim3(MT, 2), 256, SM64>>>(h1pk, wpk + WOFF_S2, neighpk, wpk + WOFF_N2, b2, h2pk, M, 128);

    // ---- Layer 3: 128 -> 128 ----
    mma_gemm<128, false, false><<<dim3(MT, 2), 256, SM128>>>(h2pk, wpk + WOFF_P3, nullptr, nullptr, bp3, hppk, M, 128);
    neigh_max_pk<128><<<nblk, 256>>>(hppk, neighpk);
    mma_gemm<128, true,  true ><<<dim3(MT, 2), 256, SM128>>>(h2pk, wpk + WOFF_S3, neighpk, wpk + WOFF_N3, b3, out, M, 128);
}

// round 10
// speedup vs baseline: 1.1871x; 1.0177x over previous
#include <cuda_runtime.h>
#include <cuda_bf16.h>
#include <cstdint>

#define NN 50000
#define EE 800000
#define SCAN_BLK 1024
#define NSCAN_BLKS ((NN + 1 + SCAN_BLK - 1) / SCAN_BLK)

// ---------------- scratch (static device memory; no allocs) ----------------
__device__ uint32_t g_feat_pk[NN * 128];
__device__ uint32_t g_hp_pk[NN * 128];
__device__ uint32_t g_neigh_pk[NN * 128];
__device__ uint32_t g_h1_pk[NN * 64];
__device__ uint32_t g_h2_pk[NN * 128];
__device__ uint32_t g_w_pk[102400];     // transposed split-bf16 weights, [Nout][K]
__device__ int   g_rowptr[NN + 1];
__device__ int   g_cursor[NN];
__device__ int   g_src_sorted[EE];
__device__ float g_ew_sorted[EE];
__device__ int   g_partials[NSCAN_BLKS];

// weight scratch offsets (uint32 elements), layout [Nout][K]
#define WOFF_P1 0        // 128x128
#define WOFF_S1 16384    // 64x128
#define WOFF_N1 24576    // 64x128
#define WOFF_P2 32768    // 64x64
#define WOFF_S2 36864    // 128x64
#define WOFF_N2 45056    // 128x64
#define WOFF_P3 53248    // 128x128
#define WOFF_S3 69632    // 128x128
#define WOFF_N3 86016    // 128x128

// ---------------- split-bf16 helpers ----------------
// packed u32: high 16 bits = bf16(x) ("hi"), low 16 bits = bf16(x - hi) ("lo")
__device__ __forceinline__ uint32_t pack_split(float x) {
    __nv_bfloat16 h = __float2bfloat16(x);
    float hf = __bfloat162float(h);
    __nv_bfloat16 l = __float2bfloat16(x - hf);
    return ((uint32_t)__bfloat16_as_ushort(h) << 16) | (uint32_t)__bfloat16_as_ushort(l);
}
__device__ __forceinline__ float unpack_split(uint32_t w) {
    float hf = __bfloat162float(__ushort_as_bfloat16((unsigned short)(w >> 16)));
    float lf = __bfloat162float(__ushort_as_bfloat16((unsigned short)(w & 0xFFFFu)));
    return hf + lf;
}

// ---------------- mma.sync m16n8k16 bf16 (baseline PTX, sm_80+) ----------------
__device__ __forceinline__ void mma16816(float* c, const uint32_t* a, uint32_t b0, uint32_t b1) {
    asm volatile(
        "mma.sync.aligned.m16n8k16.row.col.f32.bf16.bf16.f32 "
        "{%0,%1,%2,%3}, {%4,%5,%6,%7}, {%8,%9}, {%0,%1,%2,%3};"
        : "+f"(c[0]), "+f"(c[1]), "+f"(c[2]), "+f"(c[3])
        : "r"(a[0]), "r"(a[1]), "r"(a[2]), "r"(a[3]), "r"(b0), "r"(b1));
}
#define SEL_HI 0x7632u   // {a.hi16, b.hi16}
#define SEL_LO 0x5410u   // {a.lo16, b.lo16}

// ---------------- pack feat ----------------
__global__ void pack_feat_kernel(const float* __restrict__ f) {
    int i = blockIdx.x * blockDim.x + threadIdx.x;
    if (i < NN * 128) g_feat_pk[i] = pack_split(f[i]);
}

// ---------------- combined weight prep: transpose + split-pack all 9 weights ----------------
__global__ void wprep_all_kernel(
    const float* __restrict__ W0, const float* __restrict__ W1t, const float* __restrict__ W2t,
    const float* __restrict__ W3, const float* __restrict__ W4, const float* __restrict__ W5,
    const float* __restrict__ W6, const float* __restrict__ W7, const float* __restrict__ W8)
{
    const float* Ws[9] = {W0, W1t, W2t, W3, W4, W5, W6, W7, W8};
    const int off[9] = {WOFF_P1, WOFF_S1, WOFF_N1, WOFF_P2, WOFF_S2, WOFF_N2, WOFF_P3, WOFF_S3, WOFF_N3};
    const int Kd [9] = {128, 128, 128, 64, 64, 64, 128, 128, 128};
    const int Nd [9] = {128, 64, 64, 64, 128, 128, 128, 128, 128};
    int s = blockIdx.y;
    int sz = Kd[s] * Nd[s];
    int i = blockIdx.x * blockDim.x + threadIdx.x;
    if (i < sz) {
        int k = i / Nd[s], n = i % Nd[s];
        g_w_pk[off[s] + n * Kd[s] + k] = pack_split(Ws[s][k * Nd[s] + n]);
    }
}

// ---------------- CSR build ----------------
__global__ void zero_counts_kernel() {
    int i = blockIdx.x * blockDim.x + threadIdx.x;
    if (i <= NN) g_rowptr[i] = 0;
}
__global__ void hist_kernel(const int* __restrict__ dst) {
    int i = blockIdx.x * blockDim.x + threadIdx.x;
    if (i < EE) atomicAdd(&g_rowptr[dst[i] + 1], 1);
}
__global__ void scan_chunk_kernel(int n) {
    __shared__ int sdata[SCAN_BLK];
    int tid = threadIdx.x;
    int i = blockIdx.x * SCAN_BLK + tid;
    int v = (i < n) ? g_rowptr[i] : 0;
    sdata[tid] = v;
    __syncthreads();
    for (int off = 1; off < SCAN_BLK; off <<= 1) {
        int t = (tid >= off) ? sdata[tid - off] : 0;
        __syncthreads();
        sdata[tid] += t;
        __syncthreads();
    }
    if (i < n) g_rowptr[i] = sdata[tid];
    if (tid == SCAN_BLK - 1) g_partials[blockIdx.x] = sdata[tid];
}
__global__ void scan_partials_kernel(int nb) {
    __shared__ int sh[64];
    int t = threadIdx.x;
    sh[t] = (t < nb) ? g_partials[t] : 0;
    __syncthreads();
    for (int off = 1; off < 64; off <<= 1) {
        int x = (t >= off) ? sh[t - off] : 0;
        __syncthreads();
        sh[t] += x;
        __syncthreads();
    }
    if (t < nb) g_partials[t] = sh[t];
}
__global__ void scan_add_kernel(int n) {
    int i = blockIdx.x * SCAN_BLK + threadIdx.x;
    if (i < n) {
        int off = (blockIdx.x > 0) ? g_partials[blockIdx.x - 1] : 0;
        int val = g_rowptr[i] + off;
        g_rowptr[i] = val;
        if (i < NN) g_cursor[i] = val;
    }
}
__global__ void scatter_kernel(const int* __restrict__ src,
                               const int* __restrict__ dst,
                               const float* __restrict__ ew) {
    int e = blockIdx.x * blockDim.x + threadIdx.x;
    if (e < EE) {
        int p = atomicAdd(&g_cursor[dst[e]], 1);
        g_src_sorted[p] = src[e];
        g_ew_sorted[p]  = ew[e];
    }
}

// ---------------- neighbor max (packed in/out, warp per node, no atomics) ----------------
template <int DIN>
__global__ void neigh_max_pk(const uint32_t* __restrict__ hp, uint32_t* __restrict__ out) {
    int warp = (blockIdx.x * blockDim.x + threadIdx.x) >> 5;
    int lane = threadIdx.x & 31;
    if (warp >= NN) return;
    int beg = g_rowptr[warp];
    int end = g_rowptr[warp + 1];
    if (DIN == 128) {
        float m0 = 0.f, m1 = 0.f, m2 = 0.f, m3 = 0.f;
        int e = beg;
        for (; e + 1 < end; e += 2) {       // 2-way unroll: MLP 2
            int s0 = g_src_sorted[e],     s1 = g_src_sorted[e + 1];
            float w0 = g_ew_sorted[e],    w1 = g_ew_sorted[e + 1];
            uint4 p0 = *(const uint4*)&hp[(size_t)s0 * 128 + lane * 4];
            uint4 p1 = *(const uint4*)&hp[(size_t)s1 * 128 + lane * 4];
            m0 = fmaxf(m0, unpack_split(p0.x) * w0);
            m1 = fmaxf(m1, unpack_split(p0.y) * w0);
            m2 = fmaxf(m2, unpack_split(p0.z) * w0);
            m3 = fmaxf(m3, unpack_split(p0.w) * w0);
            m0 = fmaxf(m0, unpack_split(p1.x) * w1);
            m1 = fmaxf(m1, unpack_split(p1.y) * w1);
            m2 = fmaxf(m2, unpack_split(p1.z) * w1);
            m3 = fmaxf(m3, unpack_split(p1.w) * w1);
        }
        if (e < end) {
            int s = g_src_sorted[e];
            float w = g_ew_sorted[e];
            uint4 p = *(const uint4*)&hp[(size_t)s * 128 + lane * 4];
            m0 = fmaxf(m0, unpack_split(p.x) * w);
            m1 = fmaxf(m1, unpack_split(p.y) * w);
            m2 = fmaxf(m2, unpack_split(p.z) * w);
            m3 = fmaxf(m3, unpack_split(p.w) * w);
        }
        uint4 o;
        o.x = pack_split(m0); o.y = pack_split(m1);
        o.z = pack_split(m2); o.w = pack_split(m3);
        *(uint4*)&out[(size_t)warp * 128 + lane * 4] = o;
    } else {
        float m0 = 0.f, m1 = 0.f;
        int e = beg;
        for (; e + 1 < end; e += 2) {
            int s0 = g_src_sorted[e],  s1 = g_src_sorted[e + 1];
            float w0 = g_ew_sorted[e], w1 = g_ew_sorted[e + 1];
            uint2 p0 = *(const uint2*)&hp[(size_t)s0 * 64 + lane * 2];
            uint2 p1 = *(const uint2*)&hp[(size_t)s1 * 64 + lane * 2];
            m0 = fmaxf(m0, unpack_split(p0.x) * w0);
            m1 = fmaxf(m1, unpack_split(p0.y) * w0);
            m0 = fmaxf(m0, unpack_split(p1.x) * w1);
            m1 = fmaxf(m1, unpack_split(p1.y) * w1);
        }
        if (e < end) {
            int s = g_src_sorted[e];
            float w = g_ew_sorted[e];
            uint2 p = *(const uint2*)&hp[(size_t)s * 64 + lane * 2];
            m0 = fmaxf(m0, unpack_split(p.x) * w);
            m1 = fmaxf(m1, unpack_split(p.y) * w);
        }
        uint2 o;
        o.x = pack_split(m0); o.y = pack_split(m1);
        *(uint2*)&out[(size_t)warp * 64 + lane * 2] = o;
    }
}

// ---------------- HMMA GEMM: split-plane smem, register-pipelined mainloop ----------
// CTA 256 threads (8 warps), tile 128 x 64. Warp grid 4(M) x 2(N) of 32x32 warp tiles
// (2 m-subs x 4 n-subs of m16n8k16). smem: bf16 hi/lo planes for A (128 x K) and
// B (64 x K), row stride K+8 halfwords. hi/lo split done ONCE at fill (PRMT amortized).
// k-loop register double-buffers: fragments for ks+1 are prefetched while ks's 24
// HMMA execute, hiding the 29-cyc LDS latency. Split-bf16 3-pass, fp32 acc.
template <int K, bool DUAL, bool FINAL>
__global__ __launch_bounds__(256, 2) void mma_gemm(
    const uint32_t* __restrict__ A1, const uint32_t* __restrict__ W1,
    const uint32_t* __restrict__ A2, const uint32_t* __restrict__ W2,
    const float* __restrict__ bias, void* __restrict__ outp,
    int M, int NOUTtot)
{
    constexpr int SAH = K + 8;                     // halfword stride per row
    constexpr uint32_t offAhi = 0;
    constexpr uint32_t offAlo = offAhi + 128 * SAH * 2;
    constexpr uint32_t offBhi = offAlo + 128 * SAH * 2;
    constexpr uint32_t offBlo = offBhi + 64 * SAH * 2;
    constexpr int KS = K / 16;

    extern __shared__ char smem[];

    int tid = threadIdx.x;
    int warp = tid >> 5, lane = tid & 31;
    int wm = warp & 3;           // 0..3  -> m offset wm*32
    int wn = warp >> 2;          // 0..1  -> n offset wn*32
    int m0 = blockIdx.x * 128;
    int n0 = blockIdx.y * 64;

    int r  = lane >> 2;          // 0..7
    int kp = (lane & 3) * 2;     // 0,2,4,6
    int mrow0 = wm * 32 + r;     // m-sub 0 fragment row; m-sub 1 = +16

    float acc[2][4][4];
#pragma unroll
    for (int ms = 0; ms < 2; ms++)
#pragma unroll
        for (int ns = 0; ns < 4; ns++)
#pragma unroll
            for (int j = 0; j < 4; j++) acc[ms][ns][j] = 0.f;

    // double-buffered fragments
    uint32_t ahB[2][2][4], alB[2][2][4];   // [buf][ms][reg]
    uint32_t bhB[2][4][2], blB[2][4][2];   // [buf][ns][reg]

    // fragment load (R4-validated index map)
#define LOAD_FRAGS(ksv, bufv)                                                        \
    {                                                                                \
        int kb_ = (ksv) * 16;                                                        \
        _Pragma("unroll")                                                            \
        for (int ms = 0; ms < 2; ms++) {                                             \
            int mr = mrow0 + ms * 16;                                                \
            uint32_t o00 = (uint32_t)((mr    ) * SAH + kb_ + kp) * 2;                \
            uint32_t o10 = (uint32_t)((mr + 8) * SAH + kb_ + kp) * 2;                \
            uint32_t o01 = (uint32_t)((mr    ) * SAH + kb_ + 8 + kp) * 2;            \
            uint32_t o11 = (uint32_t)((mr + 8) * SAH + kb_ + 8 + kp) * 2;            \
            ahB[bufv][ms][0] = *(const uint32_t*)(smem + offAhi + o00);              \
            ahB[bufv][ms][1] = *(const uint32_t*)(smem + offAhi + o10);              \
            ahB[bufv][ms][2] = *(const uint32_t*)(smem + offAhi + o01);              \
            ahB[bufv][ms][3] = *(const uint32_t*)(smem + offAhi + o11);              \
            alB[bufv][ms][0] = *(const uint32_t*)(smem + offAlo + o00);              \
            alB[bufv][ms][1] = *(const uint32_t*)(smem + offAlo + o10);              \
            alB[bufv][ms][2] = *(const uint32_t*)(smem + offAlo + o01);              \
            alB[bufv][ms][3] = *(const uint32_t*)(smem + offAlo + o11);              \
        }                                                                            \
        _Pragma("unroll")                                                            \
        for (int ns = 0; ns < 4; ns++) {                                             \
            int nrow = wn * 32 + ns * 8 + r;                                         \
            uint32_t ob0 = (uint32_t)(nrow * SAH + kb_ + kp) * 2;                    \
            uint32_t ob1 = (uint32_t)(nrow * SAH + kb_ + 8 + kp) * 2;                \
            bhB[bufv][ns][0] = *(const uint32_t*)(smem + offBhi + ob0);              \
            bhB[bufv][ns][1] = *(const uint32_t*)(smem + offBhi + ob1);              \
            blB[bufv][ns][0] = *(const uint32_t*)(smem + offBlo + ob0);              \
            blB[bufv][ns][1] = *(const uint32_t*)(smem + offBlo + ob1);              \
        }                                                                            \
    }

    const int npass = DUAL ? 2 : 1;
    for (int phase = 0; phase < npass; phase++) {
        const uint32_t* A = (phase == 0) ? A1 : A2;
        const uint32_t* W = (phase == 0) ? W1 : W2;
        if (phase) __syncthreads();           // all reads of prev tiles done

        // fill A planes: 128 rows x K packed -> hi/lo bf16 planes (PRMT once here)
        constexpr int C4 = K / 4;
        for (int idx = tid; idx < 128 * C4; idx += 256) {
            int row = idx / C4, c4 = idx % C4;
            uint4 v = make_uint4(0, 0, 0, 0);
            if (m0 + row < M) v = *(const uint4*)&A[(size_t)(m0 + row) * K + c4 * 4];
            uint2 hi, lo;
            hi.x = __byte_perm(v.x, v.y, SEL_HI); hi.y = __byte_perm(v.z, v.w, SEL_HI);
            lo.x = __byte_perm(v.x, v.y, SEL_LO); lo.y = __byte_perm(v.z, v.w, SEL_LO);
            uint32_t ho = (uint32_t)(row * SAH + c4 * 4) * 2;
            *(uint2*)(smem + offAhi + ho) = hi;
            *(uint2*)(smem + offAlo + ho) = lo;
        }
        // fill B planes: 64 rows x K packed
        for (int idx = tid; idx < 64 * C4; idx += 256) {
            int row = idx / C4, c4 = idx % C4;
            uint4 v = *(const uint4*)&W[(size_t)(n0 + row) * K + c4 * 4];
            uint2 hi, lo;
            hi.x = __byte_perm(v.x, v.y, SEL_HI); hi.y = __byte_perm(v.z, v.w, SEL_HI);
            lo.x = __byte_perm(v.x, v.y, SEL_LO); lo.y = __byte_perm(v.z, v.w, SEL_LO);
            uint32_t ho = (uint32_t)(row * SAH + c4 * 4) * 2;
            *(uint2*)(smem + offBhi + ho) = hi;
            *(uint2*)(smem + offBlo + ho) = lo;
        }
        __syncthreads();

        LOAD_FRAGS(0, 0);     // prologue
#pragma unroll
        for (int ks = 0; ks < KS; ks++) {
            int buf = ks & 1;
            if (ks + 1 < KS) LOAD_FRAGS(ks + 1, (ks + 1) & 1);   // prefetch next step
#pragma unroll
            for (int ns = 0; ns < 4; ns++) {
                mma16816(acc[0][ns], ahB[buf][0], bhB[buf][ns][0], bhB[buf][ns][1]); // hi*hi
                mma16816(acc[0][ns], ahB[buf][0], blB[buf][ns][0], blB[buf][ns][1]); // hi*lo
                mma16816(acc[0][ns], alB[buf][0], bhB[buf][ns][0], bhB[buf][ns][1]); // lo*hi
                mma16816(acc[1][ns], ahB[buf][1], bhB[buf][ns][0], bhB[buf][ns][1]);
                mma16816(acc[1][ns], ahB[buf][1], blB[buf][ns][0], blB[buf][ns][1]);
                mma16816(acc[1][ns], alB[buf][1], bhB[buf][ns][0], bhB[buf][ns][1]);
            }
        }
    }
#undef LOAD_FRAGS

    // ---- epilogue (R4-validated fragment->element map) ----
#pragma unroll
    for (int ms = 0; ms < 2; ms++) {
        int row0 = m0 + mrow0 + ms * 16;
        int row1 = row0 + 8;
#pragma unroll
        for (int ns = 0; ns < 4; ns++) {
            int col = n0 + wn * 32 + ns * 8 + kp;
            float bx = bias[col], by = bias[col + 1];
            float v0 = fmaxf(acc[ms][ns][0] + bx, 0.f);
            float v1 = fmaxf(acc[ms][ns][1] + by, 0.f);
            float v2 = fmaxf(acc[ms][ns][2] + bx, 0.f);
            float v3 = fmaxf(acc[ms][ns][3] + by, 0.f);
            if (FINAL) {
                float* o = (float*)outp;
                if (row0 < M) *(float2*)&o[(size_t)row0 * NOUTtot + col] = make_float2(v0, v1);
                if (row1 < M) *(float2*)&o[(size_t)row1 * NOUTtot + col] = make_float2(v2, v3);
            } else {
                uint32_t* o = (uint32_t*)outp;
                if (row0 < M) *(uint2*)&o[(size_t)row0 * NOUTtot + col] = make_uint2(pack_split(v0), pack_split(v1));
                if (row1 < M) *(uint2*)&o[(size_t)row1 * NOUTtot + col] = make_uint2(pack_split(v2), pack_split(v3));
            }
        }
    }
}

// ---------------- launch ----------------
extern "C" void kernel_launch(void* const* d_in, const int* in_sizes, int n_in,
                              void* d_out, int out_size) {
    const float* feat = (const float*)d_in[0];
    const int*   src  = (const int*)d_in[1];
    const int*   dst  = (const int*)d_in[2];
    const float* ew   = (const float*)d_in[3];
    const float* Wp1 = (const float*)d_in[4],  *bp1 = (const float*)d_in[5];
    const float* Ws1 = (const float*)d_in[6],  *Wn1 = (const float*)d_in[7],  *b1 = (const float*)d_in[8];
    const float* Wp2 = (const float*)d_in[9],  *bp2 = (const float*)d_in[10];
    const float* Ws2 = (const float*)d_in[11], *Wn2 = (const float*)d_in[12], *b2 = (const float*)d_in[13];
    const float* Wp3 = (const float*)d_in[14], *bp3 = (const float*)d_in[15];
    const float* Ws3 = (const float*)d_in[16], *Wn3 = (const float*)d_in[17], *b3 = (const float*)d_in[18];
    float* out = (float*)d_out;

    uint32_t *featpk, *hppk, *neighpk, *h1pk, *h2pk, *wpk;
    cudaGetSymbolAddress((void**)&featpk, g_feat_pk);
    cudaGetSymbolAddress((void**)&hppk,   g_hp_pk);
    cudaGetSymbolAddress((void**)&neighpk,g_neigh_pk);
    cudaGetSymbolAddress((void**)&h1pk,   g_h1_pk);
    cudaGetSymbolAddress((void**)&h2pk,   g_h2_pk);
    cudaGetSymbolAddress((void**)&wpk,    g_w_pk);

    const int M = NN;
    const int SM128 = (128 + 64) * (128 + 8) * 2 * 2;   // 104448 B
    const int SM64  = (128 + 64) * (64 + 8)  * 2 * 2;   // 55296 B
    cudaFuncSetAttribute(mma_gemm<128, false, false>, cudaFuncAttributeMaxDynamicSharedMemorySize, SM128);
    cudaFuncSetAttribute(mma_gemm<128, true,  false>, cudaFuncAttributeMaxDynamicSharedMemorySize, SM128);
    cudaFuncSetAttribute(mma_gemm<128, true,  true >, cudaFuncAttributeMaxDynamicSharedMemorySize, SM128);
    cudaFuncSetAttribute(mma_gemm<64,  false, false>, cudaFuncAttributeMaxDynamicSharedMemorySize, SM64);
    cudaFuncSetAttribute(mma_gemm<64,  true,  false>, cudaFuncAttributeMaxDynamicSharedMemorySize, SM64);

    const int MT = (M + 127) / 128;   // 391 M-tiles

    // ---- ordering note: launch #4 = L1 pool GEMM so the fixed ncu window
    // (empirically the 4th launch) captures a GEMM instead of hist/scan.
    pack_feat_kernel<<<(NN * 128 + 255) / 256, 256>>>(feat);                      // 1
    wprep_all_kernel<<<dim3((128 * 128 + 255) / 256, 9), 256>>>(                  // 2
        Wp1, Ws1, Wn1, Wp2, Ws2, Wn2, Wp3, Ws3, Wn3);
    zero_counts_kernel<<<(NN + 256) / 256, 256>>>();                              // 3
    mma_gemm<128, false, false><<<dim3(MT, 2), 256, SM128>>>(                     // 4 <- ncu
        featpk, wpk + WOFF_P1, nullptr, nullptr, bp1, hppk, M, 128);
    hist_kernel<<<(EE + 255) / 256, 256>>>(dst);                                  // 5
    scan_chunk_kernel<<<NSCAN_BLKS, SCAN_BLK>>>(NN + 1);                          // 6
    scan_partials_kernel<<<1, 64>>>(NSCAN_BLKS);                                  // 7
    scan_add_kernel<<<NSCAN_BLKS, SCAN_BLK>>>(NN + 1);                            // 8
    scatter_kernel<<<(EE + 255) / 256, 256>>>(src, dst, ew);                      // 9

    dim3 nblk((NN * 32 + 255) / 256);

    // ---- Layer 1: 128 -> 64 (pool GEMM already launched above) ----
    neigh_max_pk<128><<<nblk, 256>>>(hppk, neighpk);
    mma_gemm<128, true,  false><<<dim3(MT, 1), 256, SM128>>>(featpk, wpk + WOFF_S1, neighpk, wpk + WOFF_N1, b1, h1pk, M, 64);

    // ---- Layer 2: 64 -> 128 ----
    mma_gemm<64, false, false><<<dim3(MT, 1), 256, SM64>>>(h1pk, wpk + WOFF_P2, nullptr, nullptr, bp2, hppk, M, 64);
    neigh_max_pk<64><<<nblk, 256>>>(hppk, neighpk);
    mma_gemm<64, true,  false><<<dim3(MT, 2), 256, SM64>>>(h1pk, wpk + WOFF_S2, neighpk, wpk + WOFF_N2, b2, h2pk, M, 128);

    // ---- Layer 3: 128 -> 128 ----
    mma_gemm<128, false, false><<<dim3(MT, 2), 256, SM128>>>(h2pk, wpk + WOFF_P3, nullptr, nullptr, bp3, hppk, M, 128);
    neigh_max_pk<128><<<nblk, 256>>>(hppk, neighpk);
    mma_gemm<128, true,  true ><<<dim3(MT, 2), 256, SM128>>>(h2pk, wpk + WOFF_S3, neighpk, wpk + WOFF_N3, b3, out, M, 128);
}

// round 11
// speedup vs baseline: 1.1903x; 1.0027x over previous
#include <cuda_runtime.h>
#include <cuda_bf16.h>
#include <cstdint>

#define NN 50000
#define EE 800000
#define SCAN_BLK 1024
#define NSCAN_BLKS ((NN + 1 + SCAN_BLK - 1) / SCAN_BLK)

// ---------------- scratch (static device memory; no allocs) ----------------
__device__ uint32_t g_feat_pk[NN * 128];
__device__ uint32_t g_hp_pk[NN * 128];
__device__ uint32_t g_neigh_pk[NN * 128];
__device__ uint32_t g_h1_pk[NN * 64];
__device__ uint32_t g_h2_pk[NN * 128];
__device__ uint32_t g_w_pk[102400];     // transposed split-bf16 weights, [Nout][K]
__device__ int   g_rowptr[NN + 1];
__device__ int   g_cursor[NN];
__device__ int   g_src_sorted[EE];
__device__ float g_ew_sorted[EE];
__device__ int   g_partials[NSCAN_BLKS];

// weight scratch offsets (uint32 elements), layout [Nout][K]
#define WOFF_P1 0        // 128x128
#define WOFF_S1 16384    // 64x128
#define WOFF_N1 24576    // 64x128
#define WOFF_P2 32768    // 64x64
#define WOFF_S2 36864    // 128x64
#define WOFF_N2 45056    // 128x64
#define WOFF_P3 53248    // 128x128
#define WOFF_S3 69632    // 128x128
#define WOFF_N3 86016    // 128x128

// ---------------- split-bf16 helpers ----------------
// packed u32: high 16 bits = bf16(x) ("hi"), low 16 bits = bf16(x - hi) ("lo")
__device__ __forceinline__ uint32_t pack_split(float x) {
    __nv_bfloat16 h = __float2bfloat16(x);
    float hf = __bfloat162float(h);
    __nv_bfloat16 l = __float2bfloat16(x - hf);
    return ((uint32_t)__bfloat16_as_ushort(h) << 16) | (uint32_t)__bfloat16_as_ushort(l);
}
__device__ __forceinline__ float unpack_split(uint32_t w) {
    float hf = __bfloat162float(__ushort_as_bfloat16((unsigned short)(w >> 16)));
    float lf = __bfloat162float(__ushort_as_bfloat16((unsigned short)(w & 0xFFFFu)));
    return hf + lf;
}

// ---------------- mma.sync m16n8k16 bf16 (baseline PTX, sm_80+) ----------------
__device__ __forceinline__ void mma16816(float* c, const uint32_t* a, uint32_t b0, uint32_t b1) {
    asm volatile(
        "mma.sync.aligned.m16n8k16.row.col.f32.bf16.bf16.f32 "
        "{%0,%1,%2,%3}, {%4,%5,%6,%7}, {%8,%9}, {%0,%1,%2,%3};"
        : "+f"(c[0]), "+f"(c[1]), "+f"(c[2]), "+f"(c[3])
        : "r"(a[0]), "r"(a[1]), "r"(a[2]), "r"(a[3]), "r"(b0), "r"(b1));
}
#define SEL_HI 0x7632u   // {a.hi16, b.hi16}
#define SEL_LO 0x5410u   // {a.lo16, b.lo16}

// ---------------- pack feat ----------------
__global__ void pack_feat_kernel(const float* __restrict__ f) {
    int i = blockIdx.x * blockDim.x + threadIdx.x;
    if (i < NN * 128) g_feat_pk[i] = pack_split(f[i]);
}

// ---------------- combined weight prep: transpose + split-pack all 9 weights ----------------
__global__ void wprep_all_kernel(
    const float* __restrict__ W0, const float* __restrict__ W1t, const float* __restrict__ W2t,
    const float* __restrict__ W3, const float* __restrict__ W4, const float* __restrict__ W5,
    const float* __restrict__ W6, const float* __restrict__ W7, const float* __restrict__ W8)
{
    const float* Ws[9] = {W0, W1t, W2t, W3, W4, W5, W6, W7, W8};
    const int off[9] = {WOFF_P1, WOFF_S1, WOFF_N1, WOFF_P2, WOFF_S2, WOFF_N2, WOFF_P3, WOFF_S3, WOFF_N3};
    const int Kd [9] = {128, 128, 128, 64, 64, 64, 128, 128, 128};
    const int Nd [9] = {128, 64, 64, 64, 128, 128, 128, 128, 128};
    int s = blockIdx.y;
    int sz = Kd[s] * Nd[s];
    int i = blockIdx.x * blockDim.x + threadIdx.x;
    if (i < sz) {
        int k = i / Nd[s], n = i % Nd[s];
        g_w_pk[off[s] + n * Kd[s] + k] = pack_split(Ws[s][k * Nd[s] + n]);
    }
}

// ---------------- CSR build ----------------
__global__ void zero_counts_kernel() {
    int i = blockIdx.x * blockDim.x + threadIdx.x;
    if (i <= NN) g_rowptr[i] = 0;
}
__global__ void hist_kernel(const int* __restrict__ dst) {
    int i = blockIdx.x * blockDim.x + threadIdx.x;
    if (i < EE) atomicAdd(&g_rowptr[dst[i] + 1], 1);
}
__global__ void scan_chunk_kernel(int n) {
    __shared__ int sdata[SCAN_BLK];
    int tid = threadIdx.x;
    int i = blockIdx.x * SCAN_BLK + tid;
    int v = (i < n) ? g_rowptr[i] : 0;
    sdata[tid] = v;
    __syncthreads();
    for (int off = 1; off < SCAN_BLK; off <<= 1) {
        int t = (tid >= off) ? sdata[tid - off] : 0;
        __syncthreads();
        sdata[tid] += t;
        __syncthreads();
    }
    if (i < n) g_rowptr[i] = sdata[tid];
    if (tid == SCAN_BLK - 1) g_partials[blockIdx.x] = sdata[tid];
}
__global__ void scan_partials_kernel(int nb) {
    __shared__ int sh[64];
    int t = threadIdx.x;
    sh[t] = (t < nb) ? g_partials[t] : 0;
    __syncthreads();
    for (int off = 1; off < 64; off <<= 1) {
        int x = (t >= off) ? sh[t - off] : 0;
        __syncthreads();
        sh[t] += x;
        __syncthreads();
    }
    if (t < nb) g_partials[t] = sh[t];
}
__global__ void scan_add_kernel(int n) {
    int i = blockIdx.x * SCAN_BLK + threadIdx.x;
    if (i < n) {
        int off = (blockIdx.x > 0) ? g_partials[blockIdx.x - 1] : 0;
        int val = g_rowptr[i] + off;
        g_rowptr[i] = val;
        if (i < NN) g_cursor[i] = val;
    }
}
__global__ void scatter_kernel(const int* __restrict__ src,
                               const int* __restrict__ dst,
                               const float* __restrict__ ew) {
    int e = blockIdx.x * blockDim.x + threadIdx.x;
    if (e < EE) {
        int p = atomicAdd(&g_cursor[dst[e]], 1);
        g_src_sorted[p] = src[e];
        g_ew_sorted[p]  = ew[e];
    }
}

// ---------------- neighbor max (packed in/out, warp per node, no atomics) ----------------
template <int DIN>
__global__ void neigh_max_pk(const uint32_t* __restrict__ hp, uint32_t* __restrict__ out) {
    int warp = (blockIdx.x * blockDim.x + threadIdx.x) >> 5;
    int lane = threadIdx.x & 31;
    if (warp >= NN) return;
    int beg = g_rowptr[warp];
    int end = g_rowptr[warp + 1];
    if (DIN == 128) {
        float m0 = 0.f, m1 = 0.f, m2 = 0.f, m3 = 0.f;
        int e = beg;
        for (; e + 1 < end; e += 2) {       // 2-way unroll: MLP 2
            int s0 = g_src_sorted[e],     s1 = g_src_sorted[e + 1];
            float w0 = g_ew_sorted[e],    w1 = g_ew_sorted[e + 1];
            uint4 p0 = *(const uint4*)&hp[(size_t)s0 * 128 + lane * 4];
            uint4 p1 = *(const uint4*)&hp[(size_t)s1 * 128 + lane * 4];
            m0 = fmaxf(m0, unpack_split(p0.x) * w0);
            m1 = fmaxf(m1, unpack_split(p0.y) * w0);
            m2 = fmaxf(m2, unpack_split(p0.z) * w0);
            m3 = fmaxf(m3, unpack_split(p0.w) * w0);
            m0 = fmaxf(m0, unpack_split(p1.x) * w1);
            m1 = fmaxf(m1, unpack_split(p1.y) * w1);
            m2 = fmaxf(m2, unpack_split(p1.z) * w1);
            m3 = fmaxf(m3, unpack_split(p1.w) * w1);
        }
        if (e < end) {
            int s = g_src_sorted[e];
            float w = g_ew_sorted[e];
            uint4 p = *(const uint4*)&hp[(size_t)s * 128 + lane * 4];
            m0 = fmaxf(m0, unpack_split(p.x) * w);
            m1 = fmaxf(m1, unpack_split(p.y) * w);
            m2 = fmaxf(m2, unpack_split(p.z) * w);
            m3 = fmaxf(m3, unpack_split(p.w) * w);
        }
        uint4 o;
        o.x = pack_split(m0); o.y = pack_split(m1);
        o.z = pack_split(m2); o.w = pack_split(m3);
        *(uint4*)&out[(size_t)warp * 128 + lane * 4] = o;
    } else {
        float m0 = 0.f, m1 = 0.f;
        int e = beg;
        for (; e + 1 < end; e += 2) {
            int s0 = g_src_sorted[e],  s1 = g_src_sorted[e + 1];
            float w0 = g_ew_sorted[e], w1 = g_ew_sorted[e + 1];
            uint2 p0 = *(const uint2*)&hp[(size_t)s0 * 64 + lane * 2];
            uint2 p1 = *(const uint2*)&hp[(size_t)s1 * 64 + lane * 2];
            m0 = fmaxf(m0, unpack_split(p0.x) * w0);
            m1 = fmaxf(m1, unpack_split(p0.y) * w0);
            m0 = fmaxf(m0, unpack_split(p1.x) * w1);
            m1 = fmaxf(m1, unpack_split(p1.y) * w1);
        }
        if (e < end) {
            int s = g_src_sorted[e];
            float w = g_ew_sorted[e];
            uint2 p = *(const uint2*)&hp[(size_t)s * 64 + lane * 2];
            m0 = fmaxf(m0, unpack_split(p.x) * w);
            m1 = fmaxf(m1, unpack_split(p.y) * w);
        }
        uint2 o;
        o.x = pack_split(m0); o.y = pack_split(m1);
        *(uint2*)&out[(size_t)warp * 64 + lane * 2] = o;
    }
}

// ---------------- HMMA GEMM: split-plane smem, K staged in 64-chunks, 4 CTAs/SM ----
// CTA 256 threads (8 warps), tile 128 x 64. Warp grid 4(M) x 2(N) of 32x32 warp tiles
// (2 m-subs x 4 n-subs of m16n8k16). smem sized for a K-chunk of 64: bf16 hi/lo planes
// for A (128 x 64) and B (64 x 64), row stride 72 halfwords -> 55296 B/CTA -> 4 CTAs/SM.
// hi/lo split done ONCE at fill (PRMT amortized); inner loop is LDS.32 + HMMA only.
// Split-bf16 3-pass: hi*hi + hi*lo + lo*hi, fp32 acc.
template <int K, bool DUAL, bool FINAL>
__global__ __launch_bounds__(256, 4) void mma_gemm(
    const uint32_t* __restrict__ A1, const uint32_t* __restrict__ W1,
    const uint32_t* __restrict__ A2, const uint32_t* __restrict__ W2,
    const float* __restrict__ bias, void* __restrict__ outp,
    int M, int NOUTtot)
{
    constexpr int KCH = 64;                        // K-chunk staged in smem
    constexpr int SAH = KCH + 8;                   // halfword stride per row (72)
    constexpr uint32_t offAhi = 0;
    constexpr uint32_t offAlo = offAhi + 128 * SAH * 2;
    constexpr uint32_t offBhi = offAlo + 128 * SAH * 2;
    constexpr uint32_t offBlo = offBhi + 64 * SAH * 2;
    constexpr int KSC = KCH / 16;                  // 4 k-steps per chunk

    extern __shared__ char smem[];

    int tid = threadIdx.x;
    int warp = tid >> 5, lane = tid & 31;
    int wm = warp & 3;           // 0..3  -> m offset wm*32
    int wn = warp >> 2;          // 0..1  -> n offset wn*32
    int m0 = blockIdx.x * 128;
    int n0 = blockIdx.y * 64;

    int r  = lane >> 2;          // 0..7
    int kp = (lane & 3) * 2;     // 0,2,4,6
    int mrow0 = wm * 32 + r;     // m-sub 0 fragment row; m-sub 1 = +16

    float acc[2][4][4];
#pragma unroll
    for (int ms = 0; ms < 2; ms++)
#pragma unroll
        for (int ns = 0; ns < 4; ns++)
#pragma unroll
            for (int j = 0; j < 4; j++) acc[ms][ns][j] = 0.f;

    const int npass = DUAL ? 2 : 1;
    for (int phase = 0; phase < npass; phase++) {
        const uint32_t* A = (phase == 0) ? A1 : A2;
        const uint32_t* W = (phase == 0) ? W1 : W2;

        for (int kc = 0; kc < K; kc += KCH) {
            if (phase | kc) __syncthreads();       // prev-stage reads complete

            // fill A planes for this chunk: 128 rows x KCH packed -> hi/lo planes
            constexpr int C4 = KCH / 4;            // 16 uint4-chunks per row
            for (int idx = tid; idx < 128 * C4; idx += 256) {
                int row = idx / C4, c4 = idx % C4;
                uint4 v = make_uint4(0, 0, 0, 0);
                if (m0 + row < M) v = *(const uint4*)&A[(size_t)(m0 + row) * K + kc + c4 * 4];
                uint2 hi, lo;
                hi.x = __byte_perm(v.x, v.y, SEL_HI); hi.y = __byte_perm(v.z, v.w, SEL_HI);
                lo.x = __byte_perm(v.x, v.y, SEL_LO); lo.y = __byte_perm(v.z, v.w, SEL_LO);
                uint32_t ho = (uint32_t)(row * SAH + c4 * 4) * 2;
                *(uint2*)(smem + offAhi + ho) = hi;
                *(uint2*)(smem + offAlo + ho) = lo;
            }
            // fill B planes: 64 rows x KCH packed
            for (int idx = tid; idx < 64 * C4; idx += 256) {
                int row = idx / C4, c4 = idx % C4;
                uint4 v = *(const uint4*)&W[(size_t)(n0 + row) * K + kc + c4 * 4];
                uint2 hi, lo;
                hi.x = __byte_perm(v.x, v.y, SEL_HI); hi.y = __byte_perm(v.z, v.w, SEL_HI);
                lo.x = __byte_perm(v.x, v.y, SEL_LO); lo.y = __byte_perm(v.z, v.w, SEL_LO);
                uint32_t ho = (uint32_t)(row * SAH + c4 * 4) * 2;
                *(uint2*)(smem + offBhi + ho) = hi;
                *(uint2*)(smem + offBlo + ho) = lo;
            }
            __syncthreads();

#pragma unroll
            for (int ks = 0; ks < KSC; ks++) {
                int kb = ks * 16;
                // A fragments (direct LDS.32 from planes; R4-validated index map)
                uint32_t ah0[4], al0[4], ah1[4], al1[4];
#pragma unroll
                for (int ms = 0; ms < 2; ms++) {
                    int mr = mrow0 + ms * 16;
                    uint32_t o00 = (uint32_t)((mr    ) * SAH + kb + kp) * 2;
                    uint32_t o10 = (uint32_t)((mr + 8) * SAH + kb + kp) * 2;
                    uint32_t o01 = (uint32_t)((mr    ) * SAH + kb + 8 + kp) * 2;
                    uint32_t o11 = (uint32_t)((mr + 8) * SAH + kb + 8 + kp) * 2;
                    uint32_t* ah = ms ? ah1 : ah0;
                    uint32_t* al = ms ? al1 : al0;
                    ah[0] = *(const uint32_t*)(smem + offAhi + o00);
                    ah[1] = *(const uint32_t*)(smem + offAhi + o10);
                    ah[2] = *(const uint32_t*)(smem + offAhi + o01);
                    ah[3] = *(const uint32_t*)(smem + offAhi + o11);
                    al[0] = *(const uint32_t*)(smem + offAlo + o00);
                    al[1] = *(const uint32_t*)(smem + offAlo + o10);
                    al[2] = *(const uint32_t*)(smem + offAlo + o01);
                    al[3] = *(const uint32_t*)(smem + offAlo + o11);
                }
#pragma unroll
                for (int ns = 0; ns < 4; ns++) {
                    int nrow = wn * 32 + ns * 8 + r;
                    uint32_t ob0 = (uint32_t)(nrow * SAH + kb + kp) * 2;
                    uint32_t ob1 = (uint32_t)(nrow * SAH + kb + 8 + kp) * 2;
                    uint32_t bh0 = *(const uint32_t*)(smem + offBhi + ob0);
                    uint32_t bh1 = *(const uint32_t*)(smem + offBhi + ob1);
                    uint32_t bl0 = *(const uint32_t*)(smem + offBlo + ob0);
                    uint32_t bl1 = *(const uint32_t*)(smem + offBlo + ob1);
                    mma16816(acc[0][ns], ah0, bh0, bh1);   // hi*hi
                    mma16816(acc[0][ns], ah0, bl0, bl1);   // hi*lo
                    mma16816(acc[0][ns], al0, bh0, bh1);   // lo*hi
                    mma16816(acc[1][ns], ah1, bh0, bh1);
                    mma16816(acc[1][ns], ah1, bl0, bl1);
                    mma16816(acc[1][ns], al1, bh0, bh1);
                }
            }
        }
    }

    // ---- epilogue (R4-validated fragment->element map) ----
#pragma unroll
    for (int ms = 0; ms < 2; ms++) {
        int row0 = m0 + mrow0 + ms * 16;
        int row1 = row0 + 8;
#pragma unroll
        for (int ns = 0; ns < 4; ns++) {
            int col = n0 + wn * 32 + ns * 8 + kp;
            float bx = bias[col], by = bias[col + 1];
            float v0 = fmaxf(acc[ms][ns][0] + bx, 0.f);
            float v1 = fmaxf(acc[ms][ns][1] + by, 0.f);
            float v2 = fmaxf(acc[ms][ns][2] + bx, 0.f);
            float v3 = fmaxf(acc[ms][ns][3] + by, 0.f);
            if (FINAL) {
                float* o = (float*)outp;
                if (row0 < M) *(float2*)&o[(size_t)row0 * NOUTtot + col] = make_float2(v0, v1);
                if (row1 < M) *(float2*)&o[(size_t)row1 * NOUTtot + col] = make_float2(v2, v3);
            } else {
                uint32_t* o = (uint32_t*)outp;
                if (row0 < M) *(uint2*)&o[(size_t)row0 * NOUTtot + col] = make_uint2(pack_split(v0), pack_split(v1));
                if (row1 < M) *(uint2*)&o[(size_t)row1 * NOUTtot + col] = make_uint2(pack_split(v2), pack_split(v3));
            }
        }
    }
}

// ---------------- launch ----------------
extern "C" void kernel_launch(void* const* d_in, const int* in_sizes, int n_in,
                              void* d_out, int out_size) {
    const float* feat = (const float*)d_in[0];
    const int*   src  = (const int*)d_in[1];
    const int*   dst  = (const int*)d_in[2];
    const float* ew   = (const float*)d_in[3];
    const float* Wp1 = (const float*)d_in[4],  *bp1 = (const float*)d_in[5];
    const float* Ws1 = (const float*)d_in[6],  *Wn1 = (const float*)d_in[7],  *b1 = (const float*)d_in[8];
    const float* Wp2 = (const float*)d_in[9],  *bp2 = (const float*)d_in[10];
    const float* Ws2 = (const float*)d_in[11], *Wn2 = (const float*)d_in[12], *b2 = (const float*)d_in[13];
    const float* Wp3 = (const float*)d_in[14], *bp3 = (const float*)d_in[15];
    const float* Ws3 = (const float*)d_in[16], *Wn3 = (const float*)d_in[17], *b3 = (const float*)d_in[18];
    float* out = (float*)d_out;

    uint32_t *featpk, *hppk, *neighpk, *h1pk, *h2pk, *wpk;
    cudaGetSymbolAddress((void**)&featpk, g_feat_pk);
    cudaGetSymbolAddress((void**)&hppk,   g_hp_pk);
    cudaGetSymbolAddress((void**)&neighpk,g_neigh_pk);
    cudaGetSymbolAddress((void**)&h1pk,   g_h1_pk);
    cudaGetSymbolAddress((void**)&h2pk,   g_h2_pk);
    cudaGetSymbolAddress((void**)&wpk,    g_w_pk);

    const int M = NN;
    const int SMB = (128 + 64) * (64 + 8) * 2 * 2;   // 55296 B (all variants; K staged in 64s)
    cudaFuncSetAttribute(mma_gemm<128, false, false>, cudaFuncAttributeMaxDynamicSharedMemorySize, SMB);
    cudaFuncSetAttribute(mma_gemm<128, true,  false>, cudaFuncAttributeMaxDynamicSharedMemorySize, SMB);
    cudaFuncSetAttribute(mma_gemm<128, true,  true >, cudaFuncAttributeMaxDynamicSharedMemorySize, SMB);
    cudaFuncSetAttribute(mma_gemm<64,  false, false>, cudaFuncAttributeMaxDynamicSharedMemorySize, SMB);
    cudaFuncSetAttribute(mma_gemm<64,  true,  false>, cudaFuncAttributeMaxDynamicSharedMemorySize, SMB);

    const int MT = (M + 127) / 128;   // 391 M-tiles

    // ---- ordering note: launch #4 = L1 pool GEMM so the fixed ncu window
    // (empirically the 4th launch) captures a GEMM instead of hist/scan.
    pack_feat_kernel<<<(NN * 128 + 255) / 256, 256>>>(feat);                      // 1
    wprep_all_kernel<<<dim3((128 * 128 + 255) / 256, 9), 256>>>(                  // 2
        Wp1, Ws1, Wn1, Wp2, Ws2, Wn2, Wp3, Ws3, Wn3);
    zero_counts_kernel<<<(NN + 256) / 256, 256>>>();                              // 3
    mma_gemm<128, false, false><<<dim3(MT, 2), 256, SMB>>>(                       // 4 <- ncu
        featpk, wpk + WOFF_P1, nullptr, nullptr, bp1, hppk, M, 128);
    hist_kernel<<<(EE + 255) / 256, 256>>>(dst);                                  // 5
    scan_chunk_kernel<<<NSCAN_BLKS, SCAN_BLK>>>(NN + 1);                          // 6
    scan_partials_kernel<<<1, 64>>>(NSCAN_BLKS);                                  // 7
    scan_add_kernel<<<NSCAN_BLKS, SCAN_BLK>>>(NN + 1);                            // 8
    scatter_kernel<<<(EE + 255) / 256, 256>>>(src, dst, ew);                      // 9

    dim3 nblk((NN * 32 + 255) / 256);

    // ---- Layer 1: 128 -> 64 (pool GEMM already launched above) ----
    neigh_max_pk<128><<<nblk, 256>>>(hppk, neighpk);
    mma_gemm<128, true,  false><<<dim3(MT, 1), 256, SMB>>>(featpk, wpk + WOFF_S1, neighpk, wpk + WOFF_N1, b1, h1pk, M, 64);

    // ---- Layer 2: 64 -> 128 ----
    mma_gemm<64, false, false><<<dim3(MT, 1), 256, SMB>>>(h1pk, wpk + WOFF_P2, nullptr, nullptr, bp2, hppk, M, 64);
    neigh_max_pk<64><<<nblk, 256>>>(hppk, neighpk);
    mma_gemm<64, true,  false><<<dim3(MT, 2), 256, SMB>>>(h1pk, wpk + WOFF_S2, neighpk, wpk + WOFF_N2, b2, h2pk, M, 128);

    // ---- Layer 3: 128 -> 128 ----
    mma_gemm<128, false, false><<<dim3(MT, 2), 256, SMB>>>(h2pk, wpk + WOFF_P3, nullptr, nullptr, bp3, hppk, M, 128);
    neigh_max_pk<128><<<nblk, 256>>>(hppk, neighpk);
    mma_gemm<128, true,  true ><<<dim3(MT, 2), 256, SMB>>>(h2pk, wpk + WOFF_S3, neighpk, wpk + WOFF_N3, b3, out, M, 128);
}

// round 12
// speedup vs baseline: 1.2288x; 1.0323x over previous
#include <cuda_runtime.h>
#include <cuda_bf16.h>
#include <cstdint>

#define NN 50000
#define EE 800000
#define SCAN_BLK 1024
#define NSCAN_BLKS ((NN + 1 + SCAN_BLK - 1) / SCAN_BLK)

// ---------------- scratch (static device memory; no allocs) ----------------
__device__ uint32_t g_feat_pk[NN * 128];
__device__ uint32_t g_hp_pk[NN * 128];
__device__ uint32_t g_neigh_pk[NN * 128];
__device__ uint32_t g_h1_pk[NN * 64];
__device__ uint32_t g_h2_pk[NN * 128];
__device__ float    g_self[NN * 128];   // fp32 self-GEMM partial
__device__ uint32_t g_w_pk[102400];     // transposed split-bf16 weights, [Nout][K]
__device__ int   g_rowptr[NN + 1];
__device__ int   g_cursor[NN];
__device__ int   g_src_sorted[EE];
__device__ float g_ew_sorted[EE];
__device__ int   g_partials[NSCAN_BLKS];

// weight scratch offsets (uint32 elements), layout [Nout][K]
#define WOFF_P1 0        // 128x128
#define WOFF_S1 16384    // 64x128
#define WOFF_N1 24576    // 64x128
#define WOFF_P2 32768    // 64x64
#define WOFF_S2 36864    // 128x64
#define WOFF_N2 45056    // 128x64
#define WOFF_P3 53248    // 128x128
#define WOFF_S3 69632    // 128x128
#define WOFF_N3 86016    // 128x128

// ---------------- split-bf16 helpers ----------------
__device__ __forceinline__ uint32_t pack_split(float x) {
    __nv_bfloat16 h = __float2bfloat16(x);
    float hf = __bfloat162float(h);
    __nv_bfloat16 l = __float2bfloat16(x - hf);
    return ((uint32_t)__bfloat16_as_ushort(h) << 16) | (uint32_t)__bfloat16_as_ushort(l);
}
__device__ __forceinline__ float unpack_split(uint32_t w) {
    float hf = __bfloat162float(__ushort_as_bfloat16((unsigned short)(w >> 16)));
    float lf = __bfloat162float(__ushort_as_bfloat16((unsigned short)(w & 0xFFFFu)));
    return hf + lf;
}

// ---------------- mma.sync m16n8k16 bf16 (baseline PTX, sm_80+) ----------------
__device__ __forceinline__ void mma16816(float* c, const uint32_t* a, uint32_t b0, uint32_t b1) {
    asm volatile(
        "mma.sync.aligned.m16n8k16.row.col.f32.bf16.bf16.f32 "
        "{%0,%1,%2,%3}, {%4,%5,%6,%7}, {%8,%9}, {%0,%1,%2,%3};"
        : "+f"(c[0]), "+f"(c[1]), "+f"(c[2]), "+f"(c[3])
        : "r"(a[0]), "r"(a[1]), "r"(a[2]), "r"(a[3]), "r"(b0), "r"(b1));
}
#define SEL_HI 0x7632u   // {a.hi16, b.hi16}
#define SEL_LO 0x5410u   // {a.lo16, b.lo16}

// ---------------- pack feat ----------------
__global__ void pack_feat_kernel(const float* __restrict__ f) {
    int i = blockIdx.x * blockDim.x + threadIdx.x;
    if (i < NN * 128) g_feat_pk[i] = pack_split(f[i]);
}

// ---------------- combined weight prep: transpose + split-pack all 9 weights ----------------
__global__ void wprep_all_kernel(
    const float* __restrict__ W0, const float* __restrict__ W1t, const float* __restrict__ W2t,
    const float* __restrict__ W3, const float* __restrict__ W4, const float* __restrict__ W5,
    const float* __restrict__ W6, const float* __restrict__ W7, const float* __restrict__ W8)
{
    const float* Ws[9] = {W0, W1t, W2t, W3, W4, W5, W6, W7, W8};
    const int off[9] = {WOFF_P1, WOFF_S1, WOFF_N1, WOFF_P2, WOFF_S2, WOFF_N2, WOFF_P3, WOFF_S3, WOFF_N3};
    const int Kd [9] = {128, 128, 128, 64, 64, 64, 128, 128, 128};
    const int Nd [9] = {128, 64, 64, 64, 128, 128, 128, 128, 128};
    int s = blockIdx.y;
    int sz = Kd[s] * Nd[s];
    int i = blockIdx.x * blockDim.x + threadIdx.x;
    if (i < sz) {
        int k = i / Nd[s], n = i % Nd[s];
        g_w_pk[off[s] + n * Kd[s] + k] = pack_split(Ws[s][k * Nd[s] + n]);
    }
}

// ---------------- CSR build ----------------
__global__ void zero_counts_kernel() {
    int i = blockIdx.x * blockDim.x + threadIdx.x;
    if (i <= NN) g_rowptr[i] = 0;
}
__global__ void hist_kernel(const int* __restrict__ dst) {
    int i = blockIdx.x * blockDim.x + threadIdx.x;
    if (i < EE) atomicAdd(&g_rowptr[dst[i] + 1], 1);
}
__global__ void scan_chunk_kernel(int n) {
    __shared__ int sdata[SCAN_BLK];
    int tid = threadIdx.x;
    int i = blockIdx.x * SCAN_BLK + tid;
    int v = (i < n) ? g_rowptr[i] : 0;
    sdata[tid] = v;
    __syncthreads();
    for (int off = 1; off < SCAN_BLK; off <<= 1) {
        int t = (tid >= off) ? sdata[tid - off] : 0;
        __syncthreads();
        sdata[tid] += t;
        __syncthreads();
    }
    if (i < n) g_rowptr[i] = sdata[tid];
    if (tid == SCAN_BLK - 1) g_partials[blockIdx.x] = sdata[tid];
}
__global__ void scan_partials_kernel(int nb) {
    __shared__ int sh[64];
    int t = threadIdx.x;
    sh[t] = (t < nb) ? g_partials[t] : 0;
    __syncthreads();
    for (int off = 1; off < 64; off <<= 1) {
        int x = (t >= off) ? sh[t - off] : 0;
        __syncthreads();
        sh[t] += x;
        __syncthreads();
    }
    if (t < nb) g_partials[t] = sh[t];
}
__global__ void scan_add_kernel(int n) {
    int i = blockIdx.x * SCAN_BLK + threadIdx.x;
    if (i < n) {
        int off = (blockIdx.x > 0) ? g_partials[blockIdx.x - 1] : 0;
        int val = g_rowptr[i] + off;
        g_rowptr[i] = val;
        if (i < NN) g_cursor[i] = val;
    }
}
__global__ void scatter_kernel(const int* __restrict__ src,
                               const int* __restrict__ dst,
                               const float* __restrict__ ew) {
    int e = blockIdx.x * blockDim.x + threadIdx.x;
    if (e < EE) {
        int p = atomicAdd(&g_cursor[dst[e]], 1);
        g_src_sorted[p] = src[e];
        g_ew_sorted[p]  = ew[e];
    }
}

// ---------------- neighbor max (packed in/out, warp per node, no atomics) ----------------
template <int DIN>
__global__ void neigh_max_pk(const uint32_t* __restrict__ hp, uint32_t* __restrict__ out) {
    int warp = (blockIdx.x * blockDim.x + threadIdx.x) >> 5;
    int lane = threadIdx.x & 31;
    if (warp >= NN) return;
    int beg = g_rowptr[warp];
    int end = g_rowptr[warp + 1];
    if (DIN == 128) {
        float m0 = 0.f, m1 = 0.f, m2 = 0.f, m3 = 0.f;
        int e = beg;
        for (; e + 1 < end; e += 2) {       // 2-way unroll: MLP 2
            int s0 = g_src_sorted[e],     s1 = g_src_sorted[e + 1];
            float w0 = g_ew_sorted[e],    w1 = g_ew_sorted[e + 1];
            uint4 p0 = *(const uint4*)&hp[(size_t)s0 * 128 + lane * 4];
            uint4 p1 = *(const uint4*)&hp[(size_t)s1 * 128 + lane * 4];
            m0 = fmaxf(m0, unpack_split(p0.x) * w0);
            m1 = fmaxf(m1, unpack_split(p0.y) * w0);
            m2 = fmaxf(m2, unpack_split(p0.z) * w0);
            m3 = fmaxf(m3, unpack_split(p0.w) * w0);
            m0 = fmaxf(m0, unpack_split(p1.x) * w1);
            m1 = fmaxf(m1, unpack_split(p1.y) * w1);
            m2 = fmaxf(m2, unpack_split(p1.z) * w1);
            m3 = fmaxf(m3, unpack_split(p1.w) * w1);
        }
        if (e < end) {
            int s = g_src_sorted[e];
            float w = g_ew_sorted[e];
            uint4 p = *(const uint4*)&hp[(size_t)s * 128 + lane * 4];
            m0 = fmaxf(m0, unpack_split(p.x) * w);
            m1 = fmaxf(m1, unpack_split(p.y) * w);
            m2 = fmaxf(m2, unpack_split(p.z) * w);
            m3 = fmaxf(m3, unpack_split(p.w) * w);
        }
        uint4 o;
        o.x = pack_split(m0); o.y = pack_split(m1);
        o.z = pack_split(m2); o.w = pack_split(m3);
        *(uint4*)&out[(size_t)warp * 128 + lane * 4] = o;
    } else {
        float m0 = 0.f, m1 = 0.f;
        int e = beg;
        for (; e + 1 < end; e += 2) {
            int s0 = g_src_sorted[e],  s1 = g_src_sorted[e + 1];
            float w0 = g_ew_sorted[e], w1 = g_ew_sorted[e + 1];
            uint2 p0 = *(const uint2*)&hp[(size_t)s0 * 64 + lane * 2];
            uint2 p1 = *(const uint2*)&hp[(size_t)s1 * 64 + lane * 2];
            m0 = fmaxf(m0, unpack_split(p0.x) * w0);
            m1 = fmaxf(m1, unpack_split(p0.y) * w0);
            m0 = fmaxf(m0, unpack_split(p1.x) * w1);
            m1 = fmaxf(m1, unpack_split(p1.y) * w1);
        }
        if (e < end) {
            int s = g_src_sorted[e];
            float w = g_ew_sorted[e];
            uint2 p = *(const uint2*)&hp[(size_t)s * 64 + lane * 2];
            m0 = fmaxf(m0, unpack_split(p.x) * w);
            m1 = fmaxf(m1, unpack_split(p.y) * w);
        }
        uint2 o;
        o.x = pack_split(m0); o.y = pack_split(m1);
        *(uint2*)&out[(size_t)warp * 64 + lane * 2] = o;
    }
}

// ---------------- HMMA GEMM: split-plane smem, K staged in 64-chunks, 4 CTAs/SM ----
// MODE 0: out = pack(relu(A@W + bias))           (pool)
// MODE 1: out = fp32 A@W                          (self partial; no bias/relu)
// MODE 2: out = pack(relu(A@W + P + bias))        (accum over self partial)
// MODE 3: out = fp32 relu(A@W + P + bias)         (final layer accum)
template <int K, int MODE>
__global__ __launch_bounds__(256, 4) void mma_gemm(
    const uint32_t* __restrict__ A, const uint32_t* __restrict__ W,
    const float* __restrict__ bias, const float* __restrict__ Ppart,
    void* __restrict__ outp, int M, int NOUTtot)
{
    constexpr int KCH = 64;                        // K-chunk staged in smem
    constexpr int SAH = KCH + 8;                   // halfword stride per row (72)
    constexpr uint32_t offAhi = 0;
    constexpr uint32_t offAlo = offAhi + 128 * SAH * 2;
    constexpr uint32_t offBhi = offAlo + 128 * SAH * 2;
    constexpr uint32_t offBlo = offBhi + 64 * SAH * 2;
    constexpr int KSC = KCH / 16;                  // 4 k-steps per chunk

    extern __shared__ char smem[];

    int tid = threadIdx.x;
    int warp = tid >> 5, lane = tid & 31;
    int wm = warp & 3;           // 0..3  -> m offset wm*32
    int wn = warp >> 2;          // 0..1  -> n offset wn*32
    int m0 = blockIdx.x * 128;
    int n0 = blockIdx.y * 64;

    int r  = lane >> 2;          // 0..7
    int kp = (lane & 3) * 2;     // 0,2,4,6
    int mrow0 = wm * 32 + r;     // m-sub 0 fragment row; m-sub 1 = +16

    float acc[2][4][4];
#pragma unroll
    for (int ms = 0; ms < 2; ms++)
#pragma unroll
        for (int ns = 0; ns < 4; ns++)
#pragma unroll
            for (int j = 0; j < 4; j++) acc[ms][ns][j] = 0.f;

    for (int kc = 0; kc < K; kc += KCH) {
        if (kc) __syncthreads();       // prev-stage reads complete

        // fill A planes: 128 rows x KCH packed -> hi/lo bf16 planes (PRMT once here)
        constexpr int C4 = KCH / 4;    // 16 uint4-chunks per row
        for (int idx = tid; idx < 128 * C4; idx += 256) {
            int row = idx / C4, c4 = idx % C4;
            uint4 v = make_uint4(0, 0, 0, 0);
            if (m0 + row < M) v = *(const uint4*)&A[(size_t)(m0 + row) * K + kc + c4 * 4];
            uint2 hi, lo;
            hi.x = __byte_perm(v.x, v.y, SEL_HI); hi.y = __byte_perm(v.z, v.w, SEL_HI);
            lo.x = __byte_perm(v.x, v.y, SEL_LO); lo.y = __byte_perm(v.z, v.w, SEL_LO);
            uint32_t ho = (uint32_t)(row * SAH + c4 * 4) * 2;
            *(uint2*)(smem + offAhi + ho) = hi;
            *(uint2*)(smem + offAlo + ho) = lo;
        }
        // fill B planes: 64 rows x KCH packed
        for (int idx = tid; idx < 64 * C4; idx += 256) {
            int row = idx / C4, c4 = idx % C4;
            uint4 v = *(const uint4*)&W[(size_t)(n0 + row) * K + kc + c4 * 4];
            uint2 hi, lo;
            hi.x = __byte_perm(v.x, v.y, SEL_HI); hi.y = __byte_perm(v.z, v.w, SEL_HI);
            lo.x = __byte_perm(v.x, v.y, SEL_LO); lo.y = __byte_perm(v.z, v.w, SEL_LO);
            uint32_t ho = (uint32_t)(row * SAH + c4 * 4) * 2;
            *(uint2*)(smem + offBhi + ho) = hi;
            *(uint2*)(smem + offBlo + ho) = lo;
        }
        __syncthreads();

#pragma unroll
        for (int ks = 0; ks < KSC; ks++) {
            int kb = ks * 16;
            uint32_t ah0[4], al0[4], ah1[4], al1[4];
#pragma unroll
            for (int ms = 0; ms < 2; ms++) {
                int mr = mrow0 + ms * 16;
                uint32_t o00 = (uint32_t)((mr    ) * SAH + kb + kp) * 2;
                uint32_t o10 = (uint32_t)((mr + 8) * SAH + kb + kp) * 2;
                uint32_t o01 = (uint32_t)((mr    ) * SAH + kb + 8 + kp) * 2;
                uint32_t o11 = (uint32_t)((mr + 8) * SAH + kb + 8 + kp) * 2;
                uint32_t* ah = ms ? ah1 : ah0;
                uint32_t* al = ms ? al1 : al0;
                ah[0] = *(const uint32_t*)(smem + offAhi + o00);
                ah[1] = *(const uint32_t*)(smem + offAhi + o10);
                ah[2] = *(const uint32_t*)(smem + offAhi + o01);
                ah[3] = *(const uint32_t*)(smem + offAhi + o11);
                al[0] = *(const uint32_t*)(smem + offAlo + o00);
                al[1] = *(const uint32_t*)(smem + offAlo + o10);
                al[2] = *(const uint32_t*)(smem + offAlo + o01);
                al[3] = *(const uint32_t*)(smem + offAlo + o11);
            }
#pragma unroll
            for (int ns = 0; ns < 4; ns++) {
                int nrow = wn * 32 + ns * 8 + r;
                uint32_t ob0 = (uint32_t)(nrow * SAH + kb + kp) * 2;
                uint32_t ob1 = (uint32_t)(nrow * SAH + kb + 8 + kp) * 2;
                uint32_t bh0 = *(const uint32_t*)(smem + offBhi + ob0);
                uint32_t bh1 = *(const uint32_t*)(smem + offBhi + ob1);
                uint32_t bl0 = *(const uint32_t*)(smem + offBlo + ob0);
                uint32_t bl1 = *(const uint32_t*)(smem + offBlo + ob1);
                mma16816(acc[0][ns], ah0, bh0, bh1);   // hi*hi
                mma16816(acc[0][ns], ah0, bl0, bl1);   // hi*lo
                mma16816(acc[0][ns], al0, bh0, bh1);   // lo*hi
                mma16816(acc[1][ns], ah1, bh0, bh1);
                mma16816(acc[1][ns], ah1, bl0, bl1);
                mma16816(acc[1][ns], al1, bh0, bh1);
            }
        }
    }

    // ---- epilogue (R4-validated fragment->element map) ----
#pragma unroll
    for (int ms = 0; ms < 2; ms++) {
        int row0 = m0 + mrow0 + ms * 16;
        int row1 = row0 + 8;
#pragma unroll
        for (int ns = 0; ns < 4; ns++) {
            int col = n0 + wn * 32 + ns * 8 + kp;
            if (MODE == 1) {
                float* o = (float*)outp;
                if (row0 < M) *(float2*)&o[(size_t)row0 * NOUTtot + col] =
                    make_float2(acc[ms][ns][0], acc[ms][ns][1]);
                if (row1 < M) *(float2*)&o[(size_t)row1 * NOUTtot + col] =
                    make_float2(acc[ms][ns][2], acc[ms][ns][3]);
            } else {
                float bx = bias[col], by = bias[col + 1];
                float p0 = 0.f, p1 = 0.f, p2 = 0.f, p3 = 0.f;
                if (MODE >= 2) {
                    if (row0 < M) { float2 t = *(const float2*)&Ppart[(size_t)row0 * NOUTtot + col]; p0 = t.x; p1 = t.y; }
                    if (row1 < M) { float2 t = *(const float2*)&Ppart[(size_t)row1 * NOUTtot + col]; p2 = t.x; p3 = t.y; }
                }
                float v0 = fmaxf(acc[ms][ns][0] + p0 + bx, 0.f);
                float v1 = fmaxf(acc[ms][ns][1] + p1 + by, 0.f);
                float v2 = fmaxf(acc[ms][ns][2] + p2 + bx, 0.f);
                float v3 = fmaxf(acc[ms][ns][3] + p3 + by, 0.f);
                if (MODE == 3) {
                    float* o = (float*)outp;
                    if (row0 < M) *(float2*)&o[(size_t)row0 * NOUTtot + col] = make_float2(v0, v1);
                    if (row1 < M) *(float2*)&o[(size_t)row1 * NOUTtot + col] = make_float2(v2, v3);
                } else {
                    uint32_t* o = (uint32_t*)outp;
                    if (row0 < M) *(uint2*)&o[(size_t)row0 * NOUTtot + col] = make_uint2(pack_split(v0), pack_split(v1));
                    if (row1 < M) *(uint2*)&o[(size_t)row1 * NOUTtot + col] = make_uint2(pack_split(v2), pack_split(v3));
                }
            }
        }
    }
}

// ---------------- launch ----------------
extern "C" void kernel_launch(void* const* d_in, const int* in_sizes, int n_in,
                              void* d_out, int out_size) {
    const float* feat = (const float*)d_in[0];
    const int*   src  = (const int*)d_in[1];
    const int*   dst  = (const int*)d_in[2];
    const float* ew   = (const float*)d_in[3];
    const float* Wp1 = (const float*)d_in[4],  *bp1 = (const float*)d_in[5];
    const float* Ws1 = (const float*)d_in[6],  *Wn1 = (const float*)d_in[7],  *b1 = (const float*)d_in[8];
    const float* Wp2 = (const float*)d_in[9],  *bp2 = (const float*)d_in[10];
    const float* Ws2 = (const float*)d_in[11], *Wn2 = (const float*)d_in[12], *b2 = (const float*)d_in[13];
    const float* Wp3 = (const float*)d_in[14], *bp3 = (const float*)d_in[15];
    const float* Ws3 = (const float*)d_in[16], *Wn3 = (const float*)d_in[17], *b3 = (const float*)d_in[18];
    float* out = (float*)d_out;

    uint32_t *featpk, *hppk, *neighpk, *h1pk, *h2pk, *wpk;
    float* selfp;
    cudaGetSymbolAddress((void**)&featpk, g_feat_pk);
    cudaGetSymbolAddress((void**)&hppk,   g_hp_pk);
    cudaGetSymbolAddress((void**)&neighpk,g_neigh_pk);
    cudaGetSymbolAddress((void**)&h1pk,   g_h1_pk);
    cudaGetSymbolAddress((void**)&h2pk,   g_h2_pk);
    cudaGetSymbolAddress((void**)&selfp,  g_self);
    cudaGetSymbolAddress((void**)&wpk,    g_w_pk);

    // one-time stream/event setup (first call is the eager correctness run)
    static cudaStream_t s1 = nullptr;
    static cudaEvent_t evRoot, evPrep, evCSR, evS1, evH1, evS2, evH2, evS3;
    static bool sinit = false;
    if (!sinit) {
        cudaStreamCreateWithFlags(&s1, cudaStreamNonBlocking);
        cudaEventCreateWithFlags(&evRoot, cudaEventDisableTiming);
        cudaEventCreateWithFlags(&evPrep, cudaEventDisableTiming);
        cudaEventCreateWithFlags(&evCSR,  cudaEventDisableTiming);
        cudaEventCreateWithFlags(&evS1,   cudaEventDisableTiming);
        cudaEventCreateWithFlags(&evH1,   cudaEventDisableTiming);
        cudaEventCreateWithFlags(&evS2,   cudaEventDisableTiming);
        cudaEventCreateWithFlags(&evH2,   cudaEventDisableTiming);
        cudaEventCreateWithFlags(&evS3,   cudaEventDisableTiming);
        sinit = true;
    }

    const int M = NN;
    const int SMB = (128 + 64) * (64 + 8) * 2 * 2;   // 55296 B
    cudaFuncSetAttribute(mma_gemm<128, 0>, cudaFuncAttributeMaxDynamicSharedMemorySize, SMB);
    cudaFuncSetAttribute(mma_gemm<128, 1>, cudaFuncAttributeMaxDynamicSharedMemorySize, SMB);
    cudaFuncSetAttribute(mma_gemm<128, 2>, cudaFuncAttributeMaxDynamicSharedMemorySize, SMB);
    cudaFuncSetAttribute(mma_gemm<128, 3>, cudaFuncAttributeMaxDynamicSharedMemorySize, SMB);
    cudaFuncSetAttribute(mma_gemm<64,  0>, cudaFuncAttributeMaxDynamicSharedMemorySize, SMB);
    cudaFuncSetAttribute(mma_gemm<64,  1>, cudaFuncAttributeMaxDynamicSharedMemorySize, SMB);
    cudaFuncSetAttribute(mma_gemm<64,  2>, cudaFuncAttributeMaxDynamicSharedMemorySize, SMB);

    const int MT = (M + 127) / 128;   // 391 M-tiles
    dim3 nblk((NN * 32 + 255) / 256);

    // ======== fork: s1 builds CSR + runs self-GEMMs; default stream runs the chain ========
    cudaEventRecord(evRoot, 0);
    cudaStreamWaitEvent(s1, evRoot, 0);

    // --- s1: CSR build (independent of features/weights) ---
    zero_counts_kernel<<<(NN + 256) / 256, 256, 0, s1>>>();
    hist_kernel<<<(EE + 255) / 256, 256, 0, s1>>>(dst);
    scan_chunk_kernel<<<NSCAN_BLKS, SCAN_BLK, 0, s1>>>(NN + 1);
    scan_partials_kernel<<<1, 64, 0, s1>>>(NSCAN_BLKS);
    scan_add_kernel<<<NSCAN_BLKS, SCAN_BLK, 0, s1>>>(NN + 1);
    scatter_kernel<<<(EE + 255) / 256, 256, 0, s1>>>(src, dst, ew);
    cudaEventRecord(evCSR, s1);

    // --- s0: pack + weights + L1 pool ---
    pack_feat_kernel<<<(NN * 128 + 255) / 256, 256>>>(feat);
    wprep_all_kernel<<<dim3((128 * 128 + 255) / 256, 9), 256>>>(
        Wp1, Ws1, Wn1, Wp2, Ws2, Wn2, Wp3, Ws3, Wn3);
    cudaEventRecord(evPrep, 0);
    mma_gemm<128, 0><<<dim3(MT, 2), 256, SMB>>>(featpk, wpk + WOFF_P1, bp1, nullptr, hppk, M, 128);

    // --- s1: self1 = feat@Ws1 (after pack+wprep) ---
    cudaStreamWaitEvent(s1, evPrep, 0);
    mma_gemm<128, 1><<<dim3(MT, 1), 256, SMB, s1>>>(featpk, wpk + WOFF_S1, nullptr, nullptr, selfp, M, 64);
    cudaEventRecord(evS1, s1);

    // --- s0: neigh1 (needs CSR + pool1), then accum1 (needs self1) ---
    cudaStreamWaitEvent(0, evCSR, 0);
    neigh_max_pk<128><<<nblk, 256>>>(hppk, neighpk);
    cudaStreamWaitEvent(0, evS1, 0);
    mma_gemm<128, 2><<<dim3(MT, 1), 256, SMB>>>(neighpk, wpk + WOFF_N1, b1, selfp, h1pk, M, 64);
    cudaEventRecord(evH1, 0);

    // --- s1: self2 = h1@Ws2 (after accum1 freed selfp) ---
    cudaStreamWaitEvent(s1, evH1, 0);
    mma_gemm<64, 1><<<dim3(MT, 2), 256, SMB, s1>>>(h1pk, wpk + WOFF_S2, nullptr, nullptr, selfp, M, 128);
    cudaEventRecord(evS2, s1);

    // --- s0: layer 2 pool/neigh/accum ---
    mma_gemm<64, 0><<<dim3(MT, 1), 256, SMB>>>(h1pk, wpk + WOFF_P2, bp2, nullptr, hppk, M, 64);
    neigh_max_pk<64><<<nblk, 256>>>(hppk, neighpk);
    cudaStreamWaitEvent(0, evS2, 0);
    mma_gemm<64, 2><<<dim3(MT, 2), 256, SMB>>>(neighpk, wpk + WOFF_N2, b2, selfp, h2pk, M, 128);
    cudaEventRecord(evH2, 0);

    // --- s1: self3 = h2@Ws3 ---
    cudaStreamWaitEvent(s1, evH2, 0);
    mma_gemm<128, 1><<<dim3(MT, 2), 256, SMB, s1>>>(h2pk, wpk + WOFF_S3, nullptr, nullptr, selfp, M, 128);
    cudaEventRecord(evS3, s1);

    // --- s0: layer 3 pool/neigh/accum(final) ---
    mma_gemm<128, 0><<<dim3(MT, 2), 256, SMB>>>(h2pk, wpk + WOFF_P3, bp3, nullptr, hppk, M, 128);
    neigh_max_pk<128><<<nblk, 256>>>(hppk, neighpk);
    cudaStreamWaitEvent(0, evS3, 0);
    mma_gemm<128, 3><<<dim3(MT, 2), 256, SMB>>>(neighpk, wpk + WOFF_N3, b3, selfp, out, M, 128);
}

// round 13
// speedup vs baseline: 1.2377x; 1.0072x over previous
#include <cuda_runtime.h>
#include <cuda_bf16.h>
#include <cstdint>

#define NN 50000
#define EE 800000
#define SCAN_BLK 1024
#define NSCAN_BLKS ((NN + 1 + SCAN_BLK - 1) / SCAN_BLK)
#define MSPLIT 25088               // = 196 tiles * 128; half-A rows [0,MSPLIT), half-B rest
#define MT_A 196
#define MT_B 195

// ---------------- scratch (static device memory; no allocs) ----------------
__device__ uint32_t g_feat_pk[NN * 128];
__device__ uint32_t g_hp_pk[NN * 128];
__device__ uint32_t g_neigh_pk[NN * 128];
__device__ uint32_t g_h1_pk[NN * 64];
__device__ uint32_t g_h2_pk[NN * 128];
__device__ float    g_self[NN * 128];   // fp32 self-GEMM partial
__device__ uint32_t g_w_pk[102400];     // transposed split-bf16 weights, [Nout][K]
__device__ int   g_rowptr[NN + 1];
__device__ int   g_cursor[NN];
__device__ int   g_src_sorted[EE];
__device__ float g_ew_sorted[EE];
__device__ int   g_partials[NSCAN_BLKS];

// weight scratch offsets (uint32 elements), layout [Nout][K]
#define WOFF_P1 0
#define WOFF_S1 16384
#define WOFF_N1 24576
#define WOFF_P2 32768
#define WOFF_S2 36864
#define WOFF_N2 45056
#define WOFF_P3 53248
#define WOFF_S3 69632
#define WOFF_N3 86016

// ---------------- split-bf16 helpers ----------------
__device__ __forceinline__ uint32_t pack_split(float x) {
    __nv_bfloat16 h = __float2bfloat16(x);
    float hf = __bfloat162float(h);
    __nv_bfloat16 l = __float2bfloat16(x - hf);
    return ((uint32_t)__bfloat16_as_ushort(h) << 16) | (uint32_t)__bfloat16_as_ushort(l);
}
__device__ __forceinline__ float unpack_split(uint32_t w) {
    float hf = __bfloat162float(__ushort_as_bfloat16((unsigned short)(w >> 16)));
    float lf = __bfloat162float(__ushort_as_bfloat16((unsigned short)(w & 0xFFFFu)));
    return hf + lf;
}

// ---------------- mma.sync m16n8k16 bf16 (baseline PTX, sm_80+) ----------------
__device__ __forceinline__ void mma16816(float* c, const uint32_t* a, uint32_t b0, uint32_t b1) {
    asm volatile(
        "mma.sync.aligned.m16n8k16.row.col.f32.bf16.bf16.f32 "
        "{%0,%1,%2,%3}, {%4,%5,%6,%7}, {%8,%9}, {%0,%1,%2,%3};"
        : "+f"(c[0]), "+f"(c[1]), "+f"(c[2]), "+f"(c[3])
        : "r"(a[0]), "r"(a[1]), "r"(a[2]), "r"(a[3]), "r"(b0), "r"(b1));
}
#define SEL_HI 0x7632u
#define SEL_LO 0x5410u

// ---------------- pack feat ----------------
__global__ void pack_feat_kernel(const float* __restrict__ f) {
    int i = blockIdx.x * blockDim.x + threadIdx.x;
    if (i < NN * 128) g_feat_pk[i] = pack_split(f[i]);
}

// ---------------- combined weight prep ----------------
__global__ void wprep_all_kernel(
    const float* __restrict__ W0, const float* __restrict__ W1t, const float* __restrict__ W2t,
    const float* __restrict__ W3, const float* __restrict__ W4, const float* __restrict__ W5,
    const float* __restrict__ W6, const float* __restrict__ W7, const float* __restrict__ W8)
{
    const float* Ws[9] = {W0, W1t, W2t, W3, W4, W5, W6, W7, W8};
    const int off[9] = {WOFF_P1, WOFF_S1, WOFF_N1, WOFF_P2, WOFF_S2, WOFF_N2, WOFF_P3, WOFF_S3, WOFF_N3};
    const int Kd [9] = {128, 128, 128, 64, 64, 64, 128, 128, 128};
    const int Nd [9] = {128, 64, 64, 64, 128, 128, 128, 128, 128};
    int s = blockIdx.y;
    int sz = Kd[s] * Nd[s];
    int i = blockIdx.x * blockDim.x + threadIdx.x;
    if (i < sz) {
        int k = i / Nd[s], n = i % Nd[s];
        g_w_pk[off[s] + n * Kd[s] + k] = pack_split(Ws[s][k * Nd[s] + n]);
    }
}

// ---------------- CSR build ----------------
__global__ void zero_counts_kernel() {
    int i = blockIdx.x * blockDim.x + threadIdx.x;
    if (i <= NN) g_rowptr[i] = 0;
}
__global__ void hist_kernel(const int* __restrict__ dst) {
    int i = blockIdx.x * blockDim.x + threadIdx.x;
    if (i < EE) atomicAdd(&g_rowptr[dst[i] + 1], 1);
}
__global__ void scan_chunk_kernel(int n) {
    __shared__ int sdata[SCAN_BLK];
    int tid = threadIdx.x;
    int i = blockIdx.x * SCAN_BLK + tid;
    int v = (i < n) ? g_rowptr[i] : 0;
    sdata[tid] = v;
    __syncthreads();
    for (int off = 1; off < SCAN_BLK; off <<= 1) {
        int t = (tid >= off) ? sdata[tid - off] : 0;
        __syncthreads();
        sdata[tid] += t;
        __syncthreads();
    }
    if (i < n) g_rowptr[i] = sdata[tid];
    if (tid == SCAN_BLK - 1) g_partials[blockIdx.x] = sdata[tid];
}
__global__ void scan_partials_kernel(int nb) {
    __shared__ int sh[64];
    int t = threadIdx.x;
    sh[t] = (t < nb) ? g_partials[t] : 0;
    __syncthreads();
    for (int off = 1; off < 64; off <<= 1) {
        int x = (t >= off) ? sh[t - off] : 0;
        __syncthreads();
        sh[t] += x;
        __syncthreads();
    }
    if (t < nb) g_partials[t] = sh[t];
}
__global__ void scan_add_kernel(int n) {
    int i = blockIdx.x * SCAN_BLK + threadIdx.x;
    if (i < n) {
        int off = (blockIdx.x > 0) ? g_partials[blockIdx.x - 1] : 0;
        int val = g_rowptr[i] + off;
        g_rowptr[i] = val;
        if (i < NN) g_cursor[i] = val;
    }
}
__global__ void scatter_kernel(const int* __restrict__ src,
                               const int* __restrict__ dst,
                               const float* __restrict__ ew) {
    int e = blockIdx.x * blockDim.x + threadIdx.x;
    if (e < EE) {
        int p = atomicAdd(&g_cursor[dst[e]], 1);
        g_src_sorted[p] = src[e];
        g_ew_sorted[p]  = ew[e];
    }
}

// ---------------- neighbor max (node-range partition, 4-way unroll) ----------------
template <int DIN>
__global__ void neigh_max_pk(const uint32_t* __restrict__ hp, uint32_t* __restrict__ out,
                             int node_base, int node_end) {
    int warp = node_base + ((blockIdx.x * blockDim.x + threadIdx.x) >> 5);
    int lane = threadIdx.x & 31;
    if (warp >= node_end) return;
    int beg = g_rowptr[warp];
    int end = g_rowptr[warp + 1];
    if (DIN == 128) {
        float m0 = 0.f, m1 = 0.f, m2 = 0.f, m3 = 0.f;
        int e = beg;
        for (; e + 3 < end; e += 4) {       // 4-way unroll: MLP 4
            int s0 = g_src_sorted[e],     s1 = g_src_sorted[e + 1];
            int s2 = g_src_sorted[e + 2], s3 = g_src_sorted[e + 3];
            float w0 = g_ew_sorted[e],     w1 = g_ew_sorted[e + 1];
            float w2 = g_ew_sorted[e + 2], w3 = g_ew_sorted[e + 3];
            uint4 p0 = *(const uint4*)&hp[(size_t)s0 * 128 + lane * 4];
            uint4 p1 = *(const uint4*)&hp[(size_t)s1 * 128 + lane * 4];
            uint4 p2 = *(const uint4*)&hp[(size_t)s2 * 128 + lane * 4];
            uint4 p3 = *(const uint4*)&hp[(size_t)s3 * 128 + lane * 4];
            m0 = fmaxf(m0, unpack_split(p0.x) * w0); m1 = fmaxf(m1, unpack_split(p0.y) * w0);
            m2 = fmaxf(m2, unpack_split(p0.z) * w0); m3 = fmaxf(m3, unpack_split(p0.w) * w0);
            m0 = fmaxf(m0, unpack_split(p1.x) * w1); m1 = fmaxf(m1, unpack_split(p1.y) * w1);
            m2 = fmaxf(m2, unpack_split(p1.z) * w1); m3 = fmaxf(m3, unpack_split(p1.w) * w1);
            m0 = fmaxf(m0, unpack_split(p2.x) * w2); m1 = fmaxf(m1, unpack_split(p2.y) * w2);
            m2 = fmaxf(m2, unpack_split(p2.z) * w2); m3 = fmaxf(m3, unpack_split(p2.w) * w2);
            m0 = fmaxf(m0, unpack_split(p3.x) * w3); m1 = fmaxf(m1, unpack_split(p3.y) * w3);
            m2 = fmaxf(m2, unpack_split(p3.z) * w3); m3 = fmaxf(m3, unpack_split(p3.w) * w3);
        }
        for (; e < end; e++) {
            int s = g_src_sorted[e];
            float w = g_ew_sorted[e];
            uint4 p = *(const uint4*)&hp[(size_t)s * 128 + lane * 4];
            m0 = fmaxf(m0, unpack_split(p.x) * w); m1 = fmaxf(m1, unpack_split(p.y) * w);
            m2 = fmaxf(m2, unpack_split(p.z) * w); m3 = fmaxf(m3, unpack_split(p.w) * w);
        }
        uint4 o;
        o.x = pack_split(m0); o.y = pack_split(m1);
        o.z = pack_split(m2); o.w = pack_split(m3);
        *(uint4*)&out[(size_t)warp * 128 + lane * 4] = o;
    } else {
        float m0 = 0.f, m1 = 0.f;
        int e = beg;
        for (; e + 3 < end; e += 4) {
            int s0 = g_src_sorted[e],     s1 = g_src_sorted[e + 1];
            int s2 = g_src_sorted[e + 2], s3 = g_src_sorted[e + 3];
            float w0 = g_ew_sorted[e],     w1 = g_ew_sorted[e + 1];
            float w2 = g_ew_sorted[e + 2], w3 = g_ew_sorted[e + 3];
            uint2 p0 = *(const uint2*)&hp[(size_t)s0 * 64 + lane * 2];
            uint2 p1 = *(const uint2*)&hp[(size_t)s1 * 64 + lane * 2];
            uint2 p2 = *(const uint2*)&hp[(size_t)s2 * 64 + lane * 2];
            uint2 p3 = *(const uint2*)&hp[(size_t)s3 * 64 + lane * 2];
            m0 = fmaxf(m0, unpack_split(p0.x) * w0); m1 = fmaxf(m1, unpack_split(p0.y) * w0);
            m0 = fmaxf(m0, unpack_split(p1.x) * w1); m1 = fmaxf(m1, unpack_split(p1.y) * w1);
            m0 = fmaxf(m0, unpack_split(p2.x) * w2); m1 = fmaxf(m1, unpack_split(p2.y) * w2);
            m0 = fmaxf(m0, unpack_split(p3.x) * w3); m1 = fmaxf(m1, unpack_split(p3.y) * w3);
        }
        for (; e < end; e++) {
            int s = g_src_sorted[e];
            float w = g_ew_sorted[e];
            uint2 p = *(const uint2*)&hp[(size_t)s * 64 + lane * 2];
            m0 = fmaxf(m0, unpack_split(p.x) * w); m1 = fmaxf(m1, unpack_split(p.y) * w);
        }
        uint2 o;
        o.x = pack_split(m0); o.y = pack_split(m1);
        *(uint2*)&out[(size_t)warp * 64 + lane * 2] = o;
    }
}

// ---------------- HMMA GEMM: split-plane smem, K staged in 64-chunks, 4 CTAs/SM ----
// MODE 0: out = pack(relu(A@W + bias))     MODE 1: out = fp32 A@W
// MODE 2: out = pack(relu(A@W + P + bias)) MODE 3: out = fp32 relu(A@W + P + bias)
// Row-partitioned: caller offsets A/Ppart/outp by mbase rows, passes M=row count.
template <int K, int MODE>
__global__ __launch_bounds__(256, 4) void mma_gemm(
    const uint32_t* __restrict__ A, const uint32_t* __restrict__ W,
    const float* __restrict__ bias, const float* __restrict__ Ppart,
    void* __restrict__ outp, int M, int NOUTtot)
{
    constexpr int KCH = 64;
    constexpr int SAH = KCH + 8;
    constexpr uint32_t offAhi = 0;
    constexpr uint32_t offAlo = offAhi + 128 * SAH * 2;
    constexpr uint32_t offBhi = offAlo + 128 * SAH * 2;
    constexpr uint32_t offBlo = offBhi + 64 * SAH * 2;
    constexpr int KSC = KCH / 16;

    extern __shared__ char smem[];

    int tid = threadIdx.x;
    int warp = tid >> 5, lane = tid & 31;
    int wm = warp & 3;
    int wn = warp >> 2;
    int m0 = blockIdx.x * 128;
    int n0 = blockIdx.y * 64;

    int r  = lane >> 2;
    int kp = (lane & 3) * 2;
    int mrow0 = wm * 32 + r;

    float acc[2][4][4];
#pragma unroll
    for (int ms = 0; ms < 2; ms++)
#pragma unroll
        for (int ns = 0; ns < 4; ns++)
#pragma unroll
            for (int j = 0; j < 4; j++) acc[ms][ns][j] = 0.f;

    for (int kc = 0; kc < K; kc += KCH) {
        if (kc) __syncthreads();

        constexpr int C4 = KCH / 4;
        for (int idx = tid; idx < 128 * C4; idx += 256) {
            int row = idx / C4, c4 = idx % C4;
            uint4 v = make_uint4(0, 0, 0, 0);
            if (m0 + row < M) v = *(const uint4*)&A[(size_t)(m0 + row) * K + kc + c4 * 4];
            uint2 hi, lo;
            hi.x = __byte_perm(v.x, v.y, SEL_HI); hi.y = __byte_perm(v.z, v.w, SEL_HI);
            lo.x = __byte_perm(v.x, v.y, SEL_LO); lo.y = __byte_perm(v.z, v.w, SEL_LO);
            uint32_t ho = (uint32_t)(row * SAH + c4 * 4) * 2;
            *(uint2*)(smem + offAhi + ho) = hi;
            *(uint2*)(smem + offAlo + ho) = lo;
        }
        for (int idx = tid; idx < 64 * C4; idx += 256) {
            int row = idx / C4, c4 = idx % C4;
            uint4 v = *(const uint4*)&W[(size_t)(n0 + row) * K + kc + c4 * 4];
            uint2 hi, lo;
            hi.x = __byte_perm(v.x, v.y, SEL_HI); hi.y = __byte_perm(v.z, v.w, SEL_HI);
            lo.x = __byte_perm(v.x, v.y, SEL_LO); lo.y = __byte_perm(v.z, v.w, SEL_LO);
            uint32_t ho = (uint32_t)(row * SAH + c4 * 4) * 2;
            *(uint2*)(smem + offBhi + ho) = hi;
            *(uint2*)(smem + offBlo + ho) = lo;
        }
        __syncthreads();

#pragma unroll
        for (int ks = 0; ks < KSC; ks++) {
            int kb = ks * 16;
            uint32_t ah0[4], al0[4], ah1[4], al1[4];
#pragma unroll
            for (int ms = 0; ms < 2; ms++) {
                int mr = mrow0 + ms * 16;
                uint32_t o00 = (uint32_t)((mr    ) * SAH + kb + kp) * 2;
                uint32_t o10 = (uint32_t)((mr + 8) * SAH + kb + kp) * 2;
                uint32_t o01 = (uint32_t)((mr    ) * SAH + kb + 8 + kp) * 2;
                uint32_t o11 = (uint32_t)((mr + 8) * SAH + kb + 8 + kp) * 2;
                uint32_t* ah = ms ? ah1 : ah0;
                uint32_t* al = ms ? al1 : al0;
                ah[0] = *(const uint32_t*)(smem + offAhi + o00);
                ah[1] = *(const uint32_t*)(smem + offAhi + o10);
                ah[2] = *(const uint32_t*)(smem + offAhi + o01);
                ah[3] = *(const uint32_t*)(smem + offAhi + o11);
                al[0] = *(const uint32_t*)(smem + offAlo + o00);
                al[1] = *(const uint32_t*)(smem + offAlo + o10);
                al[2] = *(const uint32_t*)(smem + offAlo + o01);
                al[3] = *(const uint32_t*)(smem + offAlo + o11);
            }
#pragma unroll
            for (int ns = 0; ns < 4; ns++) {
                int nrow = wn * 32 + ns * 8 + r;
                uint32_t ob0 = (uint32_t)(nrow * SAH + kb + kp) * 2;
                uint32_t ob1 = (uint32_t)(nrow * SAH + kb + 8 + kp) * 2;
                uint32_t bh0 = *(const uint32_t*)(smem + offBhi + ob0);
                uint32_t bh1 = *(const uint32_t*)(smem + offBhi + ob1);
                uint32_t bl0 = *(const uint32_t*)(smem + offBlo + ob0);
                uint32_t bl1 = *(const uint32_t*)(smem + offBlo + ob1);
                mma16816(acc[0][ns], ah0, bh0, bh1);
                mma16816(acc[0][ns], ah0, bl0, bl1);
                mma16816(acc[0][ns], al0, bh0, bh1);
                mma16816(acc[1][ns], ah1, bh0, bh1);
                mma16816(acc[1][ns], ah1, bl0, bl1);
                mma16816(acc[1][ns], al1, bh0, bh1);
            }
        }
    }

    // ---- epilogue ----
#pragma unroll
    for (int ms = 0; ms < 2; ms++) {
        int row0 = m0 + mrow0 + ms * 16;
        int row1 = row0 + 8;
#pragma unroll
        for (int ns = 0; ns < 4; ns++) {
            int col = n0 + wn * 32 + ns * 8 + kp;
            if (MODE == 1) {
                float* o = (float*)outp;
                if (row0 < M) *(float2*)&o[(size_t)row0 * NOUTtot + col] =
                    make_float2(acc[ms][ns][0], acc[ms][ns][1]);
                if (row1 < M) *(float2*)&o[(size_t)row1 * NOUTtot + col] =
                    make_float2(acc[ms][ns][2], acc[ms][ns][3]);
            } else {
                float bx = bias[col], by = bias[col + 1];
                float p0 = 0.f, p1 = 0.f, p2 = 0.f, p3 = 0.f;
                if (MODE >= 2) {
                    if (row0 < M) { float2 t = *(const float2*)&Ppart[(size_t)row0 * NOUTtot + col]; p0 = t.x; p1 = t.y; }
                    if (row1 < M) { float2 t = *(const float2*)&Ppart[(size_t)row1 * NOUTtot + col]; p2 = t.x; p3 = t.y; }
                }
                float v0 = fmaxf(acc[ms][ns][0] + p0 + bx, 0.f);
                float v1 = fmaxf(acc[ms][ns][1] + p1 + by, 0.f);
                float v2 = fmaxf(acc[ms][ns][2] + p2 + bx, 0.f);
                float v3 = fmaxf(acc[ms][ns][3] + p3 + by, 0.f);
                if (MODE == 3) {
                    float* o = (float*)outp;
                    if (row0 < M) *(float2*)&o[(size_t)row0 * NOUTtot + col] = make_float2(v0, v1);
                    if (row1 < M) *(float2*)&o[(size_t)row1 * NOUTtot + col] = make_float2(v2, v3);
                } else {
                    uint32_t* o = (uint32_t*)outp;
                    if (row0 < M) *(uint2*)&o[(size_t)row0 * NOUTtot + col] = make_uint2(pack_split(v0), pack_split(v1));
                    if (row1 < M) *(uint2*)&o[(size_t)row1 * NOUTtot + col] = make_uint2(pack_split(v2), pack_split(v3));
                }
            }
        }
    }
}

// ---------------- launch ----------------
extern "C" void kernel_launch(void* const* d_in, const int* in_sizes, int n_in,
                              void* d_out, int out_size) {
    const float* feat = (const float*)d_in[0];
    const int*   src  = (const int*)d_in[1];
    const int*   dst  = (const int*)d_in[2];
    const float* ew   = (const float*)d_in[3];
    const float* Wp1 = (const float*)d_in[4],  *bp1 = (const float*)d_in[5];
    const float* Ws1 = (const float*)d_in[6],  *Wn1 = (const float*)d_in[7],  *b1 = (const float*)d_in[8];
    const float* Wp2 = (const float*)d_in[9],  *bp2 = (const float*)d_in[10];
    const float* Ws2 = (const float*)d_in[11], *Wn2 = (const float*)d_in[12], *b2 = (const float*)d_in[13];
    const float* Wp3 = (const float*)d_in[14], *bp3 = (const float*)d_in[15];
    const float* Ws3 = (const float*)d_in[16], *Wn3 = (const float*)d_in[17], *b3 = (const float*)d_in[18];
    float* out = (float*)d_out;

    uint32_t *featpk, *hppk, *neighpk, *h1pk, *h2pk, *wpk;
    float* selfp;
    cudaGetSymbolAddress((void**)&featpk, g_feat_pk);
    cudaGetSymbolAddress((void**)&hppk,   g_hp_pk);
    cudaGetSymbolAddress((void**)&neighpk,g_neigh_pk);
    cudaGetSymbolAddress((void**)&h1pk,   g_h1_pk);
    cudaGetSymbolAddress((void**)&h2pk,   g_h2_pk);
    cudaGetSymbolAddress((void**)&selfp,  g_self);
    cudaGetSymbolAddress((void**)&wpk,    g_w_pk);

    static cudaStream_t s1 = nullptr;
    static cudaEvent_t evRoot, evPrep, evCSR;
    static cudaEvent_t evS[3], evNA[3], evAA[3], evAB[3];
    static bool sinit = false;
    if (!sinit) {
        cudaStreamCreateWithFlags(&s1, cudaStreamNonBlocking);
        cudaEventCreateWithFlags(&evRoot, cudaEventDisableTiming);
        cudaEventCreateWithFlags(&evPrep, cudaEventDisableTiming);
        cudaEventCreateWithFlags(&evCSR,  cudaEventDisableTiming);
        for (int i = 0; i < 3; i++) {
            cudaEventCreateWithFlags(&evS[i],  cudaEventDisableTiming);
            cudaEventCreateWithFlags(&evNA[i], cudaEventDisableTiming);
            cudaEventCreateWithFlags(&evAA[i], cudaEventDisableTiming);
            cudaEventCreateWithFlags(&evAB[i], cudaEventDisableTiming);
        }
        sinit = true;
    }

    const int M = NN;
    const int CNT_A = MSPLIT;            // 25088 rows, 196 tiles
    const int CNT_B = NN - MSPLIT;       // 24912 rows, 195 tiles
    const int SMB = (128 + 64) * (64 + 8) * 2 * 2;   // 55296 B
    cudaFuncSetAttribute(mma_gemm<128, 0>, cudaFuncAttributeMaxDynamicSharedMemorySize, SMB);
    cudaFuncSetAttribute(mma_gemm<128, 1>, cudaFuncAttributeMaxDynamicSharedMemorySize, SMB);
    cudaFuncSetAttribute(mma_gemm<128, 2>, cudaFuncAttributeMaxDynamicSharedMemorySize, SMB);
    cudaFuncSetAttribute(mma_gemm<128, 3>, cudaFuncAttributeMaxDynamicSharedMemorySize, SMB);
    cudaFuncSetAttribute(mma_gemm<64,  0>, cudaFuncAttributeMaxDynamicSharedMemorySize, SMB);
    cudaFuncSetAttribute(mma_gemm<64,  1>, cudaFuncAttributeMaxDynamicSharedMemorySize, SMB);
    cudaFuncSetAttribute(mma_gemm<64,  2>, cudaFuncAttributeMaxDynamicSharedMemorySize, SMB);
    cudaFuncSetAttribute(mma_gemm<64,  3>, cudaFuncAttributeMaxDynamicSharedMemorySize, SMB);

    const int MT = (M + 127) / 128;      // 391 full-M tiles
    dim3 nblkA((CNT_A * 32 + 255) / 256);
    dim3 nblkB((CNT_B * 32 + 255) / 256);

    // ======== fork ========
    cudaEventRecord(evRoot, 0);
    cudaStreamWaitEvent(s1, evRoot, 0);

    // --- s1: CSR build ---
    zero_counts_kernel<<<(NN + 256) / 256, 256, 0, s1>>>();
    hist_kernel<<<(EE + 255) / 256, 256, 0, s1>>>(dst);
    scan_chunk_kernel<<<NSCAN_BLKS, SCAN_BLK, 0, s1>>>(NN + 1);
    scan_partials_kernel<<<1, 64, 0, s1>>>(NSCAN_BLKS);
    scan_add_kernel<<<NSCAN_BLKS, SCAN_BLK, 0, s1>>>(NN + 1);
    scatter_kernel<<<(EE + 255) / 256, 256, 0, s1>>>(src, dst, ew);
    cudaEventRecord(evCSR, s1);

    // --- s0: pack + weights + pool1 ---
    pack_feat_kernel<<<(NN * 128 + 255) / 256, 256>>>(feat);
    wprep_all_kernel<<<dim3((128 * 128 + 255) / 256, 9), 256>>>(
        Wp1, Ws1, Wn1, Wp2, Ws2, Wn2, Wp3, Ws3, Wn3);
    cudaEventRecord(evPrep, 0);
    mma_gemm<128, 0><<<dim3(MT, 2), 256, SMB>>>(featpk, wpk + WOFF_P1, bp1, nullptr, hppk, M, 128);

    // --- s1: self1 ---
    cudaStreamWaitEvent(s1, evPrep, 0);
    mma_gemm<128, 1><<<dim3(MT, 1), 256, SMB, s1>>>(featpk, wpk + WOFF_S1, nullptr, nullptr, selfp, M, 64);
    cudaEventRecord(evS[0], s1);

    // ===== Layer 1 (128 -> 64) =====
    cudaStreamWaitEvent(0, evCSR, 0);
    neigh_max_pk<128><<<nblkA, 256>>>(hppk, neighpk, 0, MSPLIT);
    cudaEventRecord(evNA[0], 0);
    neigh_max_pk<128><<<nblkB, 256>>>(hppk, neighpk, MSPLIT, NN);
    // s1: accumA1 (self1 in-order; neighA via event)
    cudaStreamWaitEvent(s1, evNA[0], 0);
    mma_gemm<128, 2><<<dim3(MT_A, 1), 256, SMB, s1>>>(neighpk, wpk + WOFF_N1, b1, selfp, h1pk, CNT_A, 64);
    cudaEventRecord(evAA[0], s1);
    // s0: accumB1
    cudaStreamWaitEvent(0, evS[0], 0);
    mma_gemm<128, 2><<<dim3(MT_B, 1), 256, SMB>>>(
        neighpk + (size_t)MSPLIT * 128, wpk + WOFF_N1, b1,
        selfp + (size_t)MSPLIT * 64, h1pk + (size_t)MSPLIT * 64, CNT_B, 64);
    cudaEventRecord(evAB[0], 0);
    cudaStreamWaitEvent(0, evAA[0], 0);

    // ===== Layer 2 (64 -> 128) =====
    mma_gemm<64, 0><<<dim3(MT, 1), 256, SMB>>>(h1pk, wpk + WOFF_P2, bp2, nullptr, hppk, M, 64);
    // s1: self2 (needs full h1)
    cudaStreamWaitEvent(s1, evAB[0], 0);
    mma_gemm<64, 1><<<dim3(MT, 2), 256, SMB, s1>>>(h1pk, wpk + WOFF_S2, nullptr, nullptr, selfp, M, 128);
    cudaEventRecord(evS[1], s1);
    neigh_max_pk<64><<<nblkA, 256>>>(hppk, neighpk, 0, MSPLIT);
    cudaEventRecord(evNA[1], 0);
    neigh_max_pk<64><<<nblkB, 256>>>(hppk, neighpk, MSPLIT, NN);
    cudaStreamWaitEvent(s1, evNA[1], 0);
    mma_gemm<64, 2><<<dim3(MT_A, 2), 256, SMB, s1>>>(neighpk, wpk + WOFF_N2, b2, selfp, h2pk, CNT_A, 128);
    cudaEventRecord(evAA[1], s1);
    cudaStreamWaitEvent(0, evS[1], 0);
    mma_gemm<64, 2><<<dim3(MT_B, 2), 256, SMB>>>(
        neighpk + (size_t)MSPLIT * 64, wpk + WOFF_N2, b2,
        selfp + (size_t)MSPLIT * 128, h2pk + (size_t)MSPLIT * 128, CNT_B, 128);
    cudaEventRecord(evAB[1], 0);
    cudaStreamWaitEvent(0, evAA[1], 0);

    // ===== Layer 3 (128 -> 128) =====
    mma_gemm<128, 0><<<dim3(MT, 2), 256, SMB>>>(h2pk, wpk + WOFF_P3, bp3, nullptr, hppk, M, 128);
    cudaStreamWaitEvent(s1, evAB[1], 0);
    mma_gemm<128, 1><<<dim3(MT, 2), 256, SMB, s1>>>(h2pk, wpk + WOFF_S3, nullptr, nullptr, selfp, M, 128);
    cudaEventRecord(evS[2], s1);
    neigh_max_pk<128><<<nblkA, 256>>>(hppk, neighpk, 0, MSPLIT);
    cudaEventRecord(evNA[2], 0);
    neigh_max_pk<128><<<nblkB, 256>>>(hppk, neighpk, MSPLIT, NN);
    cudaStreamWaitEvent(s1, evNA[2], 0);
    mma_gemm<128, 3><<<dim3(MT_A, 2), 256, SMB, s1>>>(neighpk, wpk + WOFF_N3, b3, selfp, out, CNT_A, 128);
    cudaEventRecord(evAA[2], s1);
    cudaStreamWaitEvent(0, evS[2], 0);
    mma_gemm<128, 3><<<dim3(MT_B, 2), 256, SMB>>>(
        neighpk + (size_t)MSPLIT * 128, wpk + WOFF_N3, b3,
        selfp + (size_t)MSPLIT * 128, out + (size_t)MSPLIT * 128, CNT_B, 128);
    cudaStreamWaitEvent(0, evAA[2], 0);
}

// round 14
// speedup vs baseline: 1.2424x; 1.0038x over previous
#include <cuda_runtime.h>
#include <cuda_bf16.h>
#include <cstdint>

#define NN 50000
#define EE 800000
#define SCAN_BLK 1024
#define NSCAN_BLKS ((NN + 1 + SCAN_BLK - 1) / SCAN_BLK)

// ---------------- scratch (static device memory; no allocs) ----------------
__device__ uint32_t g_feat_pk[NN * 128];
__device__ uint32_t g_hp_pk[NN * 128];
__device__ uint32_t g_neigh_pk[NN * 128];
__device__ uint32_t g_h1_pk[NN * 64];
__device__ uint32_t g_h2_pk[NN * 128];
__device__ float    g_self[NN * 128];   // fp32 self-GEMM partial
__device__ uint32_t g_w_pk[102400];     // transposed split-bf16 weights, [Nout][K]
__device__ int   g_rowptr[NN + 1];
__device__ int   g_cursor[NN];
__device__ int   g_src_sorted[EE];
__device__ float g_ew_sorted[EE];
__device__ int   g_partials[NSCAN_BLKS];

// weight scratch offsets (uint32 elements), layout [Nout][K]
#define WOFF_P1 0
#define WOFF_S1 16384
#define WOFF_N1 24576
#define WOFF_P2 32768
#define WOFF_S2 36864
#define WOFF_N2 45056
#define WOFF_P3 53248
#define WOFF_S3 69632
#define WOFF_N3 86016

// ---------------- split-bf16 helpers ----------------
__device__ __forceinline__ uint32_t pack_split(float x) {
    __nv_bfloat16 h = __float2bfloat16(x);
    float hf = __bfloat162float(h);
    __nv_bfloat16 l = __float2bfloat16(x - hf);
    return ((uint32_t)__bfloat16_as_ushort(h) << 16) | (uint32_t)__bfloat16_as_ushort(l);
}
__device__ __forceinline__ float unpack_split(uint32_t w) {
    float hf = __bfloat162float(__ushort_as_bfloat16((unsigned short)(w >> 16)));
    float lf = __bfloat162float(__ushort_as_bfloat16((unsigned short)(w & 0xFFFFu)));
    return hf + lf;
}

// ---------------- mma.sync m16n8k16 bf16 (baseline PTX, sm_80+) ----------------
__device__ __forceinline__ void mma16816(float* c, const uint32_t* a, uint32_t b0, uint32_t b1) {
    asm volatile(
        "mma.sync.aligned.m16n8k16.row.col.f32.bf16.bf16.f32 "
        "{%0,%1,%2,%3}, {%4,%5,%6,%7}, {%8,%9}, {%0,%1,%2,%3};"
        : "+f"(c[0]), "+f"(c[1]), "+f"(c[2]), "+f"(c[3])
        : "r"(a[0]), "r"(a[1]), "r"(a[2]), "r"(a[3]), "r"(b0), "r"(b1));
}
#define SEL_HI 0x7632u
#define SEL_LO 0x5410u

// ---------------- pack feat ----------------
__global__ void pack_feat_kernel(const float* __restrict__ f) {
    int i = blockIdx.x * blockDim.x + threadIdx.x;
    if (i < NN * 128) g_feat_pk[i] = pack_split(f[i]);
}

// ---------------- combined weight prep ----------------
__global__ void wprep_all_kernel(
    const float* __restrict__ W0, const float* __restrict__ W1t, const float* __restrict__ W2t,
    const float* __restrict__ W3, const float* __restrict__ W4, const float* __restrict__ W5,
    const float* __restrict__ W6, const float* __restrict__ W7, const float* __restrict__ W8)
{
    const float* Ws[9] = {W0, W1t, W2t, W3, W4, W5, W6, W7, W8};
    const int off[9] = {WOFF_P1, WOFF_S1, WOFF_N1, WOFF_P2, WOFF_S2, WOFF_N2, WOFF_P3, WOFF_S3, WOFF_N3};
    const int Kd [9] = {128, 128, 128, 64, 64, 64, 128, 128, 128};
    const int Nd [9] = {128, 64, 64, 64, 128, 128, 128, 128, 128};
    int s = blockIdx.y;
    int sz = Kd[s] * Nd[s];
    int i = blockIdx.x * blockDim.x + threadIdx.x;
    if (i < sz) {
        int k = i / Nd[s], n = i % Nd[s];
        g_w_pk[off[s] + n * Kd[s] + k] = pack_split(Ws[s][k * Nd[s] + n]);
    }
}

// ---------------- CSR build (5 kernels) ----------------
__global__ void zero_counts_kernel() {
    int i = blockIdx.x * blockDim.x + threadIdx.x;
    if (i <= NN) g_rowptr[i] = 0;
}
__global__ void hist_kernel(const int* __restrict__ dst) {
    int i = blockIdx.x * blockDim.x + threadIdx.x;
    if (i < EE) atomicAdd(&g_rowptr[dst[i] + 1], 1);
}
__global__ void scan_chunk_kernel(int n) {
    __shared__ int sdata[SCAN_BLK];
    int tid = threadIdx.x;
    int i = blockIdx.x * SCAN_BLK + tid;
    int v = (i < n) ? g_rowptr[i] : 0;
    sdata[tid] = v;
    __syncthreads();
    for (int off = 1; off < SCAN_BLK; off <<= 1) {
        int t = (tid >= off) ? sdata[tid - off] : 0;
        __syncthreads();
        sdata[tid] += t;
        __syncthreads();
    }
    if (i < n) g_rowptr[i] = sdata[tid];
    if (tid == SCAN_BLK - 1) g_partials[blockIdx.x] = sdata[tid];
}
// scan_add with inlined partial-prefix (removes scan_partials kernel)
__global__ void scan_add_kernel(int n) {
    __shared__ int s_off;
    if (threadIdx.x == 0) {
        int acc = 0;
        for (int b = 0; b < (int)blockIdx.x; b++) acc += g_partials[b];
        s_off = acc;
    }
    __syncthreads();
    int i = blockIdx.x * SCAN_BLK + threadIdx.x;
    if (i < n) {
        int val = g_rowptr[i] + s_off;
        g_rowptr[i] = val;
        if (i < NN) g_cursor[i] = val;
    }
}
__global__ void scatter_kernel(const int* __restrict__ src,
                               const int* __restrict__ dst,
                               const float* __restrict__ ew) {
    int e = blockIdx.x * blockDim.x + threadIdx.x;
    if (e < EE) {
        int p = atomicAdd(&g_cursor[dst[e]], 1);
        g_src_sorted[p] = src[e];
        g_ew_sorted[p]  = ew[e];
    }
}

// ---------------- neighbor max (4-way unroll, full node range) ----------------
template <int DIN>
__global__ void neigh_max_pk(const uint32_t* __restrict__ hp, uint32_t* __restrict__ out) {
    int warp = (blockIdx.x * blockDim.x + threadIdx.x) >> 5;
    int lane = threadIdx.x & 31;
    if (warp >= NN) return;
    int beg = g_rowptr[warp];
    int end = g_rowptr[warp + 1];
    if (DIN == 128) {
        float m0 = 0.f, m1 = 0.f, m2 = 0.f, m3 = 0.f;
        int e = beg;
        for (; e + 3 < end; e += 4) {
            int s0 = g_src_sorted[e],     s1 = g_src_sorted[e + 1];
            int s2 = g_src_sorted[e + 2], s3 = g_src_sorted[e + 3];
            float w0 = g_ew_sorted[e],     w1 = g_ew_sorted[e + 1];
            float w2 = g_ew_sorted[e + 2], w3 = g_ew_sorted[e + 3];
            uint4 p0 = *(const uint4*)&hp[(size_t)s0 * 128 + lane * 4];
            uint4 p1 = *(const uint4*)&hp[(size_t)s1 * 128 + lane * 4];
            uint4 p2 = *(const uint4*)&hp[(size_t)s2 * 128 + lane * 4];
            uint4 p3 = *(const uint4*)&hp[(size_t)s3 * 128 + lane * 4];
            m0 = fmaxf(m0, unpack_split(p0.x) * w0); m1 = fmaxf(m1, unpack_split(p0.y) * w0);
            m2 = fmaxf(m2, unpack_split(p0.z) * w0); m3 = fmaxf(m3, unpack_split(p0.w) * w0);
            m0 = fmaxf(m0, unpack_split(p1.x) * w1); m1 = fmaxf(m1, unpack_split(p1.y) * w1);
            m2 = fmaxf(m2, unpack_split(p1.z) * w1); m3 = fmaxf(m3, unpack_split(p1.w) * w1);
            m0 = fmaxf(m0, unpack_split(p2.x) * w2); m1 = fmaxf(m1, unpack_split(p2.y) * w2);
            m2 = fmaxf(m2, unpack_split(p2.z) * w2); m3 = fmaxf(m3, unpack_split(p2.w) * w2);
            m0 = fmaxf(m0, unpack_split(p3.x) * w3); m1 = fmaxf(m1, unpack_split(p3.y) * w3);
            m2 = fmaxf(m2, unpack_split(p3.z) * w3); m3 = fmaxf(m3, unpack_split(p3.w) * w3);
        }
        for (; e < end; e++) {
            int s = g_src_sorted[e];
            float w = g_ew_sorted[e];
            uint4 p = *(const uint4*)&hp[(size_t)s * 128 + lane * 4];
            m0 = fmaxf(m0, unpack_split(p.x) * w); m1 = fmaxf(m1, unpack_split(p.y) * w);
            m2 = fmaxf(m2, unpack_split(p.z) * w); m3 = fmaxf(m3, unpack_split(p.w) * w);
        }
        uint4 o;
        o.x = pack_split(m0); o.y = pack_split(m1);
        o.z = pack_split(m2); o.w = pack_split(m3);
        *(uint4*)&out[(size_t)warp * 128 + lane * 4] = o;
    } else {
        float m0 = 0.f, m1 = 0.f;
        int e = beg;
        for (; e + 3 < end; e += 4) {
            int s0 = g_src_sorted[e],     s1 = g_src_sorted[e + 1];
            int s2 = g_src_sorted[e + 2], s3 = g_src_sorted[e + 3];
            float w0 = g_ew_sorted[e],     w1 = g_ew_sorted[e + 1];
            float w2 = g_ew_sorted[e + 2], w3 = g_ew_sorted[e + 3];
            uint2 p0 = *(const uint2*)&hp[(size_t)s0 * 64 + lane * 2];
            uint2 p1 = *(const uint2*)&hp[(size_t)s1 * 64 + lane * 2];
            uint2 p2 = *(const uint2*)&hp[(size_t)s2 * 64 + lane * 2];
            uint2 p3 = *(const uint2*)&hp[(size_t)s3 * 64 + lane * 2];
            m0 = fmaxf(m0, unpack_split(p0.x) * w0); m1 = fmaxf(m1, unpack_split(p0.y) * w0);
            m0 = fmaxf(m0, unpack_split(p1.x) * w1); m1 = fmaxf(m1, unpack_split(p1.y) * w1);
            m0 = fmaxf(m0, unpack_split(p2.x) * w2); m1 = fmaxf(m1, unpack_split(p2.y) * w2);
            m0 = fmaxf(m0, unpack_split(p3.x) * w3); m1 = fmaxf(m1, unpack_split(p3.y) * w3);
        }
        for (; e < end; e++) {
            int s = g_src_sorted[e];
            float w = g_ew_sorted[e];
            uint2 p = *(const uint2*)&hp[(size_t)s * 64 + lane * 2];
            m0 = fmaxf(m0, unpack_split(p.x) * w); m1 = fmaxf(m1, unpack_split(p.y) * w);
        }
        uint2 o;
        o.x = pack_split(m0); o.y = pack_split(m1);
        *(uint2*)&out[(size_t)warp * 64 + lane * 2] = o;
    }
}

// ================= shared GEMM core (fill + mainloop) =================
// smem planes sized for K-chunk 64; returns fp32 acc in-place.
template <int K>
__device__ __forceinline__ void gemm_core(
    const uint32_t* __restrict__ A, const uint32_t* __restrict__ Wb,
    int M, int m0, float acc[2][4][4],
    int tid, int wm, int wn, int r, int kp, int mrow0, char* smem)
{
    constexpr int KCH = 64;
    constexpr int SAH = KCH + 8;
    constexpr uint32_t offAhi = 0;
    constexpr uint32_t offAlo = offAhi + 128 * SAH * 2;
    constexpr uint32_t offBhi = offAlo + 128 * SAH * 2;
    constexpr uint32_t offBlo = offBhi + 64 * SAH * 2;
    constexpr int KSC = KCH / 16;

    for (int kc = 0; kc < K; kc += KCH) {
        if (kc) __syncthreads();
        constexpr int C4 = KCH / 4;
        for (int idx = tid; idx < 128 * C4; idx += 256) {
            int row = idx / C4, c4 = idx % C4;
            uint4 v = make_uint4(0, 0, 0, 0);
            if (m0 + row < M) v = *(const uint4*)&A[(size_t)(m0 + row) * K + kc + c4 * 4];
            uint2 hi, lo;
            hi.x = __byte_perm(v.x, v.y, SEL_HI); hi.y = __byte_perm(v.z, v.w, SEL_HI);
            lo.x = __byte_perm(v.x, v.y, SEL_LO); lo.y = __byte_perm(v.z, v.w, SEL_LO);
            uint32_t ho = (uint32_t)(row * SAH + c4 * 4) * 2;
            *(uint2*)(smem + offAhi + ho) = hi;
            *(uint2*)(smem + offAlo + ho) = lo;
        }
        for (int idx = tid; idx < 64 * C4; idx += 256) {
            int row = idx / C4, c4 = idx % C4;
            uint4 v = *(const uint4*)&Wb[(size_t)row * K + kc + c4 * 4];
            uint2 hi, lo;
            hi.x = __byte_perm(v.x, v.y, SEL_HI); hi.y = __byte_perm(v.z, v.w, SEL_HI);
            lo.x = __byte_perm(v.x, v.y, SEL_LO); lo.y = __byte_perm(v.z, v.w, SEL_LO);
            uint32_t ho = (uint32_t)(row * SAH + c4 * 4) * 2;
            *(uint2*)(smem + offBhi + ho) = hi;
            *(uint2*)(smem + offBlo + ho) = lo;
        }
        __syncthreads();

#pragma unroll
        for (int ks = 0; ks < KSC; ks++) {
            int kb = ks * 16;
            uint32_t ah0[4], al0[4], ah1[4], al1[4];
#pragma unroll
            for (int ms = 0; ms < 2; ms++) {
                int mr = mrow0 + ms * 16;
                uint32_t o00 = (uint32_t)((mr    ) * SAH + kb + kp) * 2;
                uint32_t o10 = (uint32_t)((mr + 8) * SAH + kb + kp) * 2;
                uint32_t o01 = (uint32_t)((mr    ) * SAH + kb + 8 + kp) * 2;
                uint32_t o11 = (uint32_t)((mr + 8) * SAH + kb + 8 + kp) * 2;
                uint32_t* ah = ms ? ah1 : ah0;
                uint32_t* al = ms ? al1 : al0;
                ah[0] = *(const uint32_t*)(smem + offAhi + o00);
                ah[1] = *(const uint32_t*)(smem + offAhi + o10);
                ah[2] = *(const uint32_t*)(smem + offAhi + o01);
                ah[3] = *(const uint32_t*)(smem + offAhi + o11);
                al[0] = *(const uint32_t*)(smem + offAlo + o00);
                al[1] = *(const uint32_t*)(smem + offAlo + o10);
                al[2] = *(const uint32_t*)(smem + offAlo + o01);
                al[3] = *(const uint32_t*)(smem + offAlo + o11);
            }
#pragma unroll
            for (int ns = 0; ns < 4; ns++) {
                int nrow = wn * 32 + ns * 8 + r;
                uint32_t ob0 = (uint32_t)(nrow * SAH + kb + kp) * 2;
                uint32_t ob1 = (uint32_t)(nrow * SAH + kb + 8 + kp) * 2;
                uint32_t bh0 = *(const uint32_t*)(smem + offBhi + ob0);
                uint32_t bh1 = *(const uint32_t*)(smem + offBhi + ob1);
                uint32_t bl0 = *(const uint32_t*)(smem + offBlo + ob0);
                uint32_t bl1 = *(const uint32_t*)(smem + offBlo + ob1);
                mma16816(acc[0][ns], ah0, bh0, bh1);
                mma16816(acc[0][ns], ah0, bl0, bl1);
                mma16816(acc[0][ns], al0, bh0, bh1);
                mma16816(acc[1][ns], ah1, bh0, bh1);
                mma16816(acc[1][ns], ah1, bl0, bl1);
                mma16816(acc[1][ns], al1, bh0, bh1);
            }
        }
    }
}

// ---------------- fused pool+self GEMM ----------------
// n-blocks [0, NPOOL/64): pool -> packed relu(A@Wp + bp) into out_pool (width NPOOL)
// n-blocks [NPOOL/64, ...): self -> raw fp32 A@Ws into out_self (width NSELF)
template <int K>
__global__ __launch_bounds__(256, 4) void mma_fused(
    const uint32_t* __restrict__ A,
    const uint32_t* __restrict__ Wp, const float* __restrict__ bp,
    const uint32_t* __restrict__ Wsf,
    uint32_t* __restrict__ out_pool, float* __restrict__ out_self,
    int M, int NPOOL, int NSELF)
{
    extern __shared__ char smem[];
    int tid = threadIdx.x;
    int warp = tid >> 5, lane = tid & 31;
    int wm = warp & 3, wn = warp >> 2;
    int m0 = blockIdx.x * 128;
    int n0 = blockIdx.y * 64;
    int r  = lane >> 2;
    int kp = (lane & 3) * 2;
    int mrow0 = wm * 32 + r;

    bool is_pool = (n0 < NPOOL);
    const uint32_t* Wb = is_pool ? (Wp + (size_t)n0 * K) : (Wsf + (size_t)(n0 - NPOOL) * K);

    float acc[2][4][4];
#pragma unroll
    for (int ms = 0; ms < 2; ms++)
#pragma unroll
        for (int ns = 0; ns < 4; ns++)
#pragma unroll
            for (int j = 0; j < 4; j++) acc[ms][ns][j] = 0.f;

    gemm_core<K>(A, Wb, M, m0, acc, tid, wm, wn, r, kp, mrow0, smem);

#pragma unroll
    for (int ms = 0; ms < 2; ms++) {
        int row0 = m0 + mrow0 + ms * 16;
        int row1 = row0 + 8;
#pragma unroll
        for (int ns = 0; ns < 4; ns++) {
            int cl = wn * 32 + ns * 8 + kp;          // col within this 64-wide block
            if (is_pool) {
                int col = n0 + cl;
                float bx = bp[col], by = bp[col + 1];
                float v0 = fmaxf(acc[ms][ns][0] + bx, 0.f);
                float v1 = fmaxf(acc[ms][ns][1] + by, 0.f);
                float v2 = fmaxf(acc[ms][ns][2] + bx, 0.f);
                float v3 = fmaxf(acc[ms][ns][3] + by, 0.f);
                if (row0 < M) *(uint2*)&out_pool[(size_t)row0 * NPOOL + col] = make_uint2(pack_split(v0), pack_split(v1));
                if (row1 < M) *(uint2*)&out_pool[(size_t)row1 * NPOOL + col] = make_uint2(pack_split(v2), pack_split(v3));
            } else {
                int col = (n0 - NPOOL) + cl;
                if (row0 < M) *(float2*)&out_self[(size_t)row0 * NSELF + col] = make_float2(acc[ms][ns][0], acc[ms][ns][1]);
                if (row1 < M) *(float2*)&out_self[(size_t)row1 * NSELF + col] = make_float2(acc[ms][ns][2], acc[ms][ns][3]);
            }
        }
    }
}

// ---------------- accum GEMM: out = relu(neigh@Wn + self + bias) ----------------
// FINAL=false: packed u32 out; FINAL=true: fp32 out.
template <int K, bool FINAL>
__global__ __launch_bounds__(256, 4) void mma_accum(
    const uint32_t* __restrict__ A, const uint32_t* __restrict__ W,
    const float* __restrict__ bias, const float* __restrict__ Ppart,
    void* __restrict__ outp, int M, int NOUTtot)
{
    extern __shared__ char smem[];
    int tid = threadIdx.x;
    int warp = tid >> 5, lane = tid & 31;
    int wm = warp & 3, wn = warp >> 2;
    int m0 = blockIdx.x * 128;
    int n0 = blockIdx.y * 64;
    int r  = lane >> 2;
    int kp = (lane & 3) * 2;
    int mrow0 = wm * 32 + r;

    float acc[2][4][4];
#pragma unroll
    for (int ms = 0; ms < 2; ms++)
#pragma unroll
        for (int ns = 0; ns < 4; ns++)
#pragma unroll
            for (int j = 0; j < 4; j++) acc[ms][ns][j] = 0.f;

    gemm_core<K>(A, W + (size_t)n0 * K, M, m0, acc, tid, wm, wn, r, kp, mrow0, smem);

#pragma unroll
    for (int ms = 0; ms < 2; ms++) {
        int row0 = m0 + mrow0 + ms * 16;
        int row1 = row0 + 8;
#pragma unroll
        for (int ns = 0; ns < 4; ns++) {
            int col = n0 + wn * 32 + ns * 8 + kp;
            float bx = bias[col], by = bias[col + 1];
            float p0 = 0.f, p1 = 0.f, p2 = 0.f, p3 = 0.f;
            if (row0 < M) { float2 t = *(const float2*)&Ppart[(size_t)row0 * NOUTtot + col]; p0 = t.x; p1 = t.y; }
            if (row1 < M) { float2 t = *(const float2*)&Ppart[(size_t)row1 * NOUTtot + col]; p2 = t.x; p3 = t.y; }
            float v0 = fmaxf(acc[ms][ns][0] + p0 + bx, 0.f);
            float v1 = fmaxf(acc[ms][ns][1] + p1 + by, 0.f);
            float v2 = fmaxf(acc[ms][ns][2] + p2 + bx, 0.f);
            float v3 = fmaxf(acc[ms][ns][3] + p3 + by, 0.f);
            if (FINAL) {
                float* o = (float*)outp;
                if (row0 < M) *(float2*)&o[(size_t)row0 * NOUTtot + col] = make_float2(v0, v1);
                if (row1 < M) *(float2*)&o[(size_t)row1 * NOUTtot + col] = make_float2(v2, v3);
            } else {
                uint32_t* o = (uint32_t*)outp;
                if (row0 < M) *(uint2*)&o[(size_t)row0 * NOUTtot + col] = make_uint2(pack_split(v0), pack_split(v1));
                if (row1 < M) *(uint2*)&o[(size_t)row1 * NOUTtot + col] = make_uint2(pack_split(v2), pack_split(v3));
            }
        }
    }
}

// ---------------- launch ----------------
extern "C" void kernel_launch(void* const* d_in, const int* in_sizes, int n_in,
                              void* d_out, int out_size) {
    const float* feat = (const float*)d_in[0];
    const int*   src  = (const int*)d_in[1];
    const int*   dst  = (const int*)d_in[2];
    const float* ew   = (const float*)d_in[3];
    const float* Wp1 = (const float*)d_in[4],  *bp1 = (const float*)d_in[5];
    const float* Ws1 = (const float*)d_in[6],  *Wn1 = (const float*)d_in[7],  *b1 = (const float*)d_in[8];
    const float* Wp2 = (const float*)d_in[9],  *bp2 = (const float*)d_in[10];
    const float* Ws2 = (const float*)d_in[11], *Wn2 = (const float*)d_in[12], *b2 = (const float*)d_in[13];
    const float* Wp3 = (const float*)d_in[14], *bp3 = (const float*)d_in[15];
    const float* Ws3 = (const float*)d_in[16], *Wn3 = (const float*)d_in[17], *b3 = (const float*)d_in[18];
    float* out = (float*)d_out;

    uint32_t *featpk, *hppk, *neighpk, *h1pk, *h2pk, *wpk;
    float* selfp;
    cudaGetSymbolAddress((void**)&featpk, g_feat_pk);
    cudaGetSymbolAddress((void**)&hppk,   g_hp_pk);
    cudaGetSymbolAddress((void**)&neighpk,g_neigh_pk);
    cudaGetSymbolAddress((void**)&h1pk,   g_h1_pk);
    cudaGetSymbolAddress((void**)&h2pk,   g_h2_pk);
    cudaGetSymbolAddress((void**)&selfp,  g_self);
    cudaGetSymbolAddress((void**)&wpk,    g_w_pk);

    static cudaStream_t s1 = nullptr;
    static cudaEvent_t evRoot, evCSR;
    static bool sinit = false;
    if (!sinit) {
        cudaStreamCreateWithFlags(&s1, cudaStreamNonBlocking);
        cudaEventCreateWithFlags(&evRoot, cudaEventDisableTiming);
        cudaEventCreateWithFlags(&evCSR,  cudaEventDisableTiming);
        sinit = true;
    }

    const int M = NN;
    const int SMB = (128 + 64) * (64 + 8) * 2 * 2;   // 55296 B
    cudaFuncSetAttribute(mma_fused<128>,       cudaFuncAttributeMaxDynamicSharedMemorySize, SMB);
    cudaFuncSetAttribute(mma_fused<64>,        cudaFuncAttributeMaxDynamicSharedMemorySize, SMB);
    cudaFuncSetAttribute(mma_accum<128, false>,cudaFuncAttributeMaxDynamicSharedMemorySize, SMB);
    cudaFuncSetAttribute(mma_accum<128, true >,cudaFuncAttributeMaxDynamicSharedMemorySize, SMB);
    cudaFuncSetAttribute(mma_accum<64,  false>,cudaFuncAttributeMaxDynamicSharedMemorySize, SMB);

    const int MT = (M + 127) / 128;      // 391
    dim3 nblk((NN * 32 + 255) / 256);

    // ======== fork: s1 builds CSR; s0 runs the layer chain ========
    cudaEventRecord(evRoot, 0);
    cudaStreamWaitEvent(s1, evRoot, 0);

    zero_counts_kernel<<<(NN + 256) / 256, 256, 0, s1>>>();
    hist_kernel<<<(EE + 255) / 256, 256, 0, s1>>>(dst);
    scan_chunk_kernel<<<NSCAN_BLKS, SCAN_BLK, 0, s1>>>(NN + 1);
    scan_add_kernel<<<NSCAN_BLKS, SCAN_BLK, 0, s1>>>(NN + 1);
    scatter_kernel<<<(EE + 255) / 256, 256, 0, s1>>>(src, dst, ew);
    cudaEventRecord(evCSR, s1);

    // --- s0: prep + layers ---
    pack_feat_kernel<<<(NN * 128 + 255) / 256, 256>>>(feat);
    wprep_all_kernel<<<dim3((128 * 128 + 255) / 256, 9), 256>>>(
        Wp1, Ws1, Wn1, Wp2, Ws2, Wn2, Wp3, Ws3, Wn3);

    // Layer 1: fused pool(128)+self(64) over feat (K=128)
    mma_fused<128><<<dim3(MT, 3), 256, SMB>>>(
        featpk, wpk + WOFF_P1, bp1, wpk + WOFF_S1, hppk, selfp, M, 128, 64);
    cudaStreamWaitEvent(0, evCSR, 0);
    neigh_max_pk<128><<<nblk, 256>>>(hppk, neighpk);
    mma_accum<128, false><<<dim3(MT, 1), 256, SMB>>>(neighpk, wpk + WOFF_N1, b1, selfp, h1pk, M, 64);

    // Layer 2: fused pool(64)+self(128) over h1 (K=64)
    mma_fused<64><<<dim3(MT, 3), 256, SMB>>>(
        h1pk, wpk + WOFF_P2, bp2, wpk + WOFF_S2, hppk, selfp, M, 64, 128);
    neigh_max_pk<64><<<nblk, 256>>>(hppk, neighpk);
    mma_accum<64, false><<<dim3(MT, 2), 256, SMB>>>(neighpk, wpk + WOFF_N2, b2, selfp, h2pk, M, 128);

    // Layer 3: fused pool(128)+self(128) over h2 (K=128)
    mma_fused<128><<<dim3(MT, 4), 256, SMB>>>(
        h2pk, wpk + WOFF_P3, bp3, wpk + WOFF_S3, hppk, selfp, M, 128, 128);
    neigh_max_pk<128><<<nblk, 256>>>(hppk, neighpk);
    mma_accum<128, true><<<dim3(MT, 2), 256, SMB>>>(neighpk, wpk + WOFF_N3, b3, selfp, out, M, 128);
}

// round 16
// speedup vs baseline: 1.2930x; 1.0407x over previous
#include <cuda_runtime.h>
#include <cuda_bf16.h>
#include <cstdint>

#define NN 50000
#define EE 800000
#define SCAN_BLK 1024
#define NSCAN_BLKS ((NN + 1 + SCAN_BLK - 1) / SCAN_BLK)

// ---------------- scratch (static device memory; no allocs) ----------------
__device__ uint32_t g_hp_pk[NN * 128];
__device__ uint32_t g_neigh_pk[NN * 128];
__device__ uint32_t g_h1_pk[NN * 64];
__device__ uint32_t g_h2_pk[NN * 128];
__device__ float    g_self[NN * 128];   // fp32 self-GEMM partial
__device__ uint32_t g_w_pk[102400];     // transposed split-bf16 weights, [Nout][K]
__device__ int   g_rowptr[NN + 1];
__device__ int   g_cursor[NN];
__device__ int   g_src_sorted[EE];
__device__ float g_ew_sorted[EE];
__device__ int   g_partials[NSCAN_BLKS];

// weight scratch offsets (uint32 elements), layout [Nout][K]
#define WOFF_P1 0
#define WOFF_S1 16384
#define WOFF_N1 24576
#define WOFF_P2 32768
#define WOFF_S2 36864
#define WOFF_N2 45056
#define WOFF_P3 53248
#define WOFF_S3 69632
#define WOFF_N3 86016

// ---------------- split-bf16 helpers ----------------
__device__ __forceinline__ uint32_t pack_split(float x) {
    __nv_bfloat16 h = __float2bfloat16(x);
    float hf = __bfloat162float(h);
    __nv_bfloat16 l = __float2bfloat16(x - hf);
    return ((uint32_t)__bfloat16_as_ushort(h) << 16) | (uint32_t)__bfloat16_as_ushort(l);
}
__device__ __forceinline__ float unpack_split(uint32_t w) {
    float hf = __bfloat162float(__ushort_as_bfloat16((unsigned short)(w >> 16)));
    float lf = __bfloat162float(__ushort_as_bfloat16((unsigned short)(w & 0xFFFFu)));
    return hf + lf;
}

// ---------------- mma.sync m16n8k16 bf16 (baseline PTX, sm_80+) ----------------
__device__ __forceinline__ void mma16816(float* c, const uint32_t* a, uint32_t b0, uint32_t b1) {
    asm volatile(
        "mma.sync.aligned.m16n8k16.row.col.f32.bf16.bf16.f32 "
        "{%0,%1,%2,%3}, {%4,%5,%6,%7}, {%8,%9}, {%0,%1,%2,%3};"
        : "+f"(c[0]), "+f"(c[1]), "+f"(c[2]), "+f"(c[3])
        : "r"(a[0]), "r"(a[1]), "r"(a[2]), "r"(a[3]), "r"(b0), "r"(b1));
}
#define SEL_HI 0x7632u
#define SEL_LO 0x5410u

// ---------------- combined weight prep ----------------
__global__ void wprep_all_kernel(
    const float* __restrict__ W0, const float* __restrict__ W1t, const float* __restrict__ W2t,
    const float* __restrict__ W3, const float* __restrict__ W4, const float* __restrict__ W5,
    const float* __restrict__ W6, const float* __restrict__ W7, const float* __restrict__ W8)
{
    const float* Ws[9] = {W0, W1t, W2t, W3, W4, W5, W6, W7, W8};
    const int off[9] = {WOFF_P1, WOFF_S1, WOFF_N1, WOFF_P2, WOFF_S2, WOFF_N2, WOFF_P3, WOFF_S3, WOFF_N3};
    const int Kd [9] = {128, 128, 128, 64, 64, 64, 128, 128, 128};
    const int Nd [9] = {128, 64, 64, 64, 128, 128, 128, 128, 128};
    int s = blockIdx.y;
    int sz = Kd[s] * Nd[s];
    int i = blockIdx.x * blockDim.x + threadIdx.x;
    if (i < sz) {
        int k = i / Nd[s], n = i % Nd[s];
        g_w_pk[off[s] + n * Kd[s] + k] = pack_split(Ws[s][k * Nd[s] + n]);
    }
}

// ---------------- CSR build ----------------
__global__ void zero_counts_kernel() {
    int i = blockIdx.x * blockDim.x + threadIdx.x;
    if (i <= NN) g_rowptr[i] = 0;
}
__global__ void hist_kernel(const int* __restrict__ dst) {
    int i = blockIdx.x * blockDim.x + threadIdx.x;
    if (i < EE) atomicAdd(&g_rowptr[dst[i] + 1], 1);
}
__global__ void scan_chunk_kernel(int n) {
    __shared__ int sdata[SCAN_BLK];
    int tid = threadIdx.x;
    int i = blockIdx.x * SCAN_BLK + tid;
    int v = (i < n) ? g_rowptr[i] : 0;
    sdata[tid] = v;
    __syncthreads();
    for (int off = 1; off < SCAN_BLK; off <<= 1) {
        int t = (tid >= off) ? sdata[tid - off] : 0;
        __syncthreads();
        sdata[tid] += t;
        __syncthreads();
    }
    if (i < n) g_rowptr[i] = sdata[tid];
    if (tid == SCAN_BLK - 1) g_partials[blockIdx.x] = sdata[tid];
}
__global__ void scan_add_kernel(int n) {
    __shared__ int s_off;
    if (threadIdx.x == 0) {
        int acc = 0;
        for (int b = 0; b < (int)blockIdx.x; b++) acc += g_partials[b];
        s_off = acc;
    }
    __syncthreads();
    int i = blockIdx.x * SCAN_BLK + threadIdx.x;
    if (i < n) {
        int val = g_rowptr[i] + s_off;
        g_rowptr[i] = val;
        if (i < NN) g_cursor[i] = val;
    }
}
__global__ void scatter_kernel(const int* __restrict__ src,
                               const int* __restrict__ dst,
                               const float* __restrict__ ew) {
    int e = blockIdx.x * blockDim.x + threadIdx.x;
    if (e < EE) {
        int p = atomicAdd(&g_cursor[dst[e]], 1);
        g_src_sorted[p] = src[e];
        g_ew_sorted[p]  = ew[e];
    }
}

// ---------------- neighbor max (4-way unroll) ----------------
template <int DIN>
__global__ void neigh_max_pk(const uint32_t* __restrict__ hp, uint32_t* __restrict__ out) {
    int warp = (blockIdx.x * blockDim.x + threadIdx.x) >> 5;
    int lane = threadIdx.x & 31;
    if (warp >= NN) return;
    int beg = g_rowptr[warp];
    int end = g_rowptr[warp + 1];
    if (DIN == 128) {
        float m0 = 0.f, m1 = 0.f, m2 = 0.f, m3 = 0.f;
        int e = beg;
        for (; e + 3 < end; e += 4) {
            int s0 = g_src_sorted[e],     s1 = g_src_sorted[e + 1];
            int s2 = g_src_sorted[e + 2], s3 = g_src_sorted[e + 3];
            float w0 = g_ew_sorted[e],     w1 = g_ew_sorted[e + 1];
            float w2 = g_ew_sorted[e + 2], w3 = g_ew_sorted[e + 3];
            uint4 p0 = *(const uint4*)&hp[(size_t)s0 * 128 + lane * 4];
            uint4 p1 = *(const uint4*)&hp[(size_t)s1 * 128 + lane * 4];
            uint4 p2 = *(const uint4*)&hp[(size_t)s2 * 128 + lane * 4];
            uint4 p3 = *(const uint4*)&hp[(size_t)s3 * 128 + lane * 4];
            m0 = fmaxf(m0, unpack_split(p0.x) * w0); m1 = fmaxf(m1, unpack_split(p0.y) * w0);
            m2 = fmaxf(m2, unpack_split(p0.z) * w0); m3 = fmaxf(m3, unpack_split(p0.w) * w0);
            m0 = fmaxf(m0, unpack_split(p1.x) * w1); m1 = fmaxf(m1, unpack_split(p1.y) * w1);
            m2 = fmaxf(m2, unpack_split(p1.z) * w1); m3 = fmaxf(m3, unpack_split(p1.w) * w1);
            m0 = fmaxf(m0, unpack_split(p2.x) * w2); m1 = fmaxf(m1, unpack_split(p2.y) * w2);
            m2 = fmaxf(m2, unpack_split(p2.z) * w2); m3 = fmaxf(m3, unpack_split(p2.w) * w2);
            m0 = fmaxf(m0, unpack_split(p3.x) * w3); m1 = fmaxf(m1, unpack_split(p3.y) * w3);
            m2 = fmaxf(m2, unpack_split(p3.z) * w3); m3 = fmaxf(m3, unpack_split(p3.w) * w3);
        }
        for (; e < end; e++) {
            int s = g_src_sorted[e];
            float w = g_ew_sorted[e];
            uint4 p = *(const uint4*)&hp[(size_t)s * 128 + lane * 4];
            m0 = fmaxf(m0, unpack_split(p.x) * w); m1 = fmaxf(m1, unpack_split(p.y) * w);
            m2 = fmaxf(m2, unpack_split(p.z) * w); m3 = fmaxf(m3, unpack_split(p.w) * w);
        }
        uint4 o;
        o.x = pack_split(m0); o.y = pack_split(m1);
        o.z = pack_split(m2); o.w = pack_split(m3);
        *(uint4*)&out[(size_t)warp * 128 + lane * 4] = o;
    } else {
        float m0 = 0.f, m1 = 0.f;
        int e = beg;
        for (; e + 3 < end; e += 4) {
            int s0 = g_src_sorted[e],     s1 = g_src_sorted[e + 1];
            int s2 = g_src_sorted[e + 2], s3 = g_src_sorted[e + 3];
            float w0 = g_ew_sorted[e],     w1 = g_ew_sorted[e + 1];
            float w2 = g_ew_sorted[e + 2], w3 = g_ew_sorted[e + 3];
            uint2 p0 = *(const uint2*)&hp[(size_t)s0 * 64 + lane * 2];
            uint2 p1 = *(const uint2*)&hp[(size_t)s1 * 64 + lane * 2];
            uint2 p2 = *(const uint2*)&hp[(size_t)s2 * 64 + lane * 2];
            uint2 p3 = *(const uint2*)&hp[(size_t)s3 * 64 + lane * 2];
            m0 = fmaxf(m0, unpack_split(p0.x) * w0); m1 = fmaxf(m1, unpack_split(p0.y) * w0);
            m0 = fmaxf(m0, unpack_split(p1.x) * w1); m1 = fmaxf(m1, unpack_split(p1.y) * w1);
            m0 = fmaxf(m0, unpack_split(p2.x) * w2); m1 = fmaxf(m1, unpack_split(p2.y) * w2);
            m0 = fmaxf(m0, unpack_split(p3.x) * w3); m1 = fmaxf(m1, unpack_split(p3.y) * w3);
        }
        for (; e < end; e++) {
            int s = g_src_sorted[e];
            float w = g_ew_sorted[e];
            uint2 p = *(const uint2*)&hp[(size_t)s * 64 + lane * 2];
            m0 = fmaxf(m0, unpack_split(p.x) * w); m1 = fmaxf(m1, unpack_split(p.y) * w);
        }
        uint2 o;
        o.x = pack_split(m0); o.y = pack_split(m1);
        *(uint2*)&out[(size_t)warp * 64 + lane * 2] = o;
    }
}

// ================= shared GEMM core (fill + mainloop) =================
// F32A=false: A is packed split-bf16 u32. F32A=true: A is raw fp32 (split at fill).
template <int K, bool F32A>
__device__ __forceinline__ void gemm_core(
    const void* __restrict__ Araw, const uint32_t* __restrict__ Wb,
    int M, int m0, float acc[2][4][4],
    int tid, int wn, int r, int kp, int mrow0, char* smem)
{
    constexpr int KCH = 64;
    constexpr int SAH = KCH + 8;
    constexpr uint32_t offAhi = 0;
    constexpr uint32_t offAlo = offAhi + 128 * SAH * 2;
    constexpr uint32_t offBhi = offAlo + 128 * SAH * 2;
    constexpr uint32_t offBlo = offBhi + 64 * SAH * 2;
    constexpr int KSC = KCH / 16;

    for (int kc = 0; kc < K; kc += KCH) {
        if (kc) __syncthreads();
        constexpr int C4 = KCH / 4;
        for (int idx = tid; idx < 128 * C4; idx += 256) {
            int row = idx / C4, c4 = idx % C4;
            uint4 v = make_uint4(0, 0, 0, 0);
            if (m0 + row < M) {
                if (F32A) {
                    float4 f = *(const float4*)((const float*)Araw + (size_t)(m0 + row) * K + kc + c4 * 4);
                    v.x = pack_split(f.x); v.y = pack_split(f.y);
                    v.z = pack_split(f.z); v.w = pack_split(f.w);
                } else {
                    v = *(const uint4*)((const uint32_t*)Araw + (size_t)(m0 + row) * K + kc + c4 * 4);
                }
            }
            uint2 hi, lo;
            hi.x = __byte_perm(v.x, v.y, SEL_HI); hi.y = __byte_perm(v.z, v.w, SEL_HI);
            lo.x = __byte_perm(v.x, v.y, SEL_LO); lo.y = __byte_perm(v.z, v.w, SEL_LO);
            uint32_t ho = (uint32_t)(row * SAH + c4 * 4) * 2;
            *(uint2*)(smem + offAhi + ho) = hi;
            *(uint2*)(smem + offAlo + ho) = lo;
        }
        for (int idx = tid; idx < 64 * C4; idx += 256) {
            int row = idx / C4, c4 = idx % C4;
            uint4 v = *(const uint4*)&Wb[(size_t)row * K + kc + c4 * 4];
            uint2 hi, lo;
            hi.x = __byte_perm(v.x, v.y, SEL_HI); hi.y = __byte_perm(v.z, v.w, SEL_HI);
            lo.x = __byte_perm(v.x, v.y, SEL_LO); lo.y = __byte_perm(v.z, v.w, SEL_LO);
            uint32_t ho = (uint32_t)(row * SAH + c4 * 4) * 2;
            *(uint2*)(smem + offBhi + ho) = hi;
            *(uint2*)(smem + offBlo + ho) = lo;
        }
        __syncthreads();

#pragma unroll
        for (int ks = 0; ks < KSC; ks++) {
            int kb = ks * 16;
            uint32_t ah0[4], al0[4], ah1[4], al1[4];
#pragma unroll
            for (int ms = 0; ms < 2; ms++) {
                int mr = mrow0 + ms * 16;
                uint32_t o00 = (uint32_t)((mr    ) * SAH + kb + kp) * 2;
                uint32_t o10 = (uint32_t)((mr + 8) * SAH + kb + kp) * 2;
                uint32_t o01 = (uint32_t)((mr    ) * SAH + kb + 8 + kp) * 2;
                uint32_t o11 = (uint32_t)((mr + 8) * SAH + kb + 8 + kp) * 2;
                uint32_t* ah = ms ? ah1 : ah0;
                uint32_t* al = ms ? al1 : al0;
                ah[0] = *(const uint32_t*)(smem + offAhi + o00);
                ah[1] = *(const uint32_t*)(smem + offAhi + o10);
                ah[2] = *(const uint32_t*)(smem + offAhi + o01);
                ah[3] = *(const uint32_t*)(smem + offAhi + o11);
                al[0] = *(const uint32_t*)(smem + offAlo + o00);
                al[1] = *(const uint32_t*)(smem + offAlo + o10);
                al[2] = *(const uint32_t*)(smem + offAlo + o01);
                al[3] = *(const uint32_t*)(smem + offAlo + o11);
            }
#pragma unroll
            for (int ns = 0; ns < 4; ns++) {
                int nrow = wn * 32 + ns * 8 + r;
                uint32_t ob0 = (uint32_t)(nrow * SAH + kb + kp) * 2;
                uint32_t ob1 = (uint32_t)(nrow * SAH + kb + 8 + kp) * 2;
                uint32_t bh0 = *(const uint32_t*)(smem + offBhi + ob0);
                uint32_t bh1 = *(const uint32_t*)(smem + offBhi + ob1);
                uint32_t bl0 = *(const uint32_t*)(smem + offBlo + ob0);
                uint32_t bl1 = *(const uint32_t*)(smem + offBlo + ob1);
                mma16816(acc[0][ns], ah0, bh0, bh1);
                mma16816(acc[0][ns], ah0, bl0, bl1);
                mma16816(acc[0][ns], al0, bh0, bh1);
                mma16816(acc[1][ns], ah1, bh0, bh1);
                mma16816(acc[1][ns], ah1, bl0, bl1);
                mma16816(acc[1][ns], al1, bh0, bh1);
            }
        }
    }
}

// ---------------- fused pool+self GEMM ----------------
template <int K, bool F32A>
__global__ __launch_bounds__(256, 4) void mma_fused(
    const void* __restrict__ A,
    const uint32_t* __restrict__ Wp, const float* __restrict__ bp,
    const uint32_t* __restrict__ Wsf,
    uint32_t* __restrict__ out_pool, float* __restrict__ out_self,
    int M, int NPOOL, int NSELF)
{
    extern __shared__ char smem[];
    int tid = threadIdx.x;
    int warp = tid >> 5, lane = tid & 31;
    int wm = warp & 3, wn = warp >> 2;
    int m0 = blockIdx.x * 128;
    int n0 = blockIdx.y * 64;
    int r  = lane >> 2;
    int kp = (lane & 3) * 2;
    int mrow0 = wm * 32 + r;

    bool is_pool = (n0 < NPOOL);
    const uint32_t* Wb = is_pool ? (Wp + (size_t)n0 * K) : (Wsf + (size_t)(n0 - NPOOL) * K);

    float acc[2][4][4];
#pragma unroll
    for (int ms = 0; ms < 2; ms++)
#pragma unroll
        for (int ns = 0; ns < 4; ns++)
#pragma unroll
            for (int j = 0; j < 4; j++) acc[ms][ns][j] = 0.f;

    gemm_core<K, F32A>(A, Wb, M, m0, acc, tid, wn, r, kp, mrow0, smem);

#pragma unroll
    for (int ms = 0; ms < 2; ms++) {
        int row0 = m0 + mrow0 + ms * 16;
        int row1 = row0 + 8;
#pragma unroll
        for (int ns = 0; ns < 4; ns++) {
            int cl = wn * 32 + ns * 8 + kp;
            if (is_pool) {
                int col = n0 + cl;
                float bx = bp[col], by = bp[col + 1];
                float v0 = fmaxf(acc[ms][ns][0] + bx, 0.f);
                float v1 = fmaxf(acc[ms][ns][1] + by, 0.f);
                float v2 = fmaxf(acc[ms][ns][2] + bx, 0.f);
                float v3 = fmaxf(acc[ms][ns][3] + by, 0.f);
                if (row0 < M) *(uint2*)&out_pool[(size_t)row0 * NPOOL + col] = make_uint2(pack_split(v0), pack_split(v1));
                if (row1 < M) *(uint2*)&out_pool[(size_t)row1 * NPOOL + col] = make_uint2(pack_split(v2), pack_split(v3));
            } else {
                int col = (n0 - NPOOL) + cl;
                if (row0 < M) *(float2*)&out_self[(size_t)row0 * NSELF + col] = make_float2(acc[ms][ns][0], acc[ms][ns][1]);
                if (row1 < M) *(float2*)&out_self[(size_t)row1 * NSELF + col] = make_float2(acc[ms][ns][2], acc[ms][ns][3]);
            }
        }
    }
}

// ---------------- accum GEMM: out = relu(neigh@Wn + self + bias) ----------------
template <int K, bool FINAL>
__global__ __launch_bounds__(256, 4) void mma_accum(
    const uint32_t* __restrict__ A, const uint32_t* __restrict__ W,
    const float* __restrict__ bias, const float* __restrict__ Ppart,
    void* __restrict__ outp, int M, int NOUTtot)
{
    extern __shared__ char smem[];
    int tid = threadIdx.x;
    int warp = tid >> 5, lane = tid & 31;
    int wm = warp & 3, wn = warp >> 2;
    int m0 = blockIdx.x * 128;
    int n0 = blockIdx.y * 64;
    int r  = lane >> 2;
    int kp = (lane & 3) * 2;
    int mrow0 = wm * 32 + r;

    float acc[2][4][4];
#pragma unroll
    for (int ms = 0; ms < 2; ms++)
#pragma unroll
        for (int ns = 0; ns < 4; ns++)
#pragma unroll
            for (int j = 0; j < 4; j++) acc[ms][ns][j] = 0.f;

    gemm_core<K, false>(A, W + (size_t)n0 * K, M, m0, acc, tid, wn, r, kp, mrow0, smem);

#pragma unroll
    for (int ms = 0; ms < 2; ms++) {
        int row0 = m0 + mrow0 + ms * 16;
        int row1 = row0 + 8;
#pragma unroll
        for (int ns = 0; ns < 4; ns++) {
            int col = n0 + wn * 32 + ns * 8 + kp;
            float bx = bias[col], by = bias[col + 1];
            float p0 = 0.f, p1 = 0.f, p2 = 0.f, p3 = 0.f;
            if (row0 < M) { float2 t = *(const float2*)&Ppart[(size_t)row0 * NOUTtot + col]; p0 = t.x; p1 = t.y; }
            if (row1 < M) { float2 t = *(const float2*)&Ppart[(size_t)row1 * NOUTtot + col]; p2 = t.x; p3 = t.y; }
            float v0 = fmaxf(acc[ms][ns][0] + p0 + bx, 0.f);
            float v1 = fmaxf(acc[ms][ns][1] + p1 + by, 0.f);
            float v2 = fmaxf(acc[ms][ns][2] + p2 + bx, 0.f);
            float v3 = fmaxf(acc[ms][ns][3] + p3 + by, 0.f);
            if (FINAL) {
                float* o = (float*)outp;
                if (row0 < M) *(float2*)&o[(size_t)row0 * NOUTtot + col] = make_float2(v0, v1);
                if (row1 < M) *(float2*)&o[(size_t)row1 * NOUTtot + col] = make_float2(v2, v3);
            } else {
                uint32_t* o = (uint32_t*)outp;
                if (row0 < M) *(uint2*)&o[(size_t)row0 * NOUTtot + col] = make_uint2(pack_split(v0), pack_split(v1));
                if (row1 < M) *(uint2*)&o[(size_t)row1 * NOUTtot + col] = make_uint2(pack_split(v2), pack_split(v3));
            }
        }
    }
}

// ---------------- launch ----------------
extern "C" void kernel_launch(void* const* d_in, const int* in_sizes, int n_in,
                              void* d_out, int out_size) {
    const float* feat = (const float*)d_in[0];
    const int*   src  = (const int*)d_in[1];
    const int*   dst  = (const int*)d_in[2];
    const float* ew   = (const float*)d_in[3];
    const float* Wp1 = (const float*)d_in[4],  *bp1 = (const float*)d_in[5];
    const float* Ws1 = (const float*)d_in[6],  *Wn1 = (const float*)d_in[7],  *b1 = (const float*)d_in[8];
    const float* Wp2 = (const float*)d_in[9],  *bp2 = (const float*)d_in[10];
    const float* Ws2 = (const float*)d_in[11], *Wn2 = (const float*)d_in[12], *b2 = (const float*)d_in[13];
    const float* Wp3 = (const float*)d_in[14], *bp3 = (const float*)d_in[15];
    const float* Ws3 = (const float*)d_in[16], *Wn3 = (const float*)d_in[17], *b3 = (const float*)d_in[18];
    float* out = (float*)d_out;

    uint32_t *hppk, *neighpk, *h1pk, *h2pk, *wpk;
    float* selfp;
    cudaGetSymbolAddress((void**)&hppk,   g_hp_pk);
    cudaGetSymbolAddress((void**)&neighpk,g_neigh_pk);
    cudaGetSymbolAddress((void**)&h1pk,   g_h1_pk);
    cudaGetSymbolAddress((void**)&h2pk,   g_h2_pk);
    cudaGetSymbolAddress((void**)&selfp,  g_self);
    cudaGetSymbolAddress((void**)&wpk,    g_w_pk);

    static cudaStream_t s1 = nullptr;
    static cudaEvent_t evRoot, evW, evCSR;
    static bool sinit = false;
    if (!sinit) {
        cudaStreamCreateWithFlags(&s1, cudaStreamNonBlocking);
        cudaEventCreateWithFlags(&evRoot, cudaEventDisableTiming);
        cudaEventCreateWithFlags(&evW,    cudaEventDisableTiming);
        cudaEventCreateWithFlags(&evCSR,  cudaEventDisableTiming);
        sinit = true;
    }

    const int M = NN;
    const int SMB = (128 + 64) * (64 + 8) * 2 * 2;   // 55296 B
    cudaFuncSetAttribute(mma_fused<128, true >, cudaFuncAttributeMaxDynamicSharedMemorySize, SMB);
    cudaFuncSetAttribute(mma_fused<128, false>, cudaFuncAttributeMaxDynamicSharedMemorySize, SMB);
    cudaFuncSetAttribute(mma_fused<64,  false>, cudaFuncAttributeMaxDynamicSharedMemorySize, SMB);
    cudaFuncSetAttribute(mma_accum<128, false>, cudaFuncAttributeMaxDynamicSharedMemorySize, SMB);
    cudaFuncSetAttribute(mma_accum<128, true >, cudaFuncAttributeMaxDynamicSharedMemorySize, SMB);
    cudaFuncSetAttribute(mma_accum<64,  false>, cudaFuncAttributeMaxDynamicSharedMemorySize, SMB);

    const int MT = (M + 127) / 128;      // 391
    dim3 nblk((NN * 32 + 255) / 256);

    // ======== fork: s1 does wprep + CSR (contiguous run); s0 runs the layer chain ========
    cudaEventRecord(evRoot, 0);
    cudaStreamWaitEvent(s1, evRoot, 0);

    wprep_all_kernel<<<dim3((128 * 128 + 255) / 256, 9), 256, 0, s1>>>(
        Wp1, Ws1, Wn1, Wp2, Ws2, Wn2, Wp3, Ws3, Wn3);
    cudaEventRecord(evW, s1);
    zero_counts_kernel<<<(NN + 256) / 256, 256, 0, s1>>>();
    hist_kernel<<<(EE + 255) / 256, 256, 0, s1>>>(dst);
    scan_chunk_kernel<<<NSCAN_BLKS, SCAN_BLK, 0, s1>>>(NN + 1);
    scan_add_kernel<<<NSCAN_BLKS, SCAN_BLK, 0, s1>>>(NN + 1);
    scatter_kernel<<<(EE + 255) / 256, 256, 0, s1>>>(src, dst, ew);
    cudaEventRecord(evCSR, s1);

    // --- s0: layer chain ---
    cudaStreamWaitEvent(0, evW, 0);
    // Layer 1 fused pool(128)+self(64) straight from fp32 feat (K=128)
    mma_fused<128, true><<<dim3(MT, 3), 256, SMB>>>(
        feat, wpk + WOFF_P1, bp1, wpk + WOFF_S1, hppk, selfp, M, 128, 64);
    cudaStreamWaitEvent(0, evCSR, 0);
    neigh_max_pk<128><<<nblk, 256>>>(hppk, neighpk);
    mma_accum<128, false><<<dim3(MT, 1), 256, SMB>>>(neighpk, wpk + WOFF_N1, b1, selfp, h1pk, M, 64);

    // Layer 2 (K=64): fused pool(64)+self(128)
    mma_fused<64, false><<<dim3(MT, 3), 256, SMB>>>(
        h1pk, wpk + WOFF_P2, bp2, wpk + WOFF_S2, hppk, selfp, M, 64, 128);
    neigh_max_pk<64><<<nblk, 256>>>(hppk, neighpk);
    mma_accum<64, false><<<dim3(MT, 2), 256, SMB>>>(neighpk, wpk + WOFF_N2, b2, selfp, h2pk, M, 128);

    // Layer 3 (K=128): fused pool(128)+self(128)
    mma_fused<128, false><<<dim3(MT, 4), 256, SMB>>>(
        h2pk, wpk + WOFF_P3, bp3, wpk + WOFF_S3, hppk, selfp, M, 128, 128);
    neigh_max_pk<128><<<nblk, 256>>>(hppk, neighpk);
    mma_accum<128, true><<<dim3(MT, 2), 256, SMB>>>(neighpk, wpk + WOFF_N3, b3, selfp, out, M, 128);
}

// round 17
// speedup vs baseline: 1.3180x; 1.0194x over previous
#include <cuda_runtime.h>
#include <cuda_bf16.h>
#include <cstdint>

#define NN 50000
#define EE 800000
#define SCAN_BLK 1024
#define NSCAN_BLKS ((NN + 1 + SCAN_BLK - 1) / SCAN_BLK)

// ---------------- scratch (static device memory; no allocs) ----------------
__device__ uint32_t g_hp_pk[NN * 128];
__device__ uint32_t g_neigh_pk[NN * 128];
__device__ uint32_t g_h1_pk[NN * 64];
__device__ uint32_t g_h2_pk[NN * 128];
__device__ uint32_t g_w_pk[102400];     // transposed split-bf16 weights, [Nout][K]
__device__ int   g_rowptr[NN + 1];
__device__ int   g_cursor[NN];
__device__ int   g_src_sorted[EE];
__device__ float g_ew_sorted[EE];
__device__ int   g_partials[NSCAN_BLKS];

// weight scratch offsets (uint32 elements), layout [Nout][K]
#define WOFF_P1 0
#define WOFF_S1 16384
#define WOFF_N1 24576
#define WOFF_P2 32768
#define WOFF_S2 36864
#define WOFF_N2 45056
#define WOFF_P3 53248
#define WOFF_S3 69632
#define WOFF_N3 86016

// ---------------- split-bf16 helpers ----------------
__device__ __forceinline__ uint32_t pack_split(float x) {
    __nv_bfloat16 h = __float2bfloat16(x);
    float hf = __bfloat162float(h);
    __nv_bfloat16 l = __float2bfloat16(x - hf);
    return ((uint32_t)__bfloat16_as_ushort(h) << 16) | (uint32_t)__bfloat16_as_ushort(l);
}
__device__ __forceinline__ float unpack_split(uint32_t w) {
    float hf = __bfloat162float(__ushort_as_bfloat16((unsigned short)(w >> 16)));
    float lf = __bfloat162float(__ushort_as_bfloat16((unsigned short)(w & 0xFFFFu)));
    return hf + lf;
}

// ---------------- mma.sync m16n8k16 bf16 (baseline PTX, sm_80+) ----------------
__device__ __forceinline__ void mma16816(float* c, const uint32_t* a, uint32_t b0, uint32_t b1) {
    asm volatile(
        "mma.sync.aligned.m16n8k16.row.col.f32.bf16.bf16.f32 "
        "{%0,%1,%2,%3}, {%4,%5,%6,%7}, {%8,%9}, {%0,%1,%2,%3};"
        : "+f"(c[0]), "+f"(c[1]), "+f"(c[2]), "+f"(c[3])
        : "r"(a[0]), "r"(a[1]), "r"(a[2]), "r"(a[3]), "r"(b0), "r"(b1));
}
#define SEL_HI 0x7632u
#define SEL_LO 0x5410u

// ---------------- combined weight prep ----------------
__global__ void wprep_all_kernel(
    const float* __restrict__ W0, const float* __restrict__ W1t, const float* __restrict__ W2t,
    const float* __restrict__ W3, const float* __restrict__ W4, const float* __restrict__ W5,
    const float* __restrict__ W6, const float* __restrict__ W7, const float* __restrict__ W8)
{
    const float* Ws[9] = {W0, W1t, W2t, W3, W4, W5, W6, W7, W8};
    const int off[9] = {WOFF_P1, WOFF_S1, WOFF_N1, WOFF_P2, WOFF_S2, WOFF_N2, WOFF_P3, WOFF_S3, WOFF_N3};
    const int Kd [9] = {128, 128, 128, 64, 64, 64, 128, 128, 128};
    const int Nd [9] = {128, 64, 64, 64, 128, 128, 128, 128, 128};
    int s = blockIdx.y;
    int sz = Kd[s] * Nd[s];
    int i = blockIdx.x * blockDim.x + threadIdx.x;
    if (i < sz) {
        int k = i / Nd[s], n = i % Nd[s];
        g_w_pk[off[s] + n * Kd[s] + k] = pack_split(Ws[s][k * Nd[s] + n]);
    }
}

// ---------------- CSR build ----------------
__global__ void zero_counts_kernel() {
    int i = blockIdx.x * blockDim.x + threadIdx.x;
    if (i <= NN) g_rowptr[i] = 0;
}
__global__ void hist_kernel(const int* __restrict__ dst) {
    int i = blockIdx.x * blockDim.x + threadIdx.x;
    if (i < EE) atomicAdd(&g_rowptr[dst[i] + 1], 1);
}
__global__ void scan_chunk_kernel(int n) {
    __shared__ int sdata[SCAN_BLK];
    int tid = threadIdx.x;
    int i = blockIdx.x * SCAN_BLK + tid;
    int v = (i < n) ? g_rowptr[i] : 0;
    sdata[tid] = v;
    __syncthreads();
    for (int off = 1; off < SCAN_BLK; off <<= 1) {
        int t = (tid >= off) ? sdata[tid - off] : 0;
        __syncthreads();
        sdata[tid] += t;
        __syncthreads();
    }
    if (i < n) g_rowptr[i] = sdata[tid];
    if (tid == SCAN_BLK - 1) g_partials[blockIdx.x] = sdata[tid];
}
__global__ void scan_add_kernel(int n) {
    __shared__ int s_off;
    if (threadIdx.x == 0) {
        int acc = 0;
        for (int b = 0; b < (int)blockIdx.x; b++) acc += g_partials[b];
        s_off = acc;
    }
    __syncthreads();
    int i = blockIdx.x * SCAN_BLK + threadIdx.x;
    if (i < n) {
        int val = g_rowptr[i] + s_off;
        g_rowptr[i] = val;
        if (i < NN) g_cursor[i] = val;
    }
}
__global__ void scatter_kernel(const int* __restrict__ src,
                               const int* __restrict__ dst,
                               const float* __restrict__ ew) {
    int e = blockIdx.x * blockDim.x + threadIdx.x;
    if (e < EE) {
        int p = atomicAdd(&g_cursor[dst[e]], 1);
        g_src_sorted[p] = src[e];
        g_ew_sorted[p]  = ew[e];
    }
}

// ---------------- neighbor max (4-way unroll) ----------------
template <int DIN>
__global__ void neigh_max_pk(const uint32_t* __restrict__ hp, uint32_t* __restrict__ out) {
    int warp = (blockIdx.x * blockDim.x + threadIdx.x) >> 5;
    int lane = threadIdx.x & 31;
    if (warp >= NN) return;
    int beg = g_rowptr[warp];
    int end = g_rowptr[warp + 1];
    if (DIN == 128) {
        float m0 = 0.f, m1 = 0.f, m2 = 0.f, m3 = 0.f;
        int e = beg;
        for (; e + 3 < end; e += 4) {
            int s0 = g_src_sorted[e],     s1 = g_src_sorted[e + 1];
            int s2 = g_src_sorted[e + 2], s3 = g_src_sorted[e + 3];
            float w0 = g_ew_sorted[e],     w1 = g_ew_sorted[e + 1];
            float w2 = g_ew_sorted[e + 2], w3 = g_ew_sorted[e + 3];
            uint4 p0 = *(const uint4*)&hp[(size_t)s0 * 128 + lane * 4];
            uint4 p1 = *(const uint4*)&hp[(size_t)s1 * 128 + lane * 4];
            uint4 p2 = *(const uint4*)&hp[(size_t)s2 * 128 + lane * 4];
            uint4 p3 = *(const uint4*)&hp[(size_t)s3 * 128 + lane * 4];
            m0 = fmaxf(m0, unpack_split(p0.x) * w0); m1 = fmaxf(m1, unpack_split(p0.y) * w0);
            m2 = fmaxf(m2, unpack_split(p0.z) * w0); m3 = fmaxf(m3, unpack_split(p0.w) * w0);
            m0 = fmaxf(m0, unpack_split(p1.x) * w1); m1 = fmaxf(m1, unpack_split(p1.y) * w1);
            m2 = fmaxf(m2, unpack_split(p1.z) * w1); m3 = fmaxf(m3, unpack_split(p1.w) * w1);
            m0 = fmaxf(m0, unpack_split(p2.x) * w2); m1 = fmaxf(m1, unpack_split(p2.y) * w2);
            m2 = fmaxf(m2, unpack_split(p2.z) * w2); m3 = fmaxf(m3, unpack_split(p2.w) * w2);
            m0 = fmaxf(m0, unpack_split(p3.x) * w3); m1 = fmaxf(m1, unpack_split(p3.y) * w3);
            m2 = fmaxf(m2, unpack_split(p3.z) * w3); m3 = fmaxf(m3, unpack_split(p3.w) * w3);
        }
        for (; e < end; e++) {
            int s = g_src_sorted[e];
            float w = g_ew_sorted[e];
            uint4 p = *(const uint4*)&hp[(size_t)s * 128 + lane * 4];
            m0 = fmaxf(m0, unpack_split(p.x) * w); m1 = fmaxf(m1, unpack_split(p.y) * w);
            m2 = fmaxf(m2, unpack_split(p.z) * w); m3 = fmaxf(m3, unpack_split(p.w) * w);
        }
        uint4 o;
        o.x = pack_split(m0); o.y = pack_split(m1);
        o.z = pack_split(m2); o.w = pack_split(m3);
        *(uint4*)&out[(size_t)warp * 128 + lane * 4] = o;
    } else {
        float m0 = 0.f, m1 = 0.f;
        int e = beg;
        for (; e + 3 < end; e += 4) {
            int s0 = g_src_sorted[e],     s1 = g_src_sorted[e + 1];
            int s2 = g_src_sorted[e + 2], s3 = g_src_sorted[e + 3];
            float w0 = g_ew_sorted[e],     w1 = g_ew_sorted[e + 1];
            float w2 = g_ew_sorted[e + 2], w3 = g_ew_sorted[e + 3];
            uint2 p0 = *(const uint2*)&hp[(size_t)s0 * 64 + lane * 2];
            uint2 p1 = *(const uint2*)&hp[(size_t)s1 * 64 + lane * 2];
            uint2 p2 = *(const uint2*)&hp[(size_t)s2 * 64 + lane * 2];
            uint2 p3 = *(const uint2*)&hp[(size_t)s3 * 64 + lane * 2];
            m0 = fmaxf(m0, unpack_split(p0.x) * w0); m1 = fmaxf(m1, unpack_split(p0.y) * w0);
            m0 = fmaxf(m0, unpack_split(p1.x) * w1); m1 = fmaxf(m1, unpack_split(p1.y) * w1);
            m0 = fmaxf(m0, unpack_split(p2.x) * w2); m1 = fmaxf(m1, unpack_split(p2.y) * w2);
            m0 = fmaxf(m0, unpack_split(p3.x) * w3); m1 = fmaxf(m1, unpack_split(p3.y) * w3);
        }
        for (; e < end; e++) {
            int s = g_src_sorted[e];
            float w = g_ew_sorted[e];
            uint2 p = *(const uint2*)&hp[(size_t)s * 64 + lane * 2];
            m0 = fmaxf(m0, unpack_split(p.x) * w); m1 = fmaxf(m1, unpack_split(p.y) * w);
        }
        uint2 o;
        o.x = pack_split(m0); o.y = pack_split(m1);
        *(uint2*)&out[(size_t)warp * 64 + lane * 2] = o;
    }
}

// ================= shared GEMM core (fill + mainloop) =================
// F32A=false: A is packed split-bf16 u32. F32A=true: A is raw fp32 (split at fill).
// first=false: caller already used smem this launch (extra leading barrier).
template <int K, bool F32A>
__device__ __forceinline__ void gemm_core(
    const void* __restrict__ Araw, const uint32_t* __restrict__ Wb,
    int M, int m0, float acc[2][4][4],
    int tid, int wn, int r, int kp, int mrow0, char* smem, bool first)
{
    constexpr int KCH = 64;
    constexpr int SAH = KCH + 8;
    constexpr uint32_t offAhi = 0;
    constexpr uint32_t offAlo = offAhi + 128 * SAH * 2;
    constexpr uint32_t offBhi = offAlo + 128 * SAH * 2;
    constexpr uint32_t offBlo = offBhi + 64 * SAH * 2;
    constexpr int KSC = KCH / 16;

    for (int kc = 0; kc < K; kc += KCH) {
        if (kc || !first) __syncthreads();
        constexpr int C4 = KCH / 4;
        for (int idx = tid; idx < 128 * C4; idx += 256) {
            int row = idx / C4, c4 = idx % C4;
            uint4 v = make_uint4(0, 0, 0, 0);
            if (m0 + row < M) {
                if (F32A) {
                    float4 f = *(const float4*)((const float*)Araw + (size_t)(m0 + row) * K + kc + c4 * 4);
                    v.x = pack_split(f.x); v.y = pack_split(f.y);
                    v.z = pack_split(f.z); v.w = pack_split(f.w);
                } else {
                    v = *(const uint4*)((const uint32_t*)Araw + (size_t)(m0 + row) * K + kc + c4 * 4);
                }
            }
            uint2 hi, lo;
            hi.x = __byte_perm(v.x, v.y, SEL_HI); hi.y = __byte_perm(v.z, v.w, SEL_HI);
            lo.x = __byte_perm(v.x, v.y, SEL_LO); lo.y = __byte_perm(v.z, v.w, SEL_LO);
            uint32_t ho = (uint32_t)(row * SAH + c4 * 4) * 2;
            *(uint2*)(smem + offAhi + ho) = hi;
            *(uint2*)(smem + offAlo + ho) = lo;
        }
        for (int idx = tid; idx < 64 * C4; idx += 256) {
            int row = idx / C4, c4 = idx % C4;
            uint4 v = *(const uint4*)&Wb[(size_t)row * K + kc + c4 * 4];
            uint2 hi, lo;
            hi.x = __byte_perm(v.x, v.y, SEL_HI); hi.y = __byte_perm(v.z, v.w, SEL_HI);
            lo.x = __byte_perm(v.x, v.y, SEL_LO); lo.y = __byte_perm(v.z, v.w, SEL_LO);
            uint32_t ho = (uint32_t)(row * SAH + c4 * 4) * 2;
            *(uint2*)(smem + offBhi + ho) = hi;
            *(uint2*)(smem + offBlo + ho) = lo;
        }
        __syncthreads();

#pragma unroll
        for (int ks = 0; ks < KSC; ks++) {
            int kb = ks * 16;
            uint32_t ah0[4], al0[4], ah1[4], al1[4];
#pragma unroll
            for (int ms = 0; ms < 2; ms++) {
                int mr = mrow0 + ms * 16;
                uint32_t o00 = (uint32_t)((mr    ) * SAH + kb + kp) * 2;
                uint32_t o10 = (uint32_t)((mr + 8) * SAH + kb + kp) * 2;
                uint32_t o01 = (uint32_t)((mr    ) * SAH + kb + 8 + kp) * 2;
                uint32_t o11 = (uint32_t)((mr + 8) * SAH + kb + 8 + kp) * 2;
                uint32_t* ah = ms ? ah1 : ah0;
                uint32_t* al = ms ? al1 : al0;
                ah[0] = *(const uint32_t*)(smem + offAhi + o00);
                ah[1] = *(const uint32_t*)(smem + offAhi + o10);
                ah[2] = *(const uint32_t*)(smem + offAhi + o01);
                ah[3] = *(const uint32_t*)(smem + offAhi + o11);
                al[0] = *(const uint32_t*)(smem + offAlo + o00);
                al[1] = *(const uint32_t*)(smem + offAlo + o10);
                al[2] = *(const uint32_t*)(smem + offAlo + o01);
                al[3] = *(const uint32_t*)(smem + offAlo + o11);
            }
#pragma unroll
            for (int ns = 0; ns < 4; ns++) {
                int nrow = wn * 32 + ns * 8 + r;
                uint32_t ob0 = (uint32_t)(nrow * SAH + kb + kp) * 2;
                uint32_t ob1 = (uint32_t)(nrow * SAH + kb + 8 + kp) * 2;
                uint32_t bh0 = *(const uint32_t*)(smem + offBhi + ob0);
                uint32_t bh1 = *(const uint32_t*)(smem + offBhi + ob1);
                uint32_t bl0 = *(const uint32_t*)(smem + offBlo + ob0);
                uint32_t bl1 = *(const uint32_t*)(smem + offBlo + ob1);
                mma16816(acc[0][ns], ah0, bh0, bh1);
                mma16816(acc[0][ns], ah0, bl0, bl1);
                mma16816(acc[0][ns], al0, bh0, bh1);
                mma16816(acc[1][ns], ah1, bh0, bh1);
                mma16816(acc[1][ns], ah1, bl0, bl1);
                mma16816(acc[1][ns], al1, bh0, bh1);
            }
        }
    }
}

// ---------------- pool GEMM: out_pool = pack(relu(A@Wp + bp)) ----------------
template <int K, bool F32A>
__global__ __launch_bounds__(256, 4) void mma_pool(
    const void* __restrict__ A,
    const uint32_t* __restrict__ Wp, const float* __restrict__ bp,
    uint32_t* __restrict__ out_pool, int M, int NPOOL)
{
    extern __shared__ char smem[];
    int tid = threadIdx.x;
    int warp = tid >> 5, lane = tid & 31;
    int wm = warp & 3, wn = warp >> 2;
    int m0 = blockIdx.x * 128;
    int n0 = blockIdx.y * 64;
    int r  = lane >> 2;
    int kp = (lane & 3) * 2;
    int mrow0 = wm * 32 + r;

    float acc[2][4][4];
#pragma unroll
    for (int ms = 0; ms < 2; ms++)
#pragma unroll
        for (int ns = 0; ns < 4; ns++)
#pragma unroll
            for (int j = 0; j < 4; j++) acc[ms][ns][j] = 0.f;

    gemm_core<K, F32A>(A, Wp + (size_t)n0 * K, M, m0, acc, tid, wn, r, kp, mrow0, smem, true);

#pragma unroll
    for (int ms = 0; ms < 2; ms++) {
        int row0 = m0 + mrow0 + ms * 16;
        int row1 = row0 + 8;
#pragma unroll
        for (int ns = 0; ns < 4; ns++) {
            int col = n0 + wn * 32 + ns * 8 + kp;
            float bx = bp[col], by = bp[col + 1];
            float v0 = fmaxf(acc[ms][ns][0] + bx, 0.f);
            float v1 = fmaxf(acc[ms][ns][1] + by, 0.f);
            float v2 = fmaxf(acc[ms][ns][2] + bx, 0.f);
            float v3 = fmaxf(acc[ms][ns][3] + by, 0.f);
            if (row0 < M) *(uint2*)&out_pool[(size_t)row0 * NPOOL + col] = make_uint2(pack_split(v0), pack_split(v1));
            if (row1 < M) *(uint2*)&out_pool[(size_t)row1 * NPOOL + col] = make_uint2(pack_split(v2), pack_split(v3));
        }
    }
}

// ---------------- DUAL accum GEMM: out = relu(neigh@Wn + h@Ws + bias) ----------------
// Phase 0: A1 (packed neigh) @ W1; Phase 1: A2 (packed h, or fp32 if F32A2) @ W2.
// Both accumulate into the same fp32 registers. FINAL: fp32 out; else packed u32.
template <int K1, int K2, bool F32A2, bool FINAL>
__global__ __launch_bounds__(256, 4) void mma_accum_dual(
    const uint32_t* __restrict__ A1, const uint32_t* __restrict__ W1,
    const void* __restrict__ A2, const uint32_t* __restrict__ W2,
    const float* __restrict__ bias, void* __restrict__ outp, int M, int NOUTtot)
{
    extern __shared__ char smem[];
    int tid = threadIdx.x;
    int warp = tid >> 5, lane = tid & 31;
    int wm = warp & 3, wn = warp >> 2;
    int m0 = blockIdx.x * 128;
    int n0 = blockIdx.y * 64;
    int r  = lane >> 2;
    int kp = (lane & 3) * 2;
    int mrow0 = wm * 32 + r;

    float acc[2][4][4];
#pragma unroll
    for (int ms = 0; ms < 2; ms++)
#pragma unroll
        for (int ns = 0; ns < 4; ns++)
#pragma unroll
            for (int j = 0; j < 4; j++) acc[ms][ns][j] = 0.f;

    gemm_core<K1, false>(A1, W1 + (size_t)n0 * K1, M, m0, acc, tid, wn, r, kp, mrow0, smem, true);
    gemm_core<K2, F32A2>(A2, W2 + (size_t)n0 * K2, M, m0, acc, tid, wn, r, kp, mrow0, smem, false);

#pragma unroll
    for (int ms = 0; ms < 2; ms++) {
        int row0 = m0 + mrow0 + ms * 16;
        int row1 = row0 + 8;
#pragma unroll
        for (int ns = 0; ns < 4; ns++) {
            int col = n0 + wn * 32 + ns * 8 + kp;
            float bx = bias[col], by = bias[col + 1];
            float v0 = fmaxf(acc[ms][ns][0] + bx, 0.f);
            float v1 = fmaxf(acc[ms][ns][1] + by, 0.f);
            float v2 = fmaxf(acc[ms][ns][2] + bx, 0.f);
            float v3 = fmaxf(acc[ms][ns][3] + by, 0.f);
            if (FINAL) {
                float* o = (float*)outp;
                if (row0 < M) *(float2*)&o[(size_t)row0 * NOUTtot + col] = make_float2(v0, v1);
                if (row1 < M) *(float2*)&o[(size_t)row1 * NOUTtot + col] = make_float2(v2, v3);
            } else {
                uint32_t* o = (uint32_t*)outp;
                if (row0 < M) *(uint2*)&o[(size_t)row0 * NOUTtot + col] = make_uint2(pack_split(v0), pack_split(v1));
                if (row1 < M) *(uint2*)&o[(size_t)row1 * NOUTtot + col] = make_uint2(pack_split(v2), pack_split(v3));
            }
        }
    }
}

// ---------------- launch ----------------
extern "C" void kernel_launch(void* const* d_in, const int* in_sizes, int n_in,
                              void* d_out, int out_size) {
    const float* feat = (const float*)d_in[0];
    const int*   src  = (const int*)d_in[1];
    const int*   dst  = (const int*)d_in[2];
    const float* ew   = (const float*)d_in[3];
    const float* Wp1 = (const float*)d_in[4],  *bp1 = (const float*)d_in[5];
    const float* Ws1 = (const float*)d_in[6],  *Wn1 = (const float*)d_in[7],  *b1 = (const float*)d_in[8];
    const float* Wp2 = (const float*)d_in[9],  *bp2 = (const float*)d_in[10];
    const float* Ws2 = (const float*)d_in[11], *Wn2 = (const float*)d_in[12], *b2 = (const float*)d_in[13];
    const float* Wp3 = (const float*)d_in[14], *bp3 = (const float*)d_in[15];
    const float* Ws3 = (const float*)d_in[16], *Wn3 = (const float*)d_in[17], *b3 = (const float*)d_in[18];
    float* out = (float*)d_out;

    uint32_t *hppk, *neighpk, *h1pk, *h2pk, *wpk;
    cudaGetSymbolAddress((void**)&hppk,   g_hp_pk);
    cudaGetSymbolAddress((void**)&neighpk,g_neigh_pk);
    cudaGetSymbolAddress((void**)&h1pk,   g_h1_pk);
    cudaGetSymbolAddress((void**)&h2pk,   g_h2_pk);
    cudaGetSymbolAddress((void**)&wpk,    g_w_pk);

    static cudaStream_t s1 = nullptr;
    static cudaEvent_t evRoot, evW, evCSR;
    static bool sinit = false;
    if (!sinit) {
        cudaStreamCreateWithFlags(&s1, cudaStreamNonBlocking);
        cudaEventCreateWithFlags(&evRoot, cudaEventDisableTiming);
        cudaEventCreateWithFlags(&evW,    cudaEventDisableTiming);
        cudaEventCreateWithFlags(&evCSR,  cudaEventDisableTiming);
        sinit = true;
    }

    const int M = NN;
    const int SMB = (128 + 64) * (64 + 8) * 2 * 2;   // 55296 B
    cudaFuncSetAttribute(mma_pool<128, true >, cudaFuncAttributeMaxDynamicSharedMemorySize, SMB);
    cudaFuncSetAttribute(mma_pool<128, false>, cudaFuncAttributeMaxDynamicSharedMemorySize, SMB);
    cudaFuncSetAttribute(mma_pool<64,  false>, cudaFuncAttributeMaxDynamicSharedMemorySize, SMB);
    cudaFuncSetAttribute(mma_accum_dual<128, 128, true,  false>, cudaFuncAttributeMaxDynamicSharedMemorySize, SMB);
    cudaFuncSetAttribute(mma_accum_dual<64,  64,  false, false>, cudaFuncAttributeMaxDynamicSharedMemorySize, SMB);
    cudaFuncSetAttribute(mma_accum_dual<128, 128, false, true >, cudaFuncAttributeMaxDynamicSharedMemorySize, SMB);

    const int MT = (M + 127) / 128;      // 391
    dim3 nblk((NN * 32 + 255) / 256);

    // ======== fork: s1 does wprep + CSR (contiguous run); s0 runs the layer chain ========
    cudaEventRecord(evRoot, 0);
    cudaStreamWaitEvent(s1, evRoot, 0);

    wprep_all_kernel<<<dim3((128 * 128 + 255) / 256, 9), 256, 0, s1>>>(
        Wp1, Ws1, Wn1, Wp2, Ws2, Wn2, Wp3, Ws3, Wn3);
    cudaEventRecord(evW, s1);
    zero_counts_kernel<<<(NN + 256) / 256, 256, 0, s1>>>();
    hist_kernel<<<(EE + 255) / 256, 256, 0, s1>>>(dst);
    scan_chunk_kernel<<<NSCAN_BLKS, SCAN_BLK, 0, s1>>>(NN + 1);
    scan_add_kernel<<<NSCAN_BLKS, SCAN_BLK, 0, s1>>>(NN + 1);
    scatter_kernel<<<(EE + 255) / 256, 256, 0, s1>>>(src, dst, ew);
    cudaEventRecord(evCSR, s1);

    // --- s0: layer chain ---
    cudaStreamWaitEvent(0, evW, 0);
    // Layer 1 (K=128): pool(128) from fp32 feat; accum = neigh@Wn1 + feat@Ws1
    mma_pool<128, true><<<dim3(MT, 2), 256, SMB>>>(feat, wpk + WOFF_P1, bp1, hppk, M, 128);
    cudaStreamWaitEvent(0, evCSR, 0);
    neigh_max_pk<128><<<nblk, 256>>>(hppk, neighpk);
    mma_accum_dual<128, 128, true, false><<<dim3(MT, 1), 256, SMB>>>(
        neighpk, wpk + WOFF_N1, feat, wpk + WOFF_S1, b1, h1pk, M, 64);

    // Layer 2 (K=64): pool(64) from h1; accum = neigh@Wn2 + h1@Ws2
    mma_pool<64, false><<<dim3(MT, 1), 256, SMB>>>(h1pk, wpk + WOFF_P2, bp2, hppk, M, 64);
    neigh_max_pk<64><<<nblk, 256>>>(hppk, neighpk);
    mma_accum_dual<64, 64, false, false><<<dim3(MT, 2), 256, SMB>>>(
        neighpk, wpk + WOFF_N2, h1pk, wpk + WOFF_S2, b2, h2pk, M, 128);

    // Layer 3 (K=128): pool(128) from h2; accum = neigh@Wn3 + h2@Ws3 -> fp32 out
    mma_pool<128, false><<<dim3(MT, 2), 256, SMB>>>(h2pk, wpk + WOFF_P3, bp3, hppk, M, 128);
    neigh_max_pk<128><<<nblk, 256>>>(hppk, neighpk);
    mma_accum_dual<128, 128, false, true><<<dim3(MT, 2), 256, SMB>>>(
        neighpk, wpk + WOFF_N3, h2pk, wpk + WOFF_S3, b3, out, M, 128);
}